// round 1
// baseline (speedup 1.0000x reference)
#include <cuda_runtime.h>
#include <math.h>

#define LAYERS 4
#define BB 4
#define SS 2048
#define DD 1024
#define HH 2048
#define MTOK (BB*SS)      /* 8192 tokens */
#define EPSLN 1e-5f

#define CHUNKS 16
#define CLOG 4
#define CLEN (SS/CHUNKS)  /* 128 */

// ------------------------- scratch (static device allocations) ---------------
__device__ float g_buf0[(size_t)MTOK*HH];   // s1 after proj1/LN; later gru h
__device__ float g_buf1[(size_t)MTOK*HH];   // conv out -> gru input
__device__ float g_buf2[(size_t)MTOK*HH];   // k  = s1 @ Wz + bz
__device__ float g_buf3[(size_t)MTOK*HH];   // pre= s1 @ Wh + bh
__device__ float g_buf4[(size_t)MTOK*HH];   // s2
__device__ float g_wc[(size_t)3*HH*HH];     // packed conv weights per layer
__device__ float g_rend[BB*CHUNKS*HH];
__device__ float g_asum[BB*CHUNKS*HH];
__device__ float g_lhin[BB*CHUNKS*HH];

// ------------------------------- GEMM ----------------------------------------
// C[m,n] (+)= sum_k A'[m,k] * B[n,k] + bias[n]
// A'[m,k] = (optional row-shift within each batch, zero-pad) A[m+shift,k] * (A2 ? A2[m+shift,k] : 1)
__global__ __launch_bounds__(256, 2)
void gemm_f32(const float* __restrict__ A, const float* __restrict__ A2,
              const float* __restrict__ Bw, const float* __restrict__ bias,
              float* __restrict__ C, int M, int N, int K, int shift, int accum)
{
    __shared__ float As[2][8][128];
    __shared__ float Bs[2][8][128];
    const int tid = threadIdx.x;
    const int bm = blockIdx.y * 128;
    const int bn = blockIdx.x * 128;

    // global-load mapping (fixed per thread across k-tiles)
    const int a_r = tid >> 1;
    const int a_c = (tid & 1) * 4;
    const int lrow = bm + a_r;
    const int t    = lrow & (SS - 1);
    const bool a_valid = ((unsigned)(t + shift)) < (unsigned)SS;
    const float* Arow  = A  + (size_t)(lrow + shift) * K;
    const float* A2row = A2 ? (A2 + (size_t)(lrow + shift) * K) : (const float*)0;
    const float* Brow  = Bw + (size_t)(bn + a_r) * K;

    const int tm = (tid >> 4) * 8;
    const int tn = (tid & 15) * 8;

    float acc[8][8];
#pragma unroll
    for (int i = 0; i < 8; i++)
#pragma unroll
        for (int j = 0; j < 8; j++) acc[i][j] = 0.f;

    // load tile 0
    float4 av = make_float4(0.f,0.f,0.f,0.f), bv;
    if (a_valid) {
        av = *(const float4*)(Arow + a_c);
        if (A2row) { float4 m2 = *(const float4*)(A2row + a_c);
            av.x*=m2.x; av.y*=m2.y; av.z*=m2.z; av.w*=m2.w; }
    }
    bv = *(const float4*)(Brow + a_c);
    As[0][a_c+0][a_r]=av.x; As[0][a_c+1][a_r]=av.y; As[0][a_c+2][a_r]=av.z; As[0][a_c+3][a_r]=av.w;
    Bs[0][a_c+0][a_r]=bv.x; Bs[0][a_c+1][a_r]=bv.y; Bs[0][a_c+2][a_r]=bv.z; Bs[0][a_c+3][a_r]=bv.w;
    __syncthreads();

    const int ntiles = K >> 3;
    int buf = 0;
    for (int kt = 0; kt < ntiles; ++kt) {
        float4 an = make_float4(0.f,0.f,0.f,0.f), bnv = an;
        const bool pf = (kt + 1 < ntiles);
        if (pf) {
            const int kb = (kt + 1) << 3;
            if (a_valid) {
                an = *(const float4*)(Arow + kb + a_c);
                if (A2row) { float4 m2 = *(const float4*)(A2row + kb + a_c);
                    an.x*=m2.x; an.y*=m2.y; an.z*=m2.z; an.w*=m2.w; }
            }
            bnv = *(const float4*)(Brow + kb + a_c);
        }
#pragma unroll
        for (int kk = 0; kk < 8; ++kk) {
            float ar[8], br[8];
            *(float4*)&ar[0] = *(const float4*)&As[buf][kk][tm];
            *(float4*)&ar[4] = *(const float4*)&As[buf][kk][tm+4];
            *(float4*)&br[0] = *(const float4*)&Bs[buf][kk][tn];
            *(float4*)&br[4] = *(const float4*)&Bs[buf][kk][tn+4];
#pragma unroll
            for (int i = 0; i < 8; i++)
#pragma unroll
                for (int j = 0; j < 8; j++)
                    acc[i][j] = fmaf(ar[i], br[j], acc[i][j]);
        }
        if (pf) {
            const int nb = buf ^ 1;
            As[nb][a_c+0][a_r]=an.x;  As[nb][a_c+1][a_r]=an.y;  As[nb][a_c+2][a_r]=an.z;  As[nb][a_c+3][a_r]=an.w;
            Bs[nb][a_c+0][a_r]=bnv.x; Bs[nb][a_c+1][a_r]=bnv.y; Bs[nb][a_c+2][a_r]=bnv.z; Bs[nb][a_c+3][a_r]=bnv.w;
            __syncthreads();
            buf = nb;
        }
    }

    float4 bi0 = make_float4(0.f,0.f,0.f,0.f), bi1 = bi0;
    if (bias) {
        bi0 = *(const float4*)(bias + bn + tn);
        bi1 = *(const float4*)(bias + bn + tn + 4);
    }
#pragma unroll
    for (int i = 0; i < 8; i++) {
        float* cp = C + (size_t)(bm + tm + i) * N + bn + tn;
        float4 c0 = make_float4(acc[i][0]+bi0.x, acc[i][1]+bi0.y, acc[i][2]+bi0.z, acc[i][3]+bi0.w);
        float4 c1 = make_float4(acc[i][4]+bi1.x, acc[i][5]+bi1.y, acc[i][6]+bi1.z, acc[i][7]+bi1.w);
        if (accum) {
            float4 o0 = *(const float4*)cp;
            float4 o1 = *(const float4*)(cp + 4);
            c0.x+=o0.x; c0.y+=o0.y; c0.z+=o0.z; c0.w+=o0.w;
            c1.x+=o1.x; c1.y+=o1.y; c1.z+=o1.z; c1.w+=o1.w;
        }
        *(float4*)cp       = c0;
        *(float4*)(cp + 4) = c1;
    }
}

// ------------------------------ LayerNorm (+SiLU) -----------------------------
template<int DO_SILU>
__global__ void ln_kernel(const float* __restrict__ in, float* __restrict__ out,
                          const float* __restrict__ g, const float* __restrict__ b)
{
    __shared__ float red[8];
    __shared__ float s_mean, s_rstd;
    const int row = blockIdx.x;
    const float4* ip = (const float4*)(in + (size_t)row * HH);
    float4 v0 = ip[threadIdx.x];
    float4 v1 = ip[threadIdx.x + 256];

    float s = v0.x+v0.y+v0.z+v0.w + v1.x+v1.y+v1.z+v1.w;
#pragma unroll
    for (int o = 16; o; o >>= 1) s += __shfl_xor_sync(0xffffffffu, s, o);
    const int wid = threadIdx.x >> 5, lane = threadIdx.x & 31;
    if (lane == 0) red[wid] = s;
    __syncthreads();
    if (threadIdx.x == 0) {
        float tt = 0.f;
#pragma unroll
        for (int i = 0; i < 8; i++) tt += red[i];
        s_mean = tt * (1.0f / HH);
    }
    __syncthreads();
    const float mean = s_mean;
    float d, ss = 0.f;
    d=v0.x-mean; ss+=d*d; d=v0.y-mean; ss+=d*d; d=v0.z-mean; ss+=d*d; d=v0.w-mean; ss+=d*d;
    d=v1.x-mean; ss+=d*d; d=v1.y-mean; ss+=d*d; d=v1.z-mean; ss+=d*d; d=v1.w-mean; ss+=d*d;
#pragma unroll
    for (int o = 16; o; o >>= 1) ss += __shfl_xor_sync(0xffffffffu, ss, o);
    if (lane == 0) red[wid] = ss;
    __syncthreads();
    if (threadIdx.x == 0) {
        float tt = 0.f;
#pragma unroll
        for (int i = 0; i < 8; i++) tt += red[i];
        s_rstd = rsqrtf(tt * (1.0f / HH) + EPSLN);
    }
    __syncthreads();
    const float rstd = s_rstd;

    float4 g0 = ((const float4*)g)[threadIdx.x];
    float4 g1 = ((const float4*)g)[threadIdx.x + 256];
    float4 b0 = ((const float4*)b)[threadIdx.x];
    float4 b1 = ((const float4*)b)[threadIdx.x + 256];
    float4 o0, o1;
    o0.x=(v0.x-mean)*rstd*g0.x+b0.x; o0.y=(v0.y-mean)*rstd*g0.y+b0.y;
    o0.z=(v0.z-mean)*rstd*g0.z+b0.z; o0.w=(v0.w-mean)*rstd*g0.w+b0.w;
    o1.x=(v1.x-mean)*rstd*g1.x+b1.x; o1.y=(v1.y-mean)*rstd*g1.y+b1.y;
    o1.z=(v1.z-mean)*rstd*g1.z+b1.z; o1.w=(v1.w-mean)*rstd*g1.w+b1.w;
    if (DO_SILU) {
        o0.x = o0.x / (1.f + expf(-o0.x)); o0.y = o0.y / (1.f + expf(-o0.y));
        o0.z = o0.z / (1.f + expf(-o0.z)); o0.w = o0.w / (1.f + expf(-o0.w));
        o1.x = o1.x / (1.f + expf(-o1.x)); o1.y = o1.y / (1.f + expf(-o1.y));
        o1.z = o1.z / (1.f + expf(-o1.z)); o1.w = o1.w / (1.f + expf(-o1.w));
    }
    float4* op = (float4*)(out + (size_t)row * HH);
    op[threadIdx.x]       = o0;
    op[threadIdx.x + 256] = o1;
}

// ----------------------------- conv weight pack -------------------------------
// convW (O=H, I=H, 3) -> packed[kk][o][i]
__global__ void pack_conv_kernel(const float* __restrict__ w, float* __restrict__ out)
{
    int idx = blockIdx.x * blockDim.x + threadIdx.x;  // over H*H
    if (idx < HH * HH) {
        const float* p = w + (size_t)idx * 3;
        out[idx]                      = p[0];
        out[(size_t)HH*HH     + idx]  = p[1];
        out[(size_t)2*HH*HH   + idx]  = p[2];
    }
}

// ------------------------------- minGRU scan ----------------------------------
__device__ __forceinline__ float softplusf(float x) {
    return fmaxf(x, 0.0f) + log1pf(expf(-fabsf(x)));
}
__device__ __forceinline__ float loggf(float x) {
    return (x >= 0.0f) ? logf(x + 0.5f) : -softplusf(-x);
}
__device__ __forceinline__ float laddexp(float a, float b) {
    float m = fmaxf(a, b);
    float d = fminf(a, b) - m;       // -inf safe: expf(-inf)=0
    return m + log1pf(expf(d));
}

__global__ void scan_a(const float* __restrict__ Kx, const float* __restrict__ Px,
                       float* __restrict__ rend, float* __restrict__ asum)
{
    const int tid = blockIdx.x * 256 + threadIdx.x;   // B*CHUNKS*H threads
    const int h = tid & (HH - 1);
    const int rest = tid >> 11;
    const int j = rest & (CHUNKS - 1);
    const int b = rest >> CLOG;
    const size_t base = ((size_t)b * SS + (size_t)j * CLEN) * HH + h;
    float A = 0.f, r = -__int_as_float(0x7f800000);
    for (int tt = 0; tt < CLEN; tt++) {
        const float kv = Kx[base + (size_t)tt * HH];
        const float pv = Px[base + (size_t)tt * HH];
        const float lc = -softplusf(kv);
        const float lv = -softplusf(-kv) + loggf(pv);
        A += lc;
        r = laddexp(r + lc, lv);
    }
    rend[tid] = r;
    asum[tid] = A;
}

__global__ void scan_b(const float* __restrict__ rend, const float* __restrict__ asum,
                       float* __restrict__ lhin)
{
    const int tid = blockIdx.x * 256 + threadIdx.x;   // B*H threads
    const int h = tid & (HH - 1);
    const int b = tid >> 11;
    float carry = -0.69314718056f;                    // log(0.5) = log_g(0)
#pragma unroll
    for (int j = 0; j < CHUNKS; j++) {
        const int idx = ((b * CHUNKS + j) << 11) + h;
        lhin[idx] = carry;
        carry = laddexp(asum[idx] + carry, rend[idx]);
    }
}

__global__ void scan_c(const float* __restrict__ Kx, const float* __restrict__ Px,
                       const float* __restrict__ lhin, float* __restrict__ out)
{
    const int tid = blockIdx.x * 256 + threadIdx.x;
    const int h = tid & (HH - 1);
    const int rest = tid >> 11;
    const int j = rest & (CHUNKS - 1);
    const int b = rest >> CLOG;
    const size_t base = ((size_t)b * SS + (size_t)j * CLEN) * HH + h;
    const float lhi = lhin[tid];
    float A = 0.f, r = -__int_as_float(0x7f800000);
    for (int tt = 0; tt < CLEN; tt++) {
        const float kv = Kx[base + (size_t)tt * HH];
        const float pv = Px[base + (size_t)tt * HH];
        const float lc = -softplusf(kv);
        const float lv = -softplusf(-kv) + loggf(pv);
        A += lc;
        r = laddexp(r + lc, lv);
        out[base + (size_t)tt * HH] = expf(laddexp(r, A + lhi));
    }
}

// --------------------------------- driver -------------------------------------
extern "C" void kernel_launch(void* const* d_in, const int* in_sizes, int n_in,
                              void* d_out, int out_size)
{
    const float* x    = (const float*)d_in[0];
    const float* Wp1  = (const float*)d_in[1];
    const float* bp1  = (const float*)d_in[2];
    const float* Wp2  = (const float*)d_in[3];
    const float* bp2  = (const float*)d_in[4];
    const float* convW= (const float*)d_in[5];
    const float* convb= (const float*)d_in[6];
    const float* Wz   = (const float*)d_in[7];
    const float* bz   = (const float*)d_in[8];
    const float* Wh   = (const float*)d_in[9];
    const float* bh   = (const float*)d_in[10];
    const float* Wd   = (const float*)d_in[11];
    const float* bd   = (const float*)d_in[12];
    const float* lng  = (const float*)d_in[13];
    const float* lnb  = (const float*)d_in[14];
    float* xb = (float*)d_out;

    float *b0,*b1,*b2,*b3,*b4,*wc,*rend,*asum,*lhin;
    cudaGetSymbolAddress((void**)&b0,  g_buf0);
    cudaGetSymbolAddress((void**)&b1,  g_buf1);
    cudaGetSymbolAddress((void**)&b2,  g_buf2);
    cudaGetSymbolAddress((void**)&b3,  g_buf3);
    cudaGetSymbolAddress((void**)&b4,  g_buf4);
    cudaGetSymbolAddress((void**)&wc,  g_wc);
    cudaGetSymbolAddress((void**)&rend,g_rend);
    cudaGetSymbolAddress((void**)&asum,g_asum);
    cudaGetSymbolAddress((void**)&lhin,g_lhin);

    cudaMemcpyAsync(xb, x, (size_t)MTOK * DD * sizeof(float),
                    cudaMemcpyDeviceToDevice, 0);

    const dim3 gH(HH/128, MTOK/128);   // N=2048 GEMMs
    const dim3 gD(DD/128, MTOK/128);   // N=1024 GEMM

    for (int i = 0; i < LAYERS; i++) {
        const float* wp1 = Wp1 + (size_t)i*HH*DD;
        const float* wp2 = Wp2 + (size_t)i*HH*DD;
        const float* cw  = convW + (size_t)i*HH*HH*3;
        const float* wz  = Wz + (size_t)i*HH*HH;
        const float* wh  = Wh + (size_t)i*HH*HH;
        const float* wd  = Wd + (size_t)i*DD*HH;

        // strand 1: proj1 + bias, LN0
        gemm_f32<<<gH, 256>>>(xb, 0, wp1, bp1 + i*HH, b0, MTOK, HH, DD, 0, 0);
        ln_kernel<0><<<MTOK, 256>>>(b0, b0, lng + (size_t)(i*4+0)*HH, lnb + (size_t)(i*4+0)*HH);

        // conv1d (full, k=3) as 3 shifted accumulated GEMMs over packed weights
        pack_conv_kernel<<<(HH*HH + 255)/256, 256>>>(cw, wc);
        gemm_f32<<<gH, 256>>>(b0, 0, wc,                   convb + i*HH, b1, MTOK, HH, HH, -1, 0);
        gemm_f32<<<gH, 256>>>(b0, 0, wc + (size_t)HH*HH,   0,            b1, MTOK, HH, HH,  0, 1);
        gemm_f32<<<gH, 256>>>(b0, 0, wc + (size_t)2*HH*HH, 0,            b1, MTOK, HH, HH,  1, 1);
        ln_kernel<1><<<MTOK, 256>>>(b1, b1, lng + (size_t)(i*4+1)*HH, lnb + (size_t)(i*4+1)*HH);

        // minGRU: gate / candidate projections, then chunked log-space scan
        gemm_f32<<<gH, 256>>>(b1, 0, wz, bz + i*HH, b2, MTOK, HH, HH, 0, 0);
        gemm_f32<<<gH, 256>>>(b1, 0, wh, bh + i*HH, b3, MTOK, HH, HH, 0, 0);
        scan_a<<<(BB*CHUNKS*HH)/256, 256>>>(b2, b3, rend, asum);
        scan_b<<<(BB*HH)/256, 256>>>(rend, asum, lhin);
        scan_c<<<(BB*CHUNKS*HH)/256, 256>>>(b2, b3, lhin, b0);
        ln_kernel<0><<<MTOK, 256>>>(b0, b0, lng + (size_t)(i*4+2)*HH, lnb + (size_t)(i*4+2)*HH);

        // strand 2: proj2, LN3 + SiLU
        gemm_f32<<<gH, 256>>>(xb, 0, wp2, bp2 + i*HH, b4, MTOK, HH, DD, 0, 0);
        ln_kernel<1><<<MTOK, 256>>>(b4, b4, lng + (size_t)(i*4+3)*HH, lnb + (size_t)(i*4+3)*HH);

        // down projection of (s1 * s2) + bias + residual (accumulate into x)
        gemm_f32<<<gD, 256>>>(b0, b4, wd, bd + i*DD, xb, MTOK, DD, HH, 0, 1);
    }
}

// round 5
// speedup vs baseline: 10.5612x; 10.5612x over previous
#include <cuda_runtime.h>
#include <cuda_bf16.h>
#include <math.h>
#include <stdint.h>

#define LAYERS 4
#define BB 4
#define SS 2048
#define DD 1024
#define HH 2048
#define MTOK (BB*SS)      /* 8192 tokens */
#define EPSLN 1e-5f

#define CHUNKS 16
#define CLOG 4
#define CLEN (SS/CHUNKS)  /* 128 */

// arch-feature gate: tcgen05 only exists on the sm_103a/sm_100a ("a") targets.
#if defined(__CUDA_ARCH_FEAT_SM103_ALL) || defined(__CUDA_ARCH_FEAT_SM100_ALL)
#define USE_TC5 1
#else
#define USE_TC5 0
#endif

// ---- GEMM tiling ----
#define TM 128
#define TN 256
#define KC 64                 /* K elements per chunk (128B rows bf16) */
#define STAGE_BYTES 98304     /* Ahi16K + Alo16K + Bhi32K + Blo32K */
#define SM_A_HI 0
#define SM_A_LO 16384
#define SM_B_HI 32768
#define SM_B_LO 65536
#define SMEM_DYN (1024 + 1024 + 2*STAGE_BYTES)

// ------------------------- scratch -------------------------------------------
__device__ __align__(256) float g_b0[(size_t)MTOK*HH];
__device__ __align__(256) float g_b2[(size_t)MTOK*HH];
__device__ __align__(256) float g_b3[(size_t)MTOK*HH];
__device__ __align__(256) float g_b4[(size_t)MTOK*HH];
__device__ __align__(256) __nv_bfloat16 g_cvth[(size_t)MTOK*HH];
__device__ __align__(256) __nv_bfloat16 g_cvtl[(size_t)MTOK*HH];
__device__ __align__(256) __nv_bfloat16 g_wp1h[(size_t)LAYERS*HH*DD];
__device__ __align__(256) __nv_bfloat16 g_wp1l[(size_t)LAYERS*HH*DD];
__device__ __align__(256) __nv_bfloat16 g_wp2h[(size_t)LAYERS*HH*DD];
__device__ __align__(256) __nv_bfloat16 g_wp2l[(size_t)LAYERS*HH*DD];
__device__ __align__(256) __nv_bfloat16 g_wzh[(size_t)LAYERS*HH*HH];
__device__ __align__(256) __nv_bfloat16 g_wzl[(size_t)LAYERS*HH*HH];
__device__ __align__(256) __nv_bfloat16 g_whh[(size_t)LAYERS*HH*HH];
__device__ __align__(256) __nv_bfloat16 g_whl[(size_t)LAYERS*HH*HH];
__device__ __align__(256) __nv_bfloat16 g_wdh[(size_t)LAYERS*DD*HH];
__device__ __align__(256) __nv_bfloat16 g_wdl[(size_t)LAYERS*DD*HH];
__device__ __align__(256) __nv_bfloat16 g_wch[(size_t)LAYERS*3*HH*HH];
__device__ __align__(256) __nv_bfloat16 g_wcl[(size_t)LAYERS*3*HH*HH];
__device__ float g_rend[BB*CHUNKS*HH];
__device__ float g_asum[BB*CHUNKS*HH];
__device__ float g_lhin[BB*CHUNKS*HH];

// ------------------------- helpers --------------------------------------------
__device__ __forceinline__ uint32_t smem_u32(const void* p) {
    uint32_t a;
    asm("{ .reg .u64 t; cvta.to.shared.u64 t, %1; cvt.u32.u64 %0, t; }" : "=r"(a) : "l"(p));
    return a;
}
#define SW128(b) ((b) ^ (((b) >> 3) & 0x70))

__device__ __forceinline__ void cpasync16(uint32_t dst, const void* src, int srcsize) {
    asm volatile("cp.async.cg.shared.global [%0], [%1], 16, %2;\n"
                 :: "r"(dst), "l"(src), "r"(srcsize));
}

#if USE_TC5
__device__ __forceinline__ uint32_t elect_one_pred() {
    uint32_t pred;
    asm volatile("{\n\t.reg .pred p;\n\telect.sync _|p, 0xFFFFFFFF;\n\t"
                 "selp.b32 %0, 1, 0, p;\n\t}" : "=r"(pred));
    return pred;
}

static constexpr uint64_t SMEM_DESC_BASE_SW128 =
    (uint64_t(2) << 61) | (uint64_t(1) << 46) | (uint64_t(64) << 32) | (uint64_t(1) << 16);
#define MAKE_SMEM_DESC(base_addr) \
    (SMEM_DESC_BASE_SW128 | ((uint64_t)((base_addr) >> 4) & 0x3FFF))

#define TCGEN05_ALLOC(smem_result_addr, nCols) \
    asm volatile("tcgen05.alloc.cta_group::1.sync.aligned.shared::cta.b32 [%0], %1;" \
        :: "r"((uint32_t)(smem_result_addr)), "r"((uint32_t)(nCols)) : "memory")
#define TCGEN05_DEALLOC(tmem_addr, nCols) \
    asm volatile("tcgen05.dealloc.cta_group::1.sync.aligned.b32 %0, %1;" \
        :: "r"(tmem_addr), "r"((uint32_t)(nCols)))
#define TCGEN05_RELINQUISH() \
    asm volatile("tcgen05.relinquish_alloc_permit.cta_group::1.sync.aligned;")
#define TCGEN05_COMMIT(mbar) \
    asm volatile("tcgen05.commit.cta_group::1.mbarrier::arrive::one.shared::cluster.b64 [%0];" \
        :: "r"((uint32_t)(mbar)) : "memory")
#define TCGEN05_FENCE_AFTER() \
    asm volatile("tcgen05.fence::after_thread_sync;" ::: "memory")
#define TCGEN05_FENCE_BEFORE() \
    asm volatile("tcgen05.fence::before_thread_sync;" ::: "memory")
#define TCGEN05_WAIT_LD() \
    asm volatile("tcgen05.wait::ld.sync.aligned;" ::: "memory")
#define MBARRIER_INIT(mbar, cnt) \
    asm volatile("mbarrier.init.shared.b64 [%0], %1;" \
        :: "r"((uint32_t)(mbar)), "r"((uint32_t)(cnt)) : "memory")
#define MBARRIER_INVAL(mbar) \
    asm volatile("mbarrier.inval.shared.b64 [%0];" :: "r"((uint32_t)(mbar)) : "memory")

#define MBARRIER_WAIT_PARITY(mbar_smem_addr, phase_parity) do { \
    uint32_t _mbar = (uint32_t)(mbar_smem_addr); \
    uint32_t _parity = (uint32_t)(phase_parity); \
    uint32_t _done; \
    asm volatile("{\n\t.reg .pred p;\n\t" \
        "mbarrier.try_wait.parity.acquire.cta.shared::cta.b64 p, [%1], %2;\n\t" \
        "selp.b32 %0, 1, 0, p;\n\t}" : "=r"(_done) : "r"(_mbar), "r"(_parity) : "memory"); \
    if (!_done) { \
        asm volatile("{\n\t.reg .pred P1;\n\t" \
            "WAIT_LOOP_%=:\n\t" \
            "mbarrier.try_wait.parity.acquire.cta.shared::cta.b64 P1, [%0], %1, 0x989680;\n\t" \
            "@P1 bra.uni WAIT_DONE_%=;\n\t" \
            "bra.uni WAIT_LOOP_%=;\n\t" \
            "WAIT_DONE_%=:\n\t}" :: "r"(_mbar), "r"(_parity) : "memory"); \
    } \
} while(0)

#define TCGEN05_LD_X32(r, tmem_addr) \
    asm volatile("tcgen05.ld.sync.aligned.32x32b.x32.b32 " \
        "{%0, %1, %2, %3, %4, %5, %6, %7, %8, %9, %10, %11, %12, %13, %14, %15, " \
        "%16, %17, %18, %19, %20, %21, %22, %23, %24, %25, %26, %27, %28, %29, %30, %31}, [%32];" \
        : "=r"((r)[0]),  "=r"((r)[1]),  "=r"((r)[2]),  "=r"((r)[3]), \
          "=r"((r)[4]),  "=r"((r)[5]),  "=r"((r)[6]),  "=r"((r)[7]), \
          "=r"((r)[8]),  "=r"((r)[9]),  "=r"((r)[10]), "=r"((r)[11]), \
          "=r"((r)[12]), "=r"((r)[13]), "=r"((r)[14]), "=r"((r)[15]), \
          "=r"((r)[16]), "=r"((r)[17]), "=r"((r)[18]), "=r"((r)[19]), \
          "=r"((r)[20]), "=r"((r)[21]), "=r"((r)[22]), "=r"((r)[23]), \
          "=r"((r)[24]), "=r"((r)[25]), "=r"((r)[26]), "=r"((r)[27]), \
          "=r"((r)[28]), "=r"((r)[29]), "=r"((r)[30]), "=r"((r)[31]) \
        : "r"(tmem_addr))

__device__ __forceinline__ void mma_f16_ss(uint32_t d, uint64_t ad, uint64_t bd,
                                           uint32_t idesc, uint32_t en) {
    asm volatile("{\n\t.reg .pred p;\n\tsetp.ne.u32 p, %4, 0;\n\t"
        "tcgen05.mma.cta_group::1.kind::f16 [%0], %1, %2, %3, {%5, %5, %5, %5}, p;\n\t}"
        :: "r"(d), "l"(ad), "l"(bd), "r"(idesc), "r"(en), "r"(0u) : "memory");
}
#else
// -------- baseline-PTX tensor path: warp-level bf16 mma.sync ------------------
__device__ __forceinline__ void ldsm_x4(uint32_t* r, uint32_t addr) {
    asm volatile("ldmatrix.sync.aligned.m8n8.x4.shared.b16 {%0,%1,%2,%3}, [%4];"
        : "=r"(r[0]), "=r"(r[1]), "=r"(r[2]), "=r"(r[3]) : "r"(addr));
}
__device__ __forceinline__ void ldsm_x2(uint32_t* r, uint32_t addr) {
    asm volatile("ldmatrix.sync.aligned.m8n8.x2.shared.b16 {%0,%1}, [%2];"
        : "=r"(r[0]), "=r"(r[1]) : "r"(addr));
}
__device__ __forceinline__ void mma16816(float* d, const uint32_t* a, const uint32_t* b) {
    asm volatile("mma.sync.aligned.m16n8k16.row.col.f32.bf16.bf16.f32 "
        "{%0,%1,%2,%3}, {%4,%5,%6,%7}, {%8,%9}, {%0,%1,%2,%3};"
        : "+f"(d[0]), "+f"(d[1]), "+f"(d[2]), "+f"(d[3])
        : "r"(a[0]), "r"(a[1]), "r"(a[2]), "r"(a[3]), "r"(b[0]), "r"(b[1]));
}
#endif

// ------------------------------- GEMM -----------------------------------------
// C[M=8192, N] (+)= sum_taps sum_k A'[m,k]*B_tap[n,k] + bias[n]
// A' rows shifted by (tap-1) within each batch (zero pad) when taps==3.
// hi/lo split bf16: acc += Ah*Bh + Ah*Bl + Al*Bh (fp32 accumulate).
__device__ __forceinline__ void load_chunk(
    int c, int buf, int kpt, int taps, int K,
    const __nv_bfloat16* __restrict__ Ahi, const __nv_bfloat16* __restrict__ Alo,
    const __nv_bfloat16* __restrict__ Bhi, const __nv_bfloat16* __restrict__ Blo,
    size_t tapStrideB, int bm, int bn, uint32_t tb)
{
    int tap = 0, kc = c;
    if (taps == 3) { tap = c / kpt; kc = c - tap * kpt; }
    const int shift = (taps == 3) ? (tap - 1) : 0;
    const int kbase = kc << 6;
    const uint32_t sb = tb + (uint32_t)buf * STAGE_BYTES;
    const int tid = threadIdx.x;

    // A tiles: 128 rows x 8 16B-units
#pragma unroll
    for (int it = 0; it < 4; ++it) {
        const int u = tid + it * 256;
        const int r = u >> 3, c16 = u & 7;
        const int m = bm + r;
        const int t = m & (SS - 1);
        const bool ok = ((unsigned)(t + shift)) < (unsigned)SS;
        const int srcsz = ok ? 16 : 0;
        const size_t goff = (size_t)(ok ? (m + shift) : m) * K + kbase + c16 * 8;
        const uint32_t so = SW128((uint32_t)(r * 128 + c16 * 16));
        cpasync16(sb + SM_A_HI + so, Ahi + goff, srcsz);
        cpasync16(sb + SM_A_LO + so, Alo + goff, srcsz);
    }
    // B tiles: 256 rows x 8 units
    const __nv_bfloat16* Bh = Bhi + (size_t)tap * tapStrideB;
    const __nv_bfloat16* Bl = Blo + (size_t)tap * tapStrideB;
#pragma unroll
    for (int it = 0; it < 8; ++it) {
        const int u = tid + it * 256;
        const int r = u >> 3, c16 = u & 7;
        const size_t goff = (size_t)(bn + r) * K + kbase + c16 * 8;
        const uint32_t so = SW128((uint32_t)(r * 128 + c16 * 16));
        cpasync16(sb + SM_B_HI + so, Bh + goff, 16);
        cpasync16(sb + SM_B_LO + so, Bl + goff, 16);
    }
}

__global__ __launch_bounds__(256, 1)
void gemm_ts(const __nv_bfloat16* __restrict__ Ahi, const __nv_bfloat16* __restrict__ Alo,
             const __nv_bfloat16* __restrict__ Bhi, const __nv_bfloat16* __restrict__ Blo,
             const float* __restrict__ bias, float* __restrict__ C,
             int N, int K, int taps, size_t tapStrideB, int accum)
{
    extern __shared__ char dsm[];
    const uint32_t raw = smem_u32(dsm);
    const uint32_t sb0 = (raw + 1023) & ~1023u;     // header (tmem ptr, mbars)
    const uint32_t tb  = sb0 + 1024;                // tiles, 1KB aligned

    const int tid = threadIdx.x;
    const int wid = tid >> 5;
    const int lane = tid & 31;
    const int bm = blockIdx.y * TM;
    const int bn = blockIdx.x * TN;
    const int kpt = K >> 6;
    const int nch = taps * kpt;

#if USE_TC5
    const uint32_t mb0 = sb0 + 8, mb1 = sb0 + 16;
    if (wid == 0) { TCGEN05_ALLOC(sb0, TN); TCGEN05_RELINQUISH(); }
    if (tid == 0) { MBARRIER_INIT(mb0, 1); MBARRIER_INIT(mb1, 1); }
    __syncthreads();
    uint32_t tmem;
    asm volatile("ld.shared.b32 %0, [%1];" : "=r"(tmem) : "r"(sb0));

    const uint32_t idesc = (1u << 4) | (1u << 7) | (1u << 10)
                         | ((TN / 8) << 17) | ((TM / 16) << 24);

    load_chunk(0, 0, kpt, taps, K, Ahi, Alo, Bhi, Blo, tapStrideB, bm, bn, tb);
    asm volatile("cp.async.commit_group;" ::: "memory");
    load_chunk(1, 1, kpt, taps, K, Ahi, Alo, Bhi, Blo, tapStrideB, bm, bn, tb);
    asm volatile("cp.async.commit_group;" ::: "memory");

    int ph0 = 0, ph1 = 0;
    for (int c = 0; c < nch; ++c) {
        const int buf = c & 1;
        if (c + 1 == nch) asm volatile("cp.async.wait_group 0;" ::: "memory");
        else              asm volatile("cp.async.wait_group 1;" ::: "memory");
        __syncthreads();

        if (wid == 0) {
            if (elect_one_pred()) {
                asm volatile("fence.proxy.async.shared::cta;" ::: "memory");
                const uint32_t sb = tb + (uint32_t)buf * STAGE_BYTES;
                const uint64_t ah = MAKE_SMEM_DESC(sb + SM_A_HI);
                const uint64_t al = MAKE_SMEM_DESC(sb + SM_A_LO);
                const uint64_t bh = MAKE_SMEM_DESC(sb + SM_B_HI);
                const uint64_t bl = MAKE_SMEM_DESC(sb + SM_B_LO);
#pragma unroll
                for (int k = 0; k < 4; ++k) {
                    mma_f16_ss(tmem, ah + k * 2, bh + k * 2, idesc,
                               (c == 0 && k == 0) ? 0u : 1u);
                    mma_f16_ss(tmem, ah + k * 2, bl + k * 2, idesc, 1u);
                    mma_f16_ss(tmem, al + k * 2, bh + k * 2, idesc, 1u);
                }
                TCGEN05_COMMIT(buf ? mb1 : mb0);
            }
        }
        if (c + 2 < nch) {
            // wait until MMA(c) consumed this buffer, then refill it for c+2
            if (buf) { MBARRIER_WAIT_PARITY(mb1, ph1); ph1 ^= 1; }
            else     { MBARRIER_WAIT_PARITY(mb0, ph0); ph0 ^= 1; }
            load_chunk(c + 2, buf, kpt, taps, K, Ahi, Alo, Bhi, Blo,
                       tapStrideB, bm, bn, tb);
            asm volatile("cp.async.commit_group;" ::: "memory");
        }
    }
    // drain last two commits
    for (int c = nch - 2; c < nch; ++c) {
        const int buf = c & 1;
        if (buf) { MBARRIER_WAIT_PARITY(mb1, ph1); ph1 ^= 1; }
        else     { MBARRIER_WAIT_PARITY(mb0, ph0); ph0 ^= 1; }
    }
    TCGEN05_FENCE_AFTER();

    // epilogue: warps 0-3 read D (128 lanes x 256 cols)
    if (wid < 4) {
        const int row = bm + wid * 32 + lane;
        float* crow = C + (size_t)row * N + bn;
#pragma unroll 1
        for (int g = 0; g < 8; ++g) {
            uint32_t r[32];
            TCGEN05_LD_X32(r, tmem + g * 32);
            TCGEN05_WAIT_LD();
            const int cb = g * 32;
#pragma unroll
            for (int j = 0; j < 8; ++j) {
                float4 o;
                o.x = __uint_as_float(r[j * 4 + 0]);
                o.y = __uint_as_float(r[j * 4 + 1]);
                o.z = __uint_as_float(r[j * 4 + 2]);
                o.w = __uint_as_float(r[j * 4 + 3]);
                if (bias) {
                    float4 bi = *(const float4*)(bias + bn + cb + j * 4);
                    o.x += bi.x; o.y += bi.y; o.z += bi.z; o.w += bi.w;
                }
                if (accum) {
                    float4 p = *(const float4*)(crow + cb + j * 4);
                    o.x += p.x; o.y += p.y; o.z += p.z; o.w += p.w;
                }
                *(float4*)(crow + cb + j * 4) = o;
            }
        }
        TCGEN05_FENCE_BEFORE();
    }
    __syncthreads();
    if (tid == 0) { MBARRIER_INVAL(mb0); MBARRIER_INVAL(mb1); }
    if (wid == 0) { TCGEN05_DEALLOC(tmem, TN); }
#else
    // ------------------- warp-level HMMA fallback -----------------------------
    // 8 warps in 2(M) x 4(N): each warp computes 64x64 of the 128x256 tile.
    const int wm = wid & 1, wn = wid >> 1;
    float acc[4][8][4];
#pragma unroll
    for (int mt = 0; mt < 4; ++mt)
#pragma unroll
        for (int nt = 0; nt < 8; ++nt)
#pragma unroll
            for (int q = 0; q < 4; ++q) acc[mt][nt][q] = 0.f;

    load_chunk(0, 0, kpt, taps, K, Ahi, Alo, Bhi, Blo, tapStrideB, bm, bn, tb);
    asm volatile("cp.async.commit_group;" ::: "memory");
    load_chunk(1, 1, kpt, taps, K, Ahi, Alo, Bhi, Blo, tapStrideB, bm, bn, tb);
    asm volatile("cp.async.commit_group;" ::: "memory");

    const uint32_t a_lrow = (uint32_t)(wm * 64 + (lane & 15));
    const uint32_t a_lkb  = (uint32_t)((lane >> 4) << 4);
    const uint32_t b_lrow = (uint32_t)(wn * 64 + (lane & 7));
    const uint32_t b_lkb  = (uint32_t)(((lane >> 3) & 1) << 4);

    for (int c = 0; c < nch; ++c) {
        const int buf = c & 1;
        if (c + 1 == nch) asm volatile("cp.async.wait_group 0;" ::: "memory");
        else              asm volatile("cp.async.wait_group 1;" ::: "memory");
        __syncthreads();
        const uint32_t sb = tb + (uint32_t)buf * STAGE_BYTES;
#pragma unroll
        for (int k16 = 0; k16 < 4; ++k16) {
            const uint32_t kb = (uint32_t)(k16 * 32);
            uint32_t ah[4][4], al[4][4];
#pragma unroll
            for (int mt = 0; mt < 4; ++mt) {
                const uint32_t off = SW128((a_lrow + mt * 16) * 128 + kb + a_lkb);
                ldsm_x4(ah[mt], sb + SM_A_HI + off);
                ldsm_x4(al[mt], sb + SM_A_LO + off);
            }
#pragma unroll
            for (int nt = 0; nt < 8; ++nt) {
                uint32_t bh[2], bl[2];
                const uint32_t off = SW128((b_lrow + nt * 8) * 128 + kb + b_lkb);
                ldsm_x2(bh, sb + SM_B_HI + off);
                ldsm_x2(bl, sb + SM_B_LO + off);
#pragma unroll
                for (int mt = 0; mt < 4; ++mt) {
                    mma16816(acc[mt][nt], ah[mt], bh);
                    mma16816(acc[mt][nt], ah[mt], bl);
                    mma16816(acc[mt][nt], al[mt], bh);
                }
            }
        }
        __syncthreads();
        if (c + 2 < nch) {
            load_chunk(c + 2, buf, kpt, taps, K, Ahi, Alo, Bhi, Blo,
                       tapStrideB, bm, bn, tb);
            asm volatile("cp.async.commit_group;" ::: "memory");
        }
    }

    // epilogue
    const int r0 = lane >> 2;
    const int c0 = (lane & 3) * 2;
#pragma unroll
    for (int mt = 0; mt < 4; ++mt) {
#pragma unroll
        for (int nt = 0; nt < 8; ++nt) {
            const int col = bn + wn * 64 + nt * 8 + c0;
            float bx = 0.f, by = 0.f;
            if (bias) { bx = bias[col]; by = bias[col + 1]; }
#pragma unroll
            for (int rr = 0; rr < 2; ++rr) {
                const int row = bm + wm * 64 + mt * 16 + r0 + rr * 8;
                float* p = C + (size_t)row * N + col;
                float vx = acc[mt][nt][rr * 2 + 0] + bx;
                float vy = acc[mt][nt][rr * 2 + 1] + by;
                if (accum) { vx += p[0]; vy += p[1]; }
                p[0] = vx; p[1] = vy;
            }
        }
    }
#endif
}

// ------------------------- conversions ----------------------------------------
__device__ __forceinline__ void split_store(float v, __nv_bfloat16* hi, __nv_bfloat16* lo) {
    __nv_bfloat16 h = __float2bfloat16(v);
    *hi = h;
    *lo = __float2bfloat16(v - __bfloat162float(h));
}

__global__ void cvt_split(const float* __restrict__ in, __nv_bfloat16* __restrict__ hi,
                          __nv_bfloat16* __restrict__ lo, int n4)
{
    const int i = blockIdx.x * 256 + threadIdx.x;
    if (i < n4) {
        float4 v = ((const float4*)in)[i];
        split_store(v.x, hi + i * 4 + 0, lo + i * 4 + 0);
        split_store(v.y, hi + i * 4 + 1, lo + i * 4 + 1);
        split_store(v.z, hi + i * 4 + 2, lo + i * 4 + 2);
        split_store(v.w, hi + i * 4 + 3, lo + i * 4 + 3);
    }
}

__global__ void cvt_split_mul(const float* __restrict__ a, const float* __restrict__ b,
                              __nv_bfloat16* __restrict__ hi, __nv_bfloat16* __restrict__ lo,
                              int n4)
{
    const int i = blockIdx.x * 256 + threadIdx.x;
    if (i < n4) {
        float4 va = ((const float4*)a)[i];
        float4 vb = ((const float4*)b)[i];
        split_store(va.x * vb.x, hi + i * 4 + 0, lo + i * 4 + 0);
        split_store(va.y * vb.y, hi + i * 4 + 1, lo + i * 4 + 1);
        split_store(va.z * vb.z, hi + i * 4 + 2, lo + i * 4 + 2);
        split_store(va.w * vb.w, hi + i * 4 + 3, lo + i * 4 + 3);
    }
}

// convW [L][O=H][I=H][3] -> [L][tap][O][I] split
__global__ void cvt_convw(const float* __restrict__ w, __nv_bfloat16* __restrict__ hi,
                          __nv_bfloat16* __restrict__ lo)
{
    const size_t idx = (size_t)blockIdx.x * 256 + threadIdx.x;
    const size_t total = (size_t)LAYERS * 3 * HH * HH;
    if (idx < total) {
        const int i = (int)(idx & (HH - 1));
        size_t r = idx >> 11;
        const int o = (int)(r & (HH - 1));
        r >>= 11;
        const int tap = (int)(r % 3);
        const int l = (int)(r / 3);
        const float v = w[(((size_t)l * HH + o) * HH + i) * 3 + tap];
        split_store(v, hi + idx, lo + idx);
    }
}

// ------------------------------ LayerNorm (+SiLU) -----------------------------
template<int DO_SILU>
__global__ void ln_kernel(const float* __restrict__ in, float* __restrict__ out,
                          const float* __restrict__ g, const float* __restrict__ b)
{
    __shared__ float red[8];
    __shared__ float s_mean, s_rstd;
    const int row = blockIdx.x;
    const float4* ip = (const float4*)(in + (size_t)row * HH);
    float4 v0 = ip[threadIdx.x];
    float4 v1 = ip[threadIdx.x + 256];

    float s = v0.x+v0.y+v0.z+v0.w + v1.x+v1.y+v1.z+v1.w;
#pragma unroll
    for (int o = 16; o; o >>= 1) s += __shfl_xor_sync(0xffffffffu, s, o);
    const int wid = threadIdx.x >> 5, lane = threadIdx.x & 31;
    if (lane == 0) red[wid] = s;
    __syncthreads();
    if (threadIdx.x == 0) {
        float tt = 0.f;
#pragma unroll
        for (int i = 0; i < 8; i++) tt += red[i];
        s_mean = tt * (1.0f / HH);
    }
    __syncthreads();
    const float mean = s_mean;
    float d, ss = 0.f;
    d=v0.x-mean; ss+=d*d; d=v0.y-mean; ss+=d*d; d=v0.z-mean; ss+=d*d; d=v0.w-mean; ss+=d*d;
    d=v1.x-mean; ss+=d*d; d=v1.y-mean; ss+=d*d; d=v1.z-mean; ss+=d*d; d=v1.w-mean; ss+=d*d;
#pragma unroll
    for (int o = 16; o; o >>= 1) ss += __shfl_xor_sync(0xffffffffu, ss, o);
    if (lane == 0) red[wid] = ss;
    __syncthreads();
    if (threadIdx.x == 0) {
        float tt = 0.f;
#pragma unroll
        for (int i = 0; i < 8; i++) tt += red[i];
        s_rstd = rsqrtf(tt * (1.0f / HH) + EPSLN);
    }
    __syncthreads();
    const float rstd = s_rstd;

    float4 g0 = ((const float4*)g)[threadIdx.x];
    float4 g1 = ((const float4*)g)[threadIdx.x + 256];
    float4 b0 = ((const float4*)b)[threadIdx.x];
    float4 b1 = ((const float4*)b)[threadIdx.x + 256];
    float4 o0, o1;
    o0.x=(v0.x-mean)*rstd*g0.x+b0.x; o0.y=(v0.y-mean)*rstd*g0.y+b0.y;
    o0.z=(v0.z-mean)*rstd*g0.z+b0.z; o0.w=(v0.w-mean)*rstd*g0.w+b0.w;
    o1.x=(v1.x-mean)*rstd*g1.x+b1.x; o1.y=(v1.y-mean)*rstd*g1.y+b1.y;
    o1.z=(v1.z-mean)*rstd*g1.z+b1.z; o1.w=(v1.w-mean)*rstd*g1.w+b1.w;
    if (DO_SILU) {
        o0.x = o0.x / (1.f + expf(-o0.x)); o0.y = o0.y / (1.f + expf(-o0.y));
        o0.z = o0.z / (1.f + expf(-o0.z)); o0.w = o0.w / (1.f + expf(-o0.w));
        o1.x = o1.x / (1.f + expf(-o1.x)); o1.y = o1.y / (1.f + expf(-o1.y));
        o1.z = o1.z / (1.f + expf(-o1.z)); o1.w = o1.w / (1.f + expf(-o1.w));
    }
    float4* op = (float4*)(out + (size_t)row * HH);
    op[threadIdx.x]       = o0;
    op[threadIdx.x + 256] = o1;
}

// ------------------------------- minGRU scan ----------------------------------
__device__ __forceinline__ float softplusf(float x) {
    return fmaxf(x, 0.0f) + log1pf(expf(-fabsf(x)));
}
__device__ __forceinline__ float loggf(float x) {
    return (x >= 0.0f) ? logf(x + 0.5f) : -softplusf(-x);
}
__device__ __forceinline__ float laddexp(float a, float b) {
    float m = fmaxf(a, b);
    float d = fminf(a, b) - m;
    return m + log1pf(expf(d));
}

__global__ void scan_a(const float* __restrict__ Kx, const float* __restrict__ Px,
                       float* __restrict__ rend, float* __restrict__ asum)
{
    const int tid = blockIdx.x * 256 + threadIdx.x;
    const int h = tid & (HH - 1);
    const int rest = tid >> 11;
    const int j = rest & (CHUNKS - 1);
    const int b = rest >> CLOG;
    const size_t base = ((size_t)b * SS + (size_t)j * CLEN) * HH + h;
    float A = 0.f, r = -__int_as_float(0x7f800000);
    for (int tt = 0; tt < CLEN; tt++) {
        const float kv = Kx[base + (size_t)tt * HH];
        const float pv = Px[base + (size_t)tt * HH];
        const float lc = -softplusf(kv);
        const float lv = -softplusf(-kv) + loggf(pv);
        A += lc;
        r = laddexp(r + lc, lv);
    }
    rend[tid] = r;
    asum[tid] = A;
}

__global__ void scan_b(const float* __restrict__ rend, const float* __restrict__ asum,
                       float* __restrict__ lhin)
{
    const int tid = blockIdx.x * 256 + threadIdx.x;
    const int h = tid & (HH - 1);
    const int b = tid >> 11;
    float carry = -0.69314718056f;
#pragma unroll
    for (int j = 0; j < CHUNKS; j++) {
        const int idx = ((b * CHUNKS + j) << 11) + h;
        lhin[idx] = carry;
        carry = laddexp(asum[idx] + carry, rend[idx]);
    }
}

__global__ void scan_c(const float* __restrict__ Kx, const float* __restrict__ Px,
                       const float* __restrict__ lhin, float* __restrict__ out)
{
    const int tid = blockIdx.x * 256 + threadIdx.x;
    const int h = tid & (HH - 1);
    const int rest = tid >> 11;
    const int j = rest & (CHUNKS - 1);
    const int b = rest >> CLOG;
    const size_t base = ((size_t)b * SS + (size_t)j * CLEN) * HH + h;
    const float lhi = lhin[tid];
    float A = 0.f, r = -__int_as_float(0x7f800000);
    for (int tt = 0; tt < CLEN; tt++) {
        const float kv = Kx[base + (size_t)tt * HH];
        const float pv = Px[base + (size_t)tt * HH];
        const float lc = -softplusf(kv);
        const float lv = -softplusf(-kv) + loggf(pv);
        A += lc;
        r = laddexp(r + lc, lv);
        out[base + (size_t)tt * HH] = expf(laddexp(r, A + lhi));
    }
}

// --------------------------------- driver -------------------------------------
extern "C" void kernel_launch(void* const* d_in, const int* in_sizes, int n_in,
                              void* d_out, int out_size)
{
    const float* x    = (const float*)d_in[0];
    const float* Wp1  = (const float*)d_in[1];
    const float* bp1  = (const float*)d_in[2];
    const float* Wp2  = (const float*)d_in[3];
    const float* bp2  = (const float*)d_in[4];
    const float* convW= (const float*)d_in[5];
    const float* convb= (const float*)d_in[6];
    const float* Wz   = (const float*)d_in[7];
    const float* bz   = (const float*)d_in[8];
    const float* Wh   = (const float*)d_in[9];
    const float* bh   = (const float*)d_in[10];
    const float* Wd   = (const float*)d_in[11];
    const float* bd   = (const float*)d_in[12];
    const float* lng  = (const float*)d_in[13];
    const float* lnb  = (const float*)d_in[14];
    float* xb = (float*)d_out;

    float *b0,*b2,*b3,*b4,*rend,*asum,*lhin;
    __nv_bfloat16 *cvth,*cvtl,*wp1h,*wp1l,*wp2h,*wp2l,*wzh,*wzl,*whh,*whl,*wdh,*wdl,*wch,*wcl;
    cudaGetSymbolAddress((void**)&b0,  g_b0);
    cudaGetSymbolAddress((void**)&b2,  g_b2);
    cudaGetSymbolAddress((void**)&b3,  g_b3);
    cudaGetSymbolAddress((void**)&b4,  g_b4);
    cudaGetSymbolAddress((void**)&rend,g_rend);
    cudaGetSymbolAddress((void**)&asum,g_asum);
    cudaGetSymbolAddress((void**)&lhin,g_lhin);
    cudaGetSymbolAddress((void**)&cvth,g_cvth);
    cudaGetSymbolAddress((void**)&cvtl,g_cvtl);
    cudaGetSymbolAddress((void**)&wp1h,g_wp1h);
    cudaGetSymbolAddress((void**)&wp1l,g_wp1l);
    cudaGetSymbolAddress((void**)&wp2h,g_wp2h);
    cudaGetSymbolAddress((void**)&wp2l,g_wp2l);
    cudaGetSymbolAddress((void**)&wzh, g_wzh);
    cudaGetSymbolAddress((void**)&wzl, g_wzl);
    cudaGetSymbolAddress((void**)&whh, g_whh);
    cudaGetSymbolAddress((void**)&whl, g_whl);
    cudaGetSymbolAddress((void**)&wdh, g_wdh);
    cudaGetSymbolAddress((void**)&wdl, g_wdl);
    cudaGetSymbolAddress((void**)&wch, g_wch);
    cudaGetSymbolAddress((void**)&wcl, g_wcl);

    cudaFuncSetAttribute(gemm_ts, cudaFuncAttributeMaxDynamicSharedMemorySize, SMEM_DYN);

    cudaMemcpyAsync(xb, x, (size_t)MTOK * DD * sizeof(float),
                    cudaMemcpyDeviceToDevice, 0);

    // weight conversions (every launch; deterministic)
    {
        const int npd = LAYERS*HH*DD/4;
        const int nhh = LAYERS*HH*HH/4;
        cvt_split<<<(npd+255)/256, 256>>>(Wp1, wp1h, wp1l, npd);
        cvt_split<<<(npd+255)/256, 256>>>(Wp2, wp2h, wp2l, npd);
        cvt_split<<<(nhh+255)/256, 256>>>(Wz,  wzh,  wzl,  nhh);
        cvt_split<<<(nhh+255)/256, 256>>>(Wh,  whh,  whl,  nhh);
        cvt_split<<<(npd+255)/256, 256>>>(Wd,  wdh,  wdl,  npd);
        const size_t ct = (size_t)LAYERS*3*HH*HH;
        cvt_convw<<<(unsigned)((ct+255)/256), 256>>>(convW, wch, wcl);
    }

    const dim3 gH(HH/TN, MTOK/TM);   // (8, 64)
    const dim3 gD(DD/TN, MTOK/TM);   // (4, 64)
    const int nx4 = MTOK*DD/4;
    const int nh4 = MTOK*HH/4;

    for (int i = 0; i < LAYERS; i++) {
        // convert x -> bf16 hi/lo
        cvt_split<<<(nx4+255)/256, 256>>>(xb, cvth, cvtl, nx4);

        // strand 2 first (frees cvt buffer for s1 conversions)
        gemm_ts<<<gH, 256, SMEM_DYN>>>(cvth, cvtl, wp2h + (size_t)i*HH*DD, wp2l + (size_t)i*HH*DD,
                                       bp2 + i*HH, b4, HH, DD, 1, 0, 0);
        ln_kernel<1><<<MTOK, 256>>>(b4, b4, lng + (size_t)(i*4+3)*HH, lnb + (size_t)(i*4+3)*HH);

        // strand 1: proj1 + LN0
        gemm_ts<<<gH, 256, SMEM_DYN>>>(cvth, cvtl, wp1h + (size_t)i*HH*DD, wp1l + (size_t)i*HH*DD,
                                       bp1 + i*HH, b0, HH, DD, 1, 0, 0);
        ln_kernel<0><<<MTOK, 256>>>(b0, b0, lng + (size_t)(i*4+0)*HH, lnb + (size_t)(i*4+0)*HH);

        // conv1d: 3 shifted taps accumulated
        cvt_split<<<(nh4+255)/256, 256>>>(b0, cvth, cvtl, nh4);
        gemm_ts<<<gH, 256, SMEM_DYN>>>(cvth, cvtl, wch + (size_t)i*3*HH*HH, wcl + (size_t)i*3*HH*HH,
                                       convb + i*HH, b0, HH, HH, 3, (size_t)HH*HH, 0);
        ln_kernel<1><<<MTOK, 256>>>(b0, b0, lng + (size_t)(i*4+1)*HH, lnb + (size_t)(i*4+1)*HH);

        // minGRU projections + scan
        cvt_split<<<(nh4+255)/256, 256>>>(b0, cvth, cvtl, nh4);
        gemm_ts<<<gH, 256, SMEM_DYN>>>(cvth, cvtl, wzh + (size_t)i*HH*HH, wzl + (size_t)i*HH*HH,
                                       bz + i*HH, b2, HH, HH, 1, 0, 0);
        gemm_ts<<<gH, 256, SMEM_DYN>>>(cvth, cvtl, whh + (size_t)i*HH*HH, whl + (size_t)i*HH*HH,
                                       bh + i*HH, b3, HH, HH, 1, 0, 0);
        scan_a<<<(BB*CHUNKS*HH)/256, 256>>>(b2, b3, rend, asum);
        scan_b<<<(BB*HH)/256, 256>>>(rend, asum, lhin);
        scan_c<<<(BB*CHUNKS*HH)/256, 256>>>(b2, b3, lhin, b0);
        ln_kernel<0><<<MTOK, 256>>>(b0, b0, lng + (size_t)(i*4+2)*HH, lnb + (size_t)(i*4+2)*HH);

        // down projection of (s1 * s2) + bias + residual
        cvt_split_mul<<<(nh4+255)/256, 256>>>(b0, b4, cvth, cvtl, nh4);
        gemm_ts<<<gD, 256, SMEM_DYN>>>(cvth, cvtl, wdh + (size_t)i*DD*HH, wdl + (size_t)i*DD*HH,
                                       bd + i*DD, xb, DD, HH, 1, 0, 1);
    }
}

// round 6
// speedup vs baseline: 10.7138x; 1.0145x over previous
#include <cuda_runtime.h>
#include <cuda_bf16.h>
#include <math.h>
#include <stdint.h>

#define LAYERS 4
#define BB 4
#define SS 2048
#define DD 1024
#define HH 2048
#define MTOK (BB*SS)      /* 8192 tokens */
#define EPSLN 1e-5f

#define CHUNKS 16
#define CLOG 4
#define CLEN (SS/CHUNKS)  /* 128 */

// arch-feature gate: tcgen05 only exists on the sm_103a/sm_100a ("a") targets.
#if defined(__CUDA_ARCH_FEAT_SM103_ALL) || defined(__CUDA_ARCH_FEAT_SM100_ALL)
#define USE_TC5 1
#else
#define USE_TC5 0
#endif

// ---- GEMM tiling ----
// CTA tile: 256(M) x 256(N). Two M=128 MMA accumulators in TMEM (cols 0-255, 256-511).
// K staged in 32-element column-halves of 128B-row SW128 tiles (stage parity = 64B col offset).
#define TM 256
#define TN 256
#define SM_A_HI 0          /* 256 rows x 128B */
#define SM_A_LO 32768
#define SM_B_HI 65536
#define SM_B_LO 98304
#define TILE_BYTES 131072
#define SMEM_DYN (1024 + 1024 + TILE_BYTES)

// ------------------------- scratch -------------------------------------------
__device__ __align__(256) float g_b0[(size_t)MTOK*HH];
__device__ __align__(256) float g_b2[(size_t)MTOK*HH];
__device__ __align__(256) float g_b3[(size_t)MTOK*HH];
__device__ __align__(256) float g_b4[(size_t)MTOK*HH];
__device__ __align__(256) __nv_bfloat16 g_cvth[(size_t)MTOK*HH];   // activation split
__device__ __align__(256) __nv_bfloat16 g_cvtl[(size_t)MTOK*HH];
__device__ __align__(256) __nv_bfloat16 g_cvtxh[(size_t)MTOK*DD];  // x split
__device__ __align__(256) __nv_bfloat16 g_cvtxl[(size_t)MTOK*DD];
__device__ __align__(256) __nv_bfloat16 g_wp1h[(size_t)LAYERS*HH*DD];
__device__ __align__(256) __nv_bfloat16 g_wp1l[(size_t)LAYERS*HH*DD];
__device__ __align__(256) __nv_bfloat16 g_wp2h[(size_t)LAYERS*HH*DD];
__device__ __align__(256) __nv_bfloat16 g_wp2l[(size_t)LAYERS*HH*DD];
__device__ __align__(256) __nv_bfloat16 g_wzh[(size_t)LAYERS*HH*HH];
__device__ __align__(256) __nv_bfloat16 g_wzl[(size_t)LAYERS*HH*HH];
__device__ __align__(256) __nv_bfloat16 g_whh[(size_t)LAYERS*HH*HH];
__device__ __align__(256) __nv_bfloat16 g_whl[(size_t)LAYERS*HH*HH];
__device__ __align__(256) __nv_bfloat16 g_wdh[(size_t)LAYERS*DD*HH];
__device__ __align__(256) __nv_bfloat16 g_wdl[(size_t)LAYERS*DD*HH];
__device__ __align__(256) __nv_bfloat16 g_wch[(size_t)LAYERS*3*HH*HH];
__device__ __align__(256) __nv_bfloat16 g_wcl[(size_t)LAYERS*3*HH*HH];
__device__ float g_rend[BB*CHUNKS*HH];
__device__ float g_asum[BB*CHUNKS*HH];
__device__ float g_lhin[BB*CHUNKS*HH];

// ------------------------- helpers --------------------------------------------
__device__ __forceinline__ uint32_t smem_u32(const void* p) {
    uint32_t a;
    asm("{ .reg .u64 t; cvta.to.shared.u64 t, %1; cvt.u32.u64 %0, t; }" : "=r"(a) : "l"(p));
    return a;
}
#define SW128(b) ((b) ^ (((b) >> 3) & 0x70))

__device__ __forceinline__ void cpasync16(uint32_t dst, const void* src, int srcsize) {
    asm volatile("cp.async.cg.shared.global [%0], [%1], 16, %2;\n"
                 :: "r"(dst), "l"(src), "r"(srcsize));
}

__device__ __forceinline__ void split_store(float v, __nv_bfloat16* hi, __nv_bfloat16* lo) {
    __nv_bfloat16 h = __float2bfloat16(v);
    *hi = h;
    *lo = __float2bfloat16(v - __bfloat162float(h));
}
__device__ __forceinline__ void split4(float4 v, uint2& h, uint2& l) {
    __nv_bfloat16 hx = __float2bfloat16(v.x), hy = __float2bfloat16(v.y);
    __nv_bfloat16 hz = __float2bfloat16(v.z), hw = __float2bfloat16(v.w);
    __nv_bfloat16 lx = __float2bfloat16(v.x - __bfloat162float(hx));
    __nv_bfloat16 ly = __float2bfloat16(v.y - __bfloat162float(hy));
    __nv_bfloat16 lz = __float2bfloat16(v.z - __bfloat162float(hz));
    __nv_bfloat16 lw = __float2bfloat16(v.w - __bfloat162float(hw));
    h.x = (uint32_t)__bfloat16_as_ushort(hx) | ((uint32_t)__bfloat16_as_ushort(hy) << 16);
    h.y = (uint32_t)__bfloat16_as_ushort(hz) | ((uint32_t)__bfloat16_as_ushort(hw) << 16);
    l.x = (uint32_t)__bfloat16_as_ushort(lx) | ((uint32_t)__bfloat16_as_ushort(ly) << 16);
    l.y = (uint32_t)__bfloat16_as_ushort(lz) | ((uint32_t)__bfloat16_as_ushort(lw) << 16);
}

#if USE_TC5
__device__ __forceinline__ uint32_t elect_one_pred() {
    uint32_t pred;
    asm volatile("{\n\t.reg .pred p;\n\telect.sync _|p, 0xFFFFFFFF;\n\t"
                 "selp.b32 %0, 1, 0, p;\n\t}" : "=r"(pred));
    return pred;
}

static constexpr uint64_t SMEM_DESC_BASE_SW128 =
    (uint64_t(2) << 61) | (uint64_t(1) << 46) | (uint64_t(64) << 32) | (uint64_t(1) << 16);
#define MAKE_SMEM_DESC(base_addr) \
    (SMEM_DESC_BASE_SW128 | ((uint64_t)((base_addr) >> 4) & 0x3FFF))

#define TCGEN05_ALLOC(smem_result_addr, nCols) \
    asm volatile("tcgen05.alloc.cta_group::1.sync.aligned.shared::cta.b32 [%0], %1;" \
        :: "r"((uint32_t)(smem_result_addr)), "r"((uint32_t)(nCols)) : "memory")
#define TCGEN05_DEALLOC(tmem_addr, nCols) \
    asm volatile("tcgen05.dealloc.cta_group::1.sync.aligned.b32 %0, %1;" \
        :: "r"(tmem_addr), "r"((uint32_t)(nCols)))
#define TCGEN05_RELINQUISH() \
    asm volatile("tcgen05.relinquish_alloc_permit.cta_group::1.sync.aligned;")
#define TCGEN05_COMMIT(mbar) \
    asm volatile("tcgen05.commit.cta_group::1.mbarrier::arrive::one.shared::cluster.b64 [%0];" \
        :: "r"((uint32_t)(mbar)) : "memory")
#define TCGEN05_FENCE_AFTER() \
    asm volatile("tcgen05.fence::after_thread_sync;" ::: "memory")
#define TCGEN05_FENCE_BEFORE() \
    asm volatile("tcgen05.fence::before_thread_sync;" ::: "memory")
#define TCGEN05_WAIT_LD() \
    asm volatile("tcgen05.wait::ld.sync.aligned;" ::: "memory")
#define MBARRIER_INIT(mbar, cnt) \
    asm volatile("mbarrier.init.shared.b64 [%0], %1;" \
        :: "r"((uint32_t)(mbar)), "r"((uint32_t)(cnt)) : "memory")
#define MBARRIER_INVAL(mbar) \
    asm volatile("mbarrier.inval.shared.b64 [%0];" :: "r"((uint32_t)(mbar)) : "memory")

#define MBARRIER_WAIT_PARITY(mbar_smem_addr, phase_parity) do { \
    uint32_t _mbar = (uint32_t)(mbar_smem_addr); \
    uint32_t _parity = (uint32_t)(phase_parity); \
    uint32_t _done; \
    asm volatile("{\n\t.reg .pred p;\n\t" \
        "mbarrier.try_wait.parity.acquire.cta.shared::cta.b64 p, [%1], %2;\n\t" \
        "selp.b32 %0, 1, 0, p;\n\t}" : "=r"(_done) : "r"(_mbar), "r"(_parity) : "memory"); \
    if (!_done) { \
        asm volatile("{\n\t.reg .pred P1;\n\t" \
            "WAIT_LOOP_%=:\n\t" \
            "mbarrier.try_wait.parity.acquire.cta.shared::cta.b64 P1, [%0], %1, 0x989680;\n\t" \
            "@P1 bra.uni WAIT_DONE_%=;\n\t" \
            "bra.uni WAIT_LOOP_%=;\n\t" \
            "WAIT_DONE_%=:\n\t}" :: "r"(_mbar), "r"(_parity) : "memory"); \
    } \
} while(0)

#define TCGEN05_LD_X32(r, tmem_addr) \
    asm volatile("tcgen05.ld.sync.aligned.32x32b.x32.b32 " \
        "{%0, %1, %2, %3, %4, %5, %6, %7, %8, %9, %10, %11, %12, %13, %14, %15, " \
        "%16, %17, %18, %19, %20, %21, %22, %23, %24, %25, %26, %27, %28, %29, %30, %31}, [%32];" \
        : "=r"((r)[0]),  "=r"((r)[1]),  "=r"((r)[2]),  "=r"((r)[3]), \
          "=r"((r)[4]),  "=r"((r)[5]),  "=r"((r)[6]),  "=r"((r)[7]), \
          "=r"((r)[8]),  "=r"((r)[9]),  "=r"((r)[10]), "=r"((r)[11]), \
          "=r"((r)[12]), "=r"((r)[13]), "=r"((r)[14]), "=r"((r)[15]), \
          "=r"((r)[16]), "=r"((r)[17]), "=r"((r)[18]), "=r"((r)[19]), \
          "=r"((r)[20]), "=r"((r)[21]), "=r"((r)[22]), "=r"((r)[23]), \
          "=r"((r)[24]), "=r"((r)[25]), "=r"((r)[26]), "=r"((r)[27]), \
          "=r"((r)[28]), "=r"((r)[29]), "=r"((r)[30]), "=r"((r)[31]) \
        : "r"(tmem_addr))

__device__ __forceinline__ void mma_f16_ss(uint32_t d, uint64_t ad, uint64_t bd,
                                           uint32_t idesc, uint32_t en) {
    asm volatile("{\n\t.reg .pred p;\n\tsetp.ne.u32 p, %4, 0;\n\t"
        "tcgen05.mma.cta_group::1.kind::f16 [%0], %1, %2, %3, {%5, %5, %5, %5}, p;\n\t}"
        :: "r"(d), "l"(ad), "l"(bd), "r"(idesc), "r"(en), "r"(0u) : "memory");
}
#endif

// ------------------------------- GEMM -----------------------------------------
// C[M=8192, N] (+)= sum_taps sum_k A'[m,k]*B_tap[n,k] + bias[n]
// A' rows shifted by (tap-1) within each batch (zero pad) when taps==3.
// hi/lo split bf16: acc += Ah*Bh + Ah*Bl + Al*Bh (fp32 accumulate in TMEM).
// Stage s = 32 K-elements, living in column-half (s&1) of the 128B-row tiles.
__device__ __forceinline__ void load_stage(
    int c, int kpt, int taps, int K,
    const __nv_bfloat16* __restrict__ Ahi, const __nv_bfloat16* __restrict__ Alo,
    const __nv_bfloat16* __restrict__ Bhi, const __nv_bfloat16* __restrict__ Blo,
    size_t tapStrideB, int bm, int bn, uint32_t tb)
{
    int tap = 0, kc = c;
    if (taps == 3) { tap = c / kpt; kc = c - tap * kpt; }
    const int shift = (taps == 3) ? (tap - 1) : 0;
    const int kbase = kc << 5;                 // 32 K per stage
    const uint32_t colb = (uint32_t)(c & 1) * 64;
    const int tid = threadIdx.x;

    // A: 256 rows x 4 16B-units (this half)
#pragma unroll
    for (int it = 0; it < 4; ++it) {
        const int u = tid + it * 256;
        const int r = u >> 2, c4 = u & 3;
        const int m = bm + r;
        const int t = m & (SS - 1);
        const bool ok = ((unsigned)(t + shift)) < (unsigned)SS;
        const int srcsz = ok ? 16 : 0;
        const size_t goff = (size_t)(ok ? (m + shift) : m) * K + kbase + c4 * 8;
        const uint32_t so = SW128((uint32_t)(r * 128 + colb + c4 * 16));
        cpasync16(tb + SM_A_HI + so, Ahi + goff, srcsz);
        cpasync16(tb + SM_A_LO + so, Alo + goff, srcsz);
    }
    // B: 256 rows x 4 units
    const __nv_bfloat16* Bh = Bhi + (size_t)tap * tapStrideB;
    const __nv_bfloat16* Bl = Blo + (size_t)tap * tapStrideB;
#pragma unroll
    for (int it = 0; it < 4; ++it) {
        const int u = tid + it * 256;
        const int r = u >> 2, c4 = u & 3;
        const size_t goff = (size_t)(bn + r) * K + kbase + c4 * 8;
        const uint32_t so = SW128((uint32_t)(r * 128 + colb + c4 * 16));
        cpasync16(tb + SM_B_HI + so, Bh + goff, 16);
        cpasync16(tb + SM_B_LO + so, Bl + goff, 16);
    }
}

__global__ __launch_bounds__(256, 1)
void gemm_ts(const __nv_bfloat16* __restrict__ Ahi, const __nv_bfloat16* __restrict__ Alo,
             const __nv_bfloat16* __restrict__ Bhi, const __nv_bfloat16* __restrict__ Blo,
             const float* __restrict__ bias, float* __restrict__ C,
             int N, int K, int taps, size_t tapStrideB, int accum,
             __nv_bfloat16* __restrict__ XsHi, __nv_bfloat16* __restrict__ XsLo)
{
    extern __shared__ char dsm[];
    const uint32_t raw = smem_u32(dsm);
    const uint32_t sb0 = (raw + 1023) & ~1023u;     // header (tmem ptr, mbars)
    const uint32_t tb  = sb0 + 1024;                // tiles, 1KB aligned

    const int tid = threadIdx.x;
    const int wid = tid >> 5;
    const int lane = tid & 31;
    const int bm = blockIdx.y * TM;
    const int bn = blockIdx.x * TN;
    const int kpt = K >> 5;                          // 32-K stages per tap
    const int nch = taps * kpt;

#if USE_TC5
    const uint32_t mb0 = sb0 + 8, mb1 = sb0 + 16;
    if (wid == 0) { TCGEN05_ALLOC(sb0, 512); TCGEN05_RELINQUISH(); }
    if (tid == 0) { MBARRIER_INIT(mb0, 1); MBARRIER_INIT(mb1, 1); }
    __syncthreads();
    uint32_t tmem;
    asm volatile("ld.shared.b32 %0, [%1];" : "=r"(tmem) : "r"(sb0));

    // per-MMA: M=128, N=256, bf16 in, fp32 out
    const uint32_t idesc = (1u << 4) | (1u << 7) | (1u << 10)
                         | ((TN / 8) << 17) | ((128 / 16) << 24);

    load_stage(0, kpt, taps, K, Ahi, Alo, Bhi, Blo, tapStrideB, bm, bn, tb);
    asm volatile("cp.async.commit_group;" ::: "memory");
    load_stage(1, kpt, taps, K, Ahi, Alo, Bhi, Blo, tapStrideB, bm, bn, tb);
    asm volatile("cp.async.commit_group;" ::: "memory");

    int ph0 = 0, ph1 = 0;
    for (int c = 0; c < nch; ++c) {
        const int buf = c & 1;
        if (c + 1 == nch) asm volatile("cp.async.wait_group 0;" ::: "memory");
        else              asm volatile("cp.async.wait_group 1;" ::: "memory");
        __syncthreads();

        if (wid == 0) {
            if (elect_one_pred()) {
                asm volatile("fence.proxy.async.shared::cta;" ::: "memory");
                const uint32_t cofs = (uint32_t)buf * 4;   // 64B column offset, 16B units
#pragma unroll
                for (int k = 0; k < 2; ++k) {
#pragma unroll
                    for (int h = 0; h < 2; ++h) {
                        const uint64_t ah = MAKE_SMEM_DESC(tb + SM_A_HI + h * 16384) + cofs + k * 2;
                        const uint64_t al = MAKE_SMEM_DESC(tb + SM_A_LO + h * 16384) + cofs + k * 2;
                        const uint64_t bh = MAKE_SMEM_DESC(tb + SM_B_HI) + cofs + k * 2;
                        const uint64_t bl = MAKE_SMEM_DESC(tb + SM_B_LO) + cofs + k * 2;
                        const uint32_t d = tmem + (uint32_t)h * 256;
                        mma_f16_ss(d, ah, bh, idesc, (c == 0 && k == 0) ? 0u : 1u);
                        mma_f16_ss(d, ah, bl, idesc, 1u);
                        mma_f16_ss(d, al, bh, idesc, 1u);
                    }
                }
                TCGEN05_COMMIT(buf ? mb1 : mb0);
            }
        }
        if (c + 2 < nch) {
            // wait until MMA(c) consumed this column-half, then refill it for c+2
            if (buf) { MBARRIER_WAIT_PARITY(mb1, ph1); ph1 ^= 1; }
            else     { MBARRIER_WAIT_PARITY(mb0, ph0); ph0 ^= 1; }
            load_stage(c + 2, kpt, taps, K, Ahi, Alo, Bhi, Blo,
                       tapStrideB, bm, bn, tb);
            asm volatile("cp.async.commit_group;" ::: "memory");
        }
    }
    // drain last two commits
    for (int c = nch - 2; c < nch; ++c) {
        const int buf = c & 1;
        if (buf) { MBARRIER_WAIT_PARITY(mb1, ph1); ph1 ^= 1; }
        else     { MBARRIER_WAIT_PARITY(mb0, ph0); ph0 ^= 1; }
    }
    TCGEN05_FENCE_AFTER();

    // epilogue: 8 warps; warps 0-3 -> M-half 0 (tmem cols 0-255), 4-7 -> half 1
    {
        const int h = wid >> 2;
        const int row = bm + h * 128 + (wid & 3) * 32 + lane;
        float* crow = C + (size_t)row * N + bn;
        const uint32_t tbase = tmem + (uint32_t)h * 256;
#pragma unroll 1
        for (int g = 0; g < 8; ++g) {
            uint32_t r[32];
            TCGEN05_LD_X32(r, tbase + g * 32);
            TCGEN05_WAIT_LD();
            const int cb = g * 32;
#pragma unroll
            for (int j = 0; j < 8; ++j) {
                float4 o;
                o.x = __uint_as_float(r[j * 4 + 0]);
                o.y = __uint_as_float(r[j * 4 + 1]);
                o.z = __uint_as_float(r[j * 4 + 2]);
                o.w = __uint_as_float(r[j * 4 + 3]);
                if (bias) {
                    float4 bi = *(const float4*)(bias + bn + cb + j * 4);
                    o.x += bi.x; o.y += bi.y; o.z += bi.z; o.w += bi.w;
                }
                if (accum) {
                    float4 p = *(const float4*)(crow + cb + j * 4);
                    o.x += p.x; o.y += p.y; o.z += p.z; o.w += p.w;
                }
                *(float4*)(crow + cb + j * 4) = o;
                if (XsHi) {
                    uint2 hh, ll;
                    split4(o, hh, ll);
                    const size_t xo = (size_t)row * N + bn + cb + j * 4;
                    *(uint2*)(XsHi + xo) = hh;
                    *(uint2*)(XsLo + xo) = ll;
                }
            }
        }
        TCGEN05_FENCE_BEFORE();
    }
    __syncthreads();
    if (tid == 0) { MBARRIER_INVAL(mb0); MBARRIER_INVAL(mb1); }
    if (wid == 0) { TCGEN05_DEALLOC(tmem, 512); }
#else
    // Correct SIMT fallback for non-'a' compile targets (never runs on GB300).
    (void)tb; (void)wid; (void)lane;
    for (int idx = tid; idx < TM * TN; idx += 256) {
        const int mi = idx >> 8;          // 0..255 (row within tile)
        const int ni = idx & 255;
        const int row = bm + mi;
        const int col = bn + ni;
        float acc = bias ? bias[col] : 0.f;
        for (int tap = 0; tap < taps; ++tap) {
            const int shift = (taps == 3) ? (tap - 1) : 0;
            const int t = row & (SS - 1);
            if (((unsigned)(t + shift)) >= (unsigned)SS) continue;
            const __nv_bfloat16* ar = Ahi + (size_t)(row + shift) * K;
            const __nv_bfloat16* al = Alo + (size_t)(row + shift) * K;
            const __nv_bfloat16* br = Bhi + (size_t)tap * tapStrideB + (size_t)col * K;
            const __nv_bfloat16* bl = Blo + (size_t)tap * tapStrideB + (size_t)col * K;
            for (int k = 0; k < K; ++k) {
                float a = __bfloat162float(ar[k]), a2 = __bfloat162float(al[k]);
                float b = __bfloat162float(br[k]), b2 = __bfloat162float(bl[k]);
                acc += a * b + a * b2 + a2 * b;
            }
        }
        float* p = C + (size_t)row * N + col;
        float v = acc + (accum ? *p : 0.f);
        *p = v;
        if (XsHi) split_store(v, XsHi + (size_t)row * N + col, XsLo + (size_t)row * N + col);
    }
#endif
}

// ------------------------- conversions ----------------------------------------
__global__ void cvt_split(const float* __restrict__ in, __nv_bfloat16* __restrict__ hi,
                          __nv_bfloat16* __restrict__ lo, int n4)
{
    const int i = blockIdx.x * 256 + threadIdx.x;
    if (i < n4) {
        float4 v = ((const float4*)in)[i];
        uint2 h, l;
        split4(v, h, l);
        ((uint2*)hi)[i] = h;
        ((uint2*)lo)[i] = l;
    }
}

// convW [L][O=H][I=H][3] -> [L][tap][O][I] split; one thread per (l,o,i) triple
__global__ void cvt_convw(const float* __restrict__ w, __nv_bfloat16* __restrict__ hi,
                          __nv_bfloat16* __restrict__ lo)
{
    const size_t idx = (size_t)blockIdx.x * 256 + threadIdx.x;  // over L*H*H
    const size_t total = (size_t)LAYERS * HH * HH;
    if (idx < total) {
        const int i = (int)(idx & (HH - 1));
        size_t r = idx >> 11;
        const int o = (int)(r & (HH - 1));
        const int l = (int)(r >> 11);
        const float* p = w + idx * 3;
#pragma unroll
        for (int tap = 0; tap < 3; ++tap) {
            const size_t dst = (((size_t)l * 3 + tap) * HH + o) * HH + i;
            split_store(p[tap], hi + dst, lo + dst);
        }
    }
}

// ------------------------------ LayerNorm family ------------------------------
// Shared LN body computes mean/rstd for one row of HH.
#define LN_PROLOG() \
    __shared__ float red[8]; \
    __shared__ float s_mean, s_rstd; \
    const int row = blockIdx.x; \
    const float4* ip = (const float4*)(in + (size_t)row * HH); \
    float4 v0 = ip[threadIdx.x]; \
    float4 v1 = ip[threadIdx.x + 256]; \
    float s = v0.x+v0.y+v0.z+v0.w + v1.x+v1.y+v1.z+v1.w; \
    _Pragma("unroll") \
    for (int o = 16; o; o >>= 1) s += __shfl_xor_sync(0xffffffffu, s, o); \
    const int wid = threadIdx.x >> 5, lane = threadIdx.x & 31; \
    if (lane == 0) red[wid] = s; \
    __syncthreads(); \
    if (threadIdx.x == 0) { \
        float tt = 0.f; \
        _Pragma("unroll") \
        for (int i = 0; i < 8; i++) tt += red[i]; \
        s_mean = tt * (1.0f / HH); \
    } \
    __syncthreads(); \
    const float mean = s_mean; \
    float d, ss = 0.f; \
    d=v0.x-mean; ss+=d*d; d=v0.y-mean; ss+=d*d; d=v0.z-mean; ss+=d*d; d=v0.w-mean; ss+=d*d; \
    d=v1.x-mean; ss+=d*d; d=v1.y-mean; ss+=d*d; d=v1.z-mean; ss+=d*d; d=v1.w-mean; ss+=d*d; \
    _Pragma("unroll") \
    for (int o = 16; o; o >>= 1) ss += __shfl_xor_sync(0xffffffffu, ss, o); \
    if (lane == 0) red[wid] = ss; \
    __syncthreads(); \
    if (threadIdx.x == 0) { \
        float tt = 0.f; \
        _Pragma("unroll") \
        for (int i = 0; i < 8; i++) tt += red[i]; \
        s_rstd = rsqrtf(tt * (1.0f / HH) + EPSLN); \
    } \
    __syncthreads(); \
    const float rstd = s_rstd; \
    float4 g0 = ((const float4*)g)[threadIdx.x]; \
    float4 g1 = ((const float4*)g)[threadIdx.x + 256]; \
    float4 b0 = ((const float4*)b)[threadIdx.x]; \
    float4 b1 = ((const float4*)b)[threadIdx.x + 256]; \
    float4 o0, o1; \
    o0.x=(v0.x-mean)*rstd*g0.x+b0.x; o0.y=(v0.y-mean)*rstd*g0.y+b0.y; \
    o0.z=(v0.z-mean)*rstd*g0.z+b0.z; o0.w=(v0.w-mean)*rstd*g0.w+b0.w; \
    o1.x=(v1.x-mean)*rstd*g1.x+b1.x; o1.y=(v1.y-mean)*rstd*g1.y+b1.y; \
    o1.z=(v1.z-mean)*rstd*g1.z+b1.z; o1.w=(v1.w-mean)*rstd*g1.w+b1.w;

__device__ __forceinline__ float4 silu4(float4 v) {
    v.x = v.x / (1.f + expf(-v.x)); v.y = v.y / (1.f + expf(-v.y));
    v.z = v.z / (1.f + expf(-v.z)); v.w = v.w / (1.f + expf(-v.w));
    return v;
}

// LN -> fp32 out (optionally SiLU)  [used for LN3 / s2]
template<int DO_SILU>
__global__ void ln_kernel(const float* __restrict__ in, float* __restrict__ out,
                          const float* __restrict__ g, const float* __restrict__ b)
{
    LN_PROLOG();
    if (DO_SILU) { o0 = silu4(o0); o1 = silu4(o1); }
    float4* op = (float4*)(out + (size_t)row * HH);
    op[threadIdx.x]       = o0;
    op[threadIdx.x + 256] = o1;
}

// LN -> split bf16 out (optionally SiLU)  [LN0, LN1]
template<int DO_SILU>
__global__ void ln_split(const float* __restrict__ in,
                         __nv_bfloat16* __restrict__ oh, __nv_bfloat16* __restrict__ ol,
                         const float* __restrict__ g, const float* __restrict__ b)
{
    LN_PROLOG();
    if (DO_SILU) { o0 = silu4(o0); o1 = silu4(o1); }
    uint2 h0, l0, h1, l1;
    split4(o0, h0, l0);
    split4(o1, h1, l1);
    uint2* hp = (uint2*)(oh + (size_t)row * HH);
    uint2* lp = (uint2*)(ol + (size_t)row * HH);
    hp[threadIdx.x] = h0; hp[threadIdx.x + 256] = h1;
    lp[threadIdx.x] = l0; lp[threadIdx.x + 256] = l1;
}

// LN(in) * mul -> split bf16 out  [LN2 fused with s1*s2]
__global__ void ln_mul_split(const float* __restrict__ in, const float* __restrict__ mul,
                             __nv_bfloat16* __restrict__ oh, __nv_bfloat16* __restrict__ ol,
                             const float* __restrict__ g, const float* __restrict__ b)
{
    LN_PROLOG();
    const float4* mp = (const float4*)(mul + (size_t)row * HH);
    float4 m0 = mp[threadIdx.x];
    float4 m1 = mp[threadIdx.x + 256];
    o0.x *= m0.x; o0.y *= m0.y; o0.z *= m0.z; o0.w *= m0.w;
    o1.x *= m1.x; o1.y *= m1.y; o1.z *= m1.z; o1.w *= m1.w;
    uint2 h0, l0, h1, l1;
    split4(o0, h0, l0);
    split4(o1, h1, l1);
    uint2* hp = (uint2*)(oh + (size_t)row * HH);
    uint2* lp = (uint2*)(ol + (size_t)row * HH);
    hp[threadIdx.x] = h0; hp[threadIdx.x + 256] = h1;
    lp[threadIdx.x] = l0; lp[threadIdx.x + 256] = l1;
}

// ------------------------------- minGRU scan ----------------------------------
__device__ __forceinline__ float softplusf(float x) {
    return fmaxf(x, 0.0f) + log1pf(expf(-fabsf(x)));
}
__device__ __forceinline__ float loggf(float x) {
    return (x >= 0.0f) ? logf(x + 0.5f) : -softplusf(-x);
}
__device__ __forceinline__ float laddexp(float a, float b) {
    float m = fmaxf(a, b);
    float d = fminf(a, b) - m;
    return m + log1pf(expf(d));
}

__global__ void scan_a(const float* __restrict__ Kx, const float* __restrict__ Px,
                       float* __restrict__ rend, float* __restrict__ asum)
{
    const int tid = blockIdx.x * 256 + threadIdx.x;
    const int h = tid & (HH - 1);
    const int rest = tid >> 11;
    const int j = rest & (CHUNKS - 1);
    const int b = rest >> CLOG;
    const size_t base = ((size_t)b * SS + (size_t)j * CLEN) * HH + h;
    float A = 0.f, r = -__int_as_float(0x7f800000);
    for (int tt = 0; tt < CLEN; tt++) {
        const float kv = Kx[base + (size_t)tt * HH];
        const float pv = Px[base + (size_t)tt * HH];
        const float lc = -softplusf(kv);
        const float lv = -softplusf(-kv) + loggf(pv);
        A += lc;
        r = laddexp(r + lc, lv);
    }
    rend[tid] = r;
    asum[tid] = A;
}

__global__ void scan_b(const float* __restrict__ rend, const float* __restrict__ asum,
                       float* __restrict__ lhin)
{
    const int tid = blockIdx.x * 256 + threadIdx.x;
    const int h = tid & (HH - 1);
    const int b = tid >> 11;
    float carry = -0.69314718056f;
#pragma unroll
    for (int j = 0; j < CHUNKS; j++) {
        const int idx = ((b * CHUNKS + j) << 11) + h;
        lhin[idx] = carry;
        carry = laddexp(asum[idx] + carry, rend[idx]);
    }
}

__global__ void scan_c(const float* __restrict__ Kx, const float* __restrict__ Px,
                       const float* __restrict__ lhin, float* __restrict__ out)
{
    const int tid = blockIdx.x * 256 + threadIdx.x;
    const int h = tid & (HH - 1);
    const int rest = tid >> 11;
    const int j = rest & (CHUNKS - 1);
    const int b = rest >> CLOG;
    const size_t base = ((size_t)b * SS + (size_t)j * CLEN) * HH + h;
    const float lhi = lhin[tid];
    float A = 0.f, r = -__int_as_float(0x7f800000);
    for (int tt = 0; tt < CLEN; tt++) {
        const float kv = Kx[base + (size_t)tt * HH];
        const float pv = Px[base + (size_t)tt * HH];
        const float lc = -softplusf(kv);
        const float lv = -softplusf(-kv) + loggf(pv);
        A += lc;
        r = laddexp(r + lc, lv);
        out[base + (size_t)tt * HH] = expf(laddexp(r, A + lhi));
    }
}

// --------------------------------- driver -------------------------------------
extern "C" void kernel_launch(void* const* d_in, const int* in_sizes, int n_in,
                              void* d_out, int out_size)
{
    const float* x    = (const float*)d_in[0];
    const float* Wp1  = (const float*)d_in[1];
    const float* bp1  = (const float*)d_in[2];
    const float* Wp2  = (const float*)d_in[3];
    const float* bp2  = (const float*)d_in[4];
    const float* convW= (const float*)d_in[5];
    const float* convb= (const float*)d_in[6];
    const float* Wz   = (const float*)d_in[7];
    const float* bz   = (const float*)d_in[8];
    const float* Wh   = (const float*)d_in[9];
    const float* bh   = (const float*)d_in[10];
    const float* Wd   = (const float*)d_in[11];
    const float* bd   = (const float*)d_in[12];
    const float* lng  = (const float*)d_in[13];
    const float* lnb  = (const float*)d_in[14];
    float* xb = (float*)d_out;

    float *b0,*b2,*b3,*b4,*rend,*asum,*lhin;
    __nv_bfloat16 *cvth,*cvtl,*cvtxh,*cvtxl;
    __nv_bfloat16 *wp1h,*wp1l,*wp2h,*wp2l,*wzh,*wzl,*whh,*whl,*wdh,*wdl,*wch,*wcl;
    cudaGetSymbolAddress((void**)&b0,  g_b0);
    cudaGetSymbolAddress((void**)&b2,  g_b2);
    cudaGetSymbolAddress((void**)&b3,  g_b3);
    cudaGetSymbolAddress((void**)&b4,  g_b4);
    cudaGetSymbolAddress((void**)&rend,g_rend);
    cudaGetSymbolAddress((void**)&asum,g_asum);
    cudaGetSymbolAddress((void**)&lhin,g_lhin);
    cudaGetSymbolAddress((void**)&cvth,g_cvth);
    cudaGetSymbolAddress((void**)&cvtl,g_cvtl);
    cudaGetSymbolAddress((void**)&cvtxh,g_cvtxh);
    cudaGetSymbolAddress((void**)&cvtxl,g_cvtxl);
    cudaGetSymbolAddress((void**)&wp1h,g_wp1h);
    cudaGetSymbolAddress((void**)&wp1l,g_wp1l);
    cudaGetSymbolAddress((void**)&wp2h,g_wp2h);
    cudaGetSymbolAddress((void**)&wp2l,g_wp2l);
    cudaGetSymbolAddress((void**)&wzh, g_wzh);
    cudaGetSymbolAddress((void**)&wzl, g_wzl);
    cudaGetSymbolAddress((void**)&whh, g_whh);
    cudaGetSymbolAddress((void**)&whl, g_whl);
    cudaGetSymbolAddress((void**)&wdh, g_wdh);
    cudaGetSymbolAddress((void**)&wdl, g_wdl);
    cudaGetSymbolAddress((void**)&wch, g_wch);
    cudaGetSymbolAddress((void**)&wcl, g_wcl);

    cudaFuncSetAttribute(gemm_ts, cudaFuncAttributeMaxDynamicSharedMemorySize, SMEM_DYN);

    cudaMemcpyAsync(xb, x, (size_t)MTOK * DD * sizeof(float),
                    cudaMemcpyDeviceToDevice, 0);

    // weight conversions (every launch; deterministic)
    {
        const int npd = LAYERS*HH*DD/4;
        const int nhh = LAYERS*HH*HH/4;
        cvt_split<<<(npd+255)/256, 256>>>(Wp1, wp1h, wp1l, npd);
        cvt_split<<<(npd+255)/256, 256>>>(Wp2, wp2h, wp2l, npd);
        cvt_split<<<(nhh+255)/256, 256>>>(Wz,  wzh,  wzl,  nhh);
        cvt_split<<<(nhh+255)/256, 256>>>(Wh,  whh,  whl,  nhh);
        cvt_split<<<(npd+255)/256, 256>>>(Wd,  wdh,  wdl,  npd);
        const size_t ct = (size_t)LAYERS*HH*HH;
        cvt_convw<<<(unsigned)((ct+255)/256), 256>>>(convW, wch, wcl);
    }

    // initial x split
    cvt_split<<<(MTOK*DD/4+255)/256, 256>>>(xb, cvtxh, cvtxl, MTOK*DD/4);

    const dim3 gH(HH/TN, MTOK/TM);   // (8, 32)
    const dim3 gD(DD/TN, MTOK/TM);   // (4, 32)

    for (int i = 0; i < LAYERS; i++) {
        // strand 2: proj2 + LN3(SiLU) -> b4 fp32
        gemm_ts<<<gH, 256, SMEM_DYN>>>(cvtxh, cvtxl,
                                       wp2h + (size_t)i*HH*DD, wp2l + (size_t)i*HH*DD,
                                       bp2 + i*HH, b4, HH, DD, 1, 0, 0, 0, 0);
        ln_kernel<1><<<MTOK, 256>>>(b4, b4, lng + (size_t)(i*4+3)*HH, lnb + (size_t)(i*4+3)*HH);

        // strand 1: proj1 -> b0; LN0 -> split
        gemm_ts<<<gH, 256, SMEM_DYN>>>(cvtxh, cvtxl,
                                       wp1h + (size_t)i*HH*DD, wp1l + (size_t)i*HH*DD,
                                       bp1 + i*HH, b0, HH, DD, 1, 0, 0, 0, 0);
        ln_split<0><<<MTOK, 256>>>(b0, cvth, cvtl,
                                   lng + (size_t)(i*4+0)*HH, lnb + (size_t)(i*4+0)*HH);

        // conv1d: 3 shifted taps accumulated in TMEM; LN1+SiLU -> split
        gemm_ts<<<gH, 256, SMEM_DYN>>>(cvth, cvtl,
                                       wch + (size_t)i*3*HH*HH, wcl + (size_t)i*3*HH*HH,
                                       convb + i*HH, b0, HH, HH, 3, (size_t)HH*HH, 0, 0, 0);
        ln_split<1><<<MTOK, 256>>>(b0, cvth, cvtl,
                                   lng + (size_t)(i*4+1)*HH, lnb + (size_t)(i*4+1)*HH);

        // minGRU projections + scan
        gemm_ts<<<gH, 256, SMEM_DYN>>>(cvth, cvtl,
                                       wzh + (size_t)i*HH*HH, wzl + (size_t)i*HH*HH,
                                       bz + i*HH, b2, HH, HH, 1, 0, 0, 0, 0);
        gemm_ts<<<gH, 256, SMEM_DYN>>>(cvth, cvtl,
                                       whh + (size_t)i*HH*HH, whl + (size_t)i*HH*HH,
                                       bh + i*HH, b3, HH, HH, 1, 0, 0, 0, 0);
        scan_a<<<(BB*CHUNKS*HH)/256, 256>>>(b2, b3, rend, asum);
        scan_b<<<(BB*HH)/256, 256>>>(rend, asum, lhin);
        scan_c<<<(BB*CHUNKS*HH)/256, 256>>>(b2, b3, lhin, b0);

        // LN2 fused with s1*s2 gating -> split
        ln_mul_split<<<MTOK, 256>>>(b0, b4, cvth, cvtl,
                                    lng + (size_t)(i*4+2)*HH, lnb + (size_t)(i*4+2)*HH);

        // down projection + bias + residual; epilogue also emits next layer's x split
        gemm_ts<<<gD, 256, SMEM_DYN>>>(cvth, cvtl,
                                       wdh + (size_t)i*DD*HH, wdl + (size_t)i*DD*HH,
                                       bd + i*DD, xb, DD, HH, 1, 0, 1, cvtxh, cvtxl);
    }
}

// round 8
// speedup vs baseline: 12.2954x; 1.1476x over previous
#include <cuda_runtime.h>
#include <cuda_bf16.h>
#include <math.h>
#include <stdint.h>

#define LAYERS 4
#define BB 4
#define SS 2048
#define DD 1024
#define HH 2048
#define MTOK (BB*SS)      /* 8192 tokens */
#define EPSLN 1e-5f

#define CHUNKS 16
#define CLOG 4
#define CLEN (SS/CHUNKS)  /* 128 */

// arch-feature gate: tcgen05 only exists on the sm_103a/sm_100a ("a") targets.
#if defined(__CUDA_ARCH_FEAT_SM103_ALL) || defined(__CUDA_ARCH_FEAT_SM100_ALL)
#define USE_TC5 1
#else
#define USE_TC5 0
#endif

// ---- GEMM tiling ----
// CTA tile: 256(M) x 256(N). Two M=128 MMA accumulators in TMEM (cols 0-255, 256-511).
// K pipelined in FOUR 16-element stages = 32B column-quarters of the 128B-row SW128
// tiles (slot = stage & 3). Loads run 3 stages ahead of the tensor pipe.
#define TM 256
#define TN 256
#define SM_A_HI 0          /* 256 rows x 128B */
#define SM_A_LO 32768
#define SM_B_HI 65536
#define SM_B_LO 98304
#define TILE_BYTES 131072
#define SMEM_DYN (1024 + 1024 + TILE_BYTES)

// ------------------------- scratch -------------------------------------------
__device__ __align__(256) float g_b0[(size_t)MTOK*HH];
__device__ __align__(256) float g_b2[(size_t)MTOK*HH];
__device__ __align__(256) float g_b3[(size_t)MTOK*HH];
__device__ __align__(256) float g_b4[(size_t)MTOK*HH];
__device__ __align__(256) __nv_bfloat16 g_cvth[(size_t)MTOK*HH];   // activation split
__device__ __align__(256) __nv_bfloat16 g_cvtl[(size_t)MTOK*HH];
__device__ __align__(256) __nv_bfloat16 g_cvtxh[(size_t)MTOK*DD];  // x split
__device__ __align__(256) __nv_bfloat16 g_cvtxl[(size_t)MTOK*DD];
__device__ __align__(256) __nv_bfloat16 g_wp1h[(size_t)LAYERS*HH*DD];
__device__ __align__(256) __nv_bfloat16 g_wp1l[(size_t)LAYERS*HH*DD];
__device__ __align__(256) __nv_bfloat16 g_wp2h[(size_t)LAYERS*HH*DD];
__device__ __align__(256) __nv_bfloat16 g_wp2l[(size_t)LAYERS*HH*DD];
__device__ __align__(256) __nv_bfloat16 g_wzh[(size_t)LAYERS*HH*HH];
__device__ __align__(256) __nv_bfloat16 g_wzl[(size_t)LAYERS*HH*HH];
__device__ __align__(256) __nv_bfloat16 g_whh[(size_t)LAYERS*HH*HH];
__device__ __align__(256) __nv_bfloat16 g_whl[(size_t)LAYERS*HH*HH];
__device__ __align__(256) __nv_bfloat16 g_wdh[(size_t)LAYERS*DD*HH];
__device__ __align__(256) __nv_bfloat16 g_wdl[(size_t)LAYERS*DD*HH];
__device__ __align__(256) __nv_bfloat16 g_wch[(size_t)LAYERS*3*HH*HH];
__device__ __align__(256) __nv_bfloat16 g_wcl[(size_t)LAYERS*3*HH*HH];
__device__ float g_rend[BB*CHUNKS*HH];
__device__ float g_asum[BB*CHUNKS*HH];
__device__ float g_lhin[BB*CHUNKS*HH];

// ------------------------- helpers --------------------------------------------
__device__ __forceinline__ uint32_t smem_u32(const void* p) {
    uint32_t a;
    asm("{ .reg .u64 t; cvta.to.shared.u64 t, %1; cvt.u32.u64 %0, t; }" : "=r"(a) : "l"(p));
    return a;
}
#define SW128(b) ((b) ^ (((b) >> 3) & 0x70))

__device__ __forceinline__ void cpasync16(uint32_t dst, const void* src, int srcsize) {
    asm volatile("cp.async.cg.shared.global [%0], [%1], 16, %2;\n"
                 :: "r"(dst), "l"(src), "r"(srcsize));
}

__device__ __forceinline__ void split_store(float v, __nv_bfloat16* hi, __nv_bfloat16* lo) {
    __nv_bfloat16 h = __float2bfloat16(v);
    *hi = h;
    *lo = __float2bfloat16(v - __bfloat162float(h));
}
__device__ __forceinline__ void split4(float4 v, uint2& h, uint2& l) {
    __nv_bfloat16 hx = __float2bfloat16(v.x), hy = __float2bfloat16(v.y);
    __nv_bfloat16 hz = __float2bfloat16(v.z), hw = __float2bfloat16(v.w);
    __nv_bfloat16 lx = __float2bfloat16(v.x - __bfloat162float(hx));
    __nv_bfloat16 ly = __float2bfloat16(v.y - __bfloat162float(hy));
    __nv_bfloat16 lz = __float2bfloat16(v.z - __bfloat162float(hz));
    __nv_bfloat16 lw = __float2bfloat16(v.w - __bfloat162float(hw));
    h.x = (uint32_t)__bfloat16_as_ushort(hx) | ((uint32_t)__bfloat16_as_ushort(hy) << 16);
    h.y = (uint32_t)__bfloat16_as_ushort(hz) | ((uint32_t)__bfloat16_as_ushort(hw) << 16);
    l.x = (uint32_t)__bfloat16_as_ushort(lx) | ((uint32_t)__bfloat16_as_ushort(ly) << 16);
    l.y = (uint32_t)__bfloat16_as_ushort(lz) | ((uint32_t)__bfloat16_as_ushort(lw) << 16);
}

#if USE_TC5
__device__ __forceinline__ uint32_t elect_one_pred() {
    uint32_t pred;
    asm volatile("{\n\t.reg .pred p;\n\telect.sync _|p, 0xFFFFFFFF;\n\t"
                 "selp.b32 %0, 1, 0, p;\n\t}" : "=r"(pred));
    return pred;
}

static constexpr uint64_t SMEM_DESC_BASE_SW128 =
    (uint64_t(2) << 61) | (uint64_t(1) << 46) | (uint64_t(64) << 32) | (uint64_t(1) << 16);
#define MAKE_SMEM_DESC(base_addr) \
    (SMEM_DESC_BASE_SW128 | ((uint64_t)((base_addr) >> 4) & 0x3FFF))

#define TCGEN05_ALLOC(smem_result_addr, nCols) \
    asm volatile("tcgen05.alloc.cta_group::1.sync.aligned.shared::cta.b32 [%0], %1;" \
        :: "r"((uint32_t)(smem_result_addr)), "r"((uint32_t)(nCols)) : "memory")
#define TCGEN05_DEALLOC(tmem_addr, nCols) \
    asm volatile("tcgen05.dealloc.cta_group::1.sync.aligned.b32 %0, %1;" \
        :: "r"(tmem_addr), "r"((uint32_t)(nCols)))
#define TCGEN05_RELINQUISH() \
    asm volatile("tcgen05.relinquish_alloc_permit.cta_group::1.sync.aligned;")
#define TCGEN05_COMMIT(mbar) \
    asm volatile("tcgen05.commit.cta_group::1.mbarrier::arrive::one.shared::cluster.b64 [%0];" \
        :: "r"((uint32_t)(mbar)) : "memory")
#define TCGEN05_FENCE_AFTER() \
    asm volatile("tcgen05.fence::after_thread_sync;" ::: "memory")
#define TCGEN05_FENCE_BEFORE() \
    asm volatile("tcgen05.fence::before_thread_sync;" ::: "memory")
#define TCGEN05_WAIT_LD() \
    asm volatile("tcgen05.wait::ld.sync.aligned;" ::: "memory")
#define MBARRIER_INIT(mbar, cnt) \
    asm volatile("mbarrier.init.shared.b64 [%0], %1;" \
        :: "r"((uint32_t)(mbar)), "r"((uint32_t)(cnt)) : "memory")
#define MBARRIER_INVAL(mbar) \
    asm volatile("mbarrier.inval.shared.b64 [%0];" :: "r"((uint32_t)(mbar)) : "memory")

#define MBARRIER_WAIT_PARITY(mbar_smem_addr, phase_parity) do { \
    uint32_t _mbar = (uint32_t)(mbar_smem_addr); \
    uint32_t _parity = (uint32_t)(phase_parity); \
    uint32_t _done; \
    asm volatile("{\n\t.reg .pred p;\n\t" \
        "mbarrier.try_wait.parity.acquire.cta.shared::cta.b64 p, [%1], %2;\n\t" \
        "selp.b32 %0, 1, 0, p;\n\t}" : "=r"(_done) : "r"(_mbar), "r"(_parity) : "memory"); \
    if (!_done) { \
        asm volatile("{\n\t.reg .pred P1;\n\t" \
            "WAIT_LOOP_%=:\n\t" \
            "mbarrier.try_wait.parity.acquire.cta.shared::cta.b64 P1, [%0], %1, 0x989680;\n\t" \
            "@P1 bra.uni WAIT_DONE_%=;\n\t" \
            "bra.uni WAIT_LOOP_%=;\n\t" \
            "WAIT_DONE_%=:\n\t}" :: "r"(_mbar), "r"(_parity) : "memory"); \
    } \
} while(0)

#define TCGEN05_LD_X32(r, tmem_addr) \
    asm volatile("tcgen05.ld.sync.aligned.32x32b.x32.b32 " \
        "{%0, %1, %2, %3, %4, %5, %6, %7, %8, %9, %10, %11, %12, %13, %14, %15, " \
        "%16, %17, %18, %19, %20, %21, %22, %23, %24, %25, %26, %27, %28, %29, %30, %31}, [%32];" \
        : "=r"((r)[0]),  "=r"((r)[1]),  "=r"((r)[2]),  "=r"((r)[3]), \
          "=r"((r)[4]),  "=r"((r)[5]),  "=r"((r)[6]),  "=r"((r)[7]), \
          "=r"((r)[8]),  "=r"((r)[9]),  "=r"((r)[10]), "=r"((r)[11]), \
          "=r"((r)[12]), "=r"((r)[13]), "=r"((r)[14]), "=r"((r)[15]), \
          "=r"((r)[16]), "=r"((r)[17]), "=r"((r)[18]), "=r"((r)[19]), \
          "=r"((r)[20]), "=r"((r)[21]), "=r"((r)[22]), "=r"((r)[23]), \
          "=r"((r)[24]), "=r"((r)[25]), "=r"((r)[26]), "=r"((r)[27]), \
          "=r"((r)[28]), "=r"((r)[29]), "=r"((r)[30]), "=r"((r)[31]) \
        : "r"(tmem_addr))

__device__ __forceinline__ void mma_f16_ss(uint32_t d, uint64_t ad, uint64_t bd,
                                           uint32_t idesc, uint32_t en) {
    asm volatile("{\n\t.reg .pred p;\n\tsetp.ne.u32 p, %4, 0;\n\t"
        "tcgen05.mma.cta_group::1.kind::f16 [%0], %1, %2, %3, {%5, %5, %5, %5}, p;\n\t}"
        :: "r"(d), "l"(ad), "l"(bd), "r"(idesc), "r"(en), "r"(0u) : "memory");
}
#endif

// ------------------------------- GEMM -----------------------------------------
// C[M=8192, N] (+)= sum_taps sum_k A'[m,k]*B_tap[n,k] + bias[n]
// A' rows shifted by (tap-1) within each batch (zero pad) when taps==3.
// hi/lo split bf16: acc += Ah*Bh + Ah*Bl + Al*Bh (fp32 accumulate in TMEM).
// Stage c = 16 K-elements in 32B column-quarter (slot c&3) of the 128B-row tiles.
__device__ __forceinline__ void load_stage(
    int c, int kpt, int taps, int K,
    const __nv_bfloat16* __restrict__ Ahi, const __nv_bfloat16* __restrict__ Alo,
    const __nv_bfloat16* __restrict__ Bhi, const __nv_bfloat16* __restrict__ Blo,
    size_t tapStrideB, int bm, int bn, uint32_t tb)
{
    int tap = 0, kc = c;
    if (taps == 3) { tap = c / kpt; kc = c - tap * kpt; }
    const int shift = (taps == 3) ? (tap - 1) : 0;
    const int kbase = kc << 4;                 // 16 K per stage
    const uint32_t colb = (uint32_t)(c & 3) * 32;
    const int tid = threadIdx.x;

    // A: 256 rows x 2 16B-units (this quarter)
#pragma unroll
    for (int it = 0; it < 2; ++it) {
        const int u = tid + it * 256;
        const int r = u >> 1, c2 = u & 1;
        const int m = bm + r;
        const int t = m & (SS - 1);
        const bool ok = ((unsigned)(t + shift)) < (unsigned)SS;
        const int srcsz = ok ? 16 : 0;
        const size_t goff = (size_t)(ok ? (m + shift) : m) * K + kbase + c2 * 8;
        const uint32_t so = SW128((uint32_t)(r * 128 + colb + c2 * 16));
        cpasync16(tb + SM_A_HI + so, Ahi + goff, srcsz);
        cpasync16(tb + SM_A_LO + so, Alo + goff, srcsz);
    }
    // B: 256 rows x 2 units
    const __nv_bfloat16* Bh = Bhi + (size_t)tap * tapStrideB;
    const __nv_bfloat16* Bl = Blo + (size_t)tap * tapStrideB;
#pragma unroll
    for (int it = 0; it < 2; ++it) {
        const int u = tid + it * 256;
        const int r = u >> 1, c2 = u & 1;
        const size_t goff = (size_t)(bn + r) * K + kbase + c2 * 8;
        const uint32_t so = SW128((uint32_t)(r * 128 + colb + c2 * 16));
        cpasync16(tb + SM_B_HI + so, Bh + goff, 16);
        cpasync16(tb + SM_B_LO + so, Bl + goff, 16);
    }
}

__global__ __launch_bounds__(256, 1)
void gemm_ts(const __nv_bfloat16* __restrict__ Ahi, const __nv_bfloat16* __restrict__ Alo,
             const __nv_bfloat16* __restrict__ Bhi, const __nv_bfloat16* __restrict__ Blo,
             const float* __restrict__ bias, float* __restrict__ C,
             int N, int K, int taps, size_t tapStrideB, int accum,
             __nv_bfloat16* __restrict__ XsHi, __nv_bfloat16* __restrict__ XsLo)
{
    extern __shared__ char dsm[];
    const uint32_t raw = smem_u32(dsm);
    const uint32_t sb0 = (raw + 1023) & ~1023u;     // header (tmem ptr, mbar)
    const uint32_t tb  = sb0 + 1024;                // tiles, 1KB aligned

    const int tid = threadIdx.x;
    const int wid = tid >> 5;
    const int lane = tid & 31;
    const int bm = blockIdx.y * TM;
    const int bn = blockIdx.x * TN;
    const int kpt = K >> 4;                          // 16-K stages per tap
    const int nch = taps * kpt;

#if USE_TC5
    const uint32_t mb0 = sb0 + 8;
    if (wid == 0) { TCGEN05_ALLOC(sb0, 512); TCGEN05_RELINQUISH(); }
    if (tid == 0) { MBARRIER_INIT(mb0, 1); }
    __syncthreads();
    uint32_t tmem;
    asm volatile("ld.shared.b32 %0, [%1];" : "=r"(tmem) : "r"(sb0));

    // per-MMA: M=128, N=256, K=16, bf16 in, fp32 out
    const uint32_t idesc = (1u << 4) | (1u << 7) | (1u << 10)
                         | ((TN / 8) << 17) | ((128 / 16) << 24);

    const uint64_t dAh0 = MAKE_SMEM_DESC(tb + SM_A_HI);
    const uint64_t dAh1 = MAKE_SMEM_DESC(tb + SM_A_HI + 16384);
    const uint64_t dAl0 = MAKE_SMEM_DESC(tb + SM_A_LO);
    const uint64_t dAl1 = MAKE_SMEM_DESC(tb + SM_A_LO + 16384);
    const uint64_t dBh  = MAKE_SMEM_DESC(tb + SM_B_HI);
    const uint64_t dBl  = MAKE_SMEM_DESC(tb + SM_B_LO);

    // prologue: fill 3 of the 4 slots
    load_stage(0, kpt, taps, K, Ahi, Alo, Bhi, Blo, tapStrideB, bm, bn, tb);
    asm volatile("cp.async.commit_group;" ::: "memory");
    load_stage(1, kpt, taps, K, Ahi, Alo, Bhi, Blo, tapStrideB, bm, bn, tb);
    asm volatile("cp.async.commit_group;" ::: "memory");
    load_stage(2, kpt, taps, K, Ahi, Alo, Bhi, Blo, tapStrideB, bm, bn, tb);
    asm volatile("cp.async.commit_group;" ::: "memory");

    int ph = 0;
    for (int c = 0; c < nch; ++c) {
        if (c + 1 >= nch)      asm volatile("cp.async.wait_group 0;" ::: "memory");
        else if (c + 2 >= nch) asm volatile("cp.async.wait_group 1;" ::: "memory");
        else                   asm volatile("cp.async.wait_group 2;" ::: "memory");
        __syncthreads();

        if (wid == 0) {
            if (elect_one_pred()) {
                asm volatile("fence.proxy.async.shared::cta;" ::: "memory");
                const uint32_t cofs = (uint32_t)(c & 3) * 2;   // 32B col offset, 16B units
                const uint32_t en0 = (c == 0) ? 0u : 1u;
                mma_f16_ss(tmem,       dAh0 + cofs, dBh + cofs, idesc, en0);
                mma_f16_ss(tmem,       dAh0 + cofs, dBl + cofs, idesc, 1u);
                mma_f16_ss(tmem,       dAl0 + cofs, dBh + cofs, idesc, 1u);
                mma_f16_ss(tmem + 256, dAh1 + cofs, dBh + cofs, idesc, en0);
                mma_f16_ss(tmem + 256, dAh1 + cofs, dBl + cofs, idesc, 1u);
                mma_f16_ss(tmem + 256, dAl1 + cofs, dBh + cofs, idesc, 1u);
                TCGEN05_COMMIT(mb0);
            }
        }
        // wait for MMA(c-1) completion -> slot (c+3)&3 is free for refill
        if (c >= 1) { MBARRIER_WAIT_PARITY(mb0, ph); ph ^= 1; }
        if (c + 3 < nch) {
            load_stage(c + 3, kpt, taps, K, Ahi, Alo, Bhi, Blo,
                       tapStrideB, bm, bn, tb);
            asm volatile("cp.async.commit_group;" ::: "memory");
        }
    }
    // final: wait for MMA(nch-1)
    MBARRIER_WAIT_PARITY(mb0, ph);
    TCGEN05_FENCE_AFTER();

    // epilogue: 8 warps; warps 0-3 -> M-half 0 (tmem cols 0-255), 4-7 -> half 1
    {
        const int h = wid >> 2;
        const int row = bm + h * 128 + (wid & 3) * 32 + lane;
        float* crow = C + (size_t)row * N + bn;
        const uint32_t tbase = tmem + (uint32_t)h * 256;
#pragma unroll 1
        for (int g = 0; g < 8; ++g) {
            uint32_t r[32];
            TCGEN05_LD_X32(r, tbase + g * 32);
            TCGEN05_WAIT_LD();
            const int cb = g * 32;
#pragma unroll
            for (int j = 0; j < 8; ++j) {
                float4 o;
                o.x = __uint_as_float(r[j * 4 + 0]);
                o.y = __uint_as_float(r[j * 4 + 1]);
                o.z = __uint_as_float(r[j * 4 + 2]);
                o.w = __uint_as_float(r[j * 4 + 3]);
                if (bias) {
                    float4 bi = *(const float4*)(bias + bn + cb + j * 4);
                    o.x += bi.x; o.y += bi.y; o.z += bi.z; o.w += bi.w;
                }
                if (accum) {
                    float4 p = *(const float4*)(crow + cb + j * 4);
                    o.x += p.x; o.y += p.y; o.z += p.z; o.w += p.w;
                }
                *(float4*)(crow + cb + j * 4) = o;
                if (XsHi) {
                    uint2 hh, ll;
                    split4(o, hh, ll);
                    const size_t xo = (size_t)row * N + bn + cb + j * 4;
                    *(uint2*)(XsHi + xo) = hh;
                    *(uint2*)(XsLo + xo) = ll;
                }
            }
        }
        TCGEN05_FENCE_BEFORE();
    }
    __syncthreads();
    if (tid == 0) { MBARRIER_INVAL(mb0); }
    if (wid == 0) { TCGEN05_DEALLOC(tmem, 512); }
#else
    // Correct SIMT fallback for non-'a' compile targets (never runs on GB300).
    (void)tb; (void)wid; (void)lane;
    for (int idx = tid; idx < TM * TN; idx += 256) {
        const int mi = idx >> 8;          // 0..255 (row within tile)
        const int ni = idx & 255;
        const int row = bm + mi;
        const int col = bn + ni;
        float acc = bias ? bias[col] : 0.f;
        for (int tap = 0; tap < taps; ++tap) {
            const int shift = (taps == 3) ? (tap - 1) : 0;
            const int t = row & (SS - 1);
            if (((unsigned)(t + shift)) >= (unsigned)SS) continue;
            const __nv_bfloat16* ar = Ahi + (size_t)(row + shift) * K;
            const __nv_bfloat16* al = Alo + (size_t)(row + shift) * K;
            const __nv_bfloat16* br = Bhi + (size_t)tap * tapStrideB + (size_t)col * K;
            const __nv_bfloat16* bl = Blo + (size_t)tap * tapStrideB + (size_t)col * K;
            for (int k = 0; k < K; ++k) {
                float a = __bfloat162float(ar[k]), a2 = __bfloat162float(al[k]);
                float b = __bfloat162float(br[k]), b2 = __bfloat162float(bl[k]);
                acc += a * b + a * b2 + a2 * b;
            }
        }
        float* p = C + (size_t)row * N + col;
        float v = acc + (accum ? *p : 0.f);
        *p = v;
        if (XsHi) split_store(v, XsHi + (size_t)row * N + col, XsLo + (size_t)row * N + col);
    }
#endif
}

// ------------------------- conversions ----------------------------------------
__global__ void cvt_split(const float* __restrict__ in, __nv_bfloat16* __restrict__ hi,
                          __nv_bfloat16* __restrict__ lo, int n4)
{
    const int i = blockIdx.x * 256 + threadIdx.x;
    if (i < n4) {
        float4 v = ((const float4*)in)[i];
        uint2 h, l;
        split4(v, h, l);
        ((uint2*)hi)[i] = h;
        ((uint2*)lo)[i] = l;
    }
}

// convW [L][O=H][I=H][3] -> [L][tap][O][I] split; one thread per (l,o,i) triple
__global__ void cvt_convw(const float* __restrict__ w, __nv_bfloat16* __restrict__ hi,
                          __nv_bfloat16* __restrict__ lo)
{
    const size_t idx = (size_t)blockIdx.x * 256 + threadIdx.x;  // over L*H*H
    const size_t total = (size_t)LAYERS * HH * HH;
    if (idx < total) {
        const int i = (int)(idx & (HH - 1));
        size_t r = idx >> 11;
        const int o = (int)(r & (HH - 1));
        const int l = (int)(r >> 11);
        const float* p = w + idx * 3;
#pragma unroll
        for (int tap = 0; tap < 3; ++tap) {
            const size_t dst = (((size_t)l * 3 + tap) * HH + o) * HH + i;
            split_store(p[tap], hi + dst, lo + dst);
        }
    }
}

// ------------------------------ LayerNorm family ------------------------------
// Shared LN body computes mean/rstd for one row of HH.
#define LN_PROLOG() \
    __shared__ float red[8]; \
    __shared__ float s_mean, s_rstd; \
    const int row = blockIdx.x; \
    const float4* ip = (const float4*)(in + (size_t)row * HH); \
    float4 v0 = ip[threadIdx.x]; \
    float4 v1 = ip[threadIdx.x + 256]; \
    float s = v0.x+v0.y+v0.z+v0.w + v1.x+v1.y+v1.z+v1.w; \
    _Pragma("unroll") \
    for (int o = 16; o; o >>= 1) s += __shfl_xor_sync(0xffffffffu, s, o); \
    const int wid = threadIdx.x >> 5, lane = threadIdx.x & 31; \
    if (lane == 0) red[wid] = s; \
    __syncthreads(); \
    if (threadIdx.x == 0) { \
        float tt = 0.f; \
        _Pragma("unroll") \
        for (int i = 0; i < 8; i++) tt += red[i]; \
        s_mean = tt * (1.0f / HH); \
    } \
    __syncthreads(); \
    const float mean = s_mean; \
    float d, ss = 0.f; \
    d=v0.x-mean; ss+=d*d; d=v0.y-mean; ss+=d*d; d=v0.z-mean; ss+=d*d; d=v0.w-mean; ss+=d*d; \
    d=v1.x-mean; ss+=d*d; d=v1.y-mean; ss+=d*d; d=v1.z-mean; ss+=d*d; d=v1.w-mean; ss+=d*d; \
    _Pragma("unroll") \
    for (int o = 16; o; o >>= 1) ss += __shfl_xor_sync(0xffffffffu, ss, o); \
    if (lane == 0) red[wid] = ss; \
    __syncthreads(); \
    if (threadIdx.x == 0) { \
        float tt = 0.f; \
        _Pragma("unroll") \
        for (int i = 0; i < 8; i++) tt += red[i]; \
        s_rstd = rsqrtf(tt * (1.0f / HH) + EPSLN); \
    } \
    __syncthreads(); \
    const float rstd = s_rstd; \
    float4 g0 = ((const float4*)g)[threadIdx.x]; \
    float4 g1 = ((const float4*)g)[threadIdx.x + 256]; \
    float4 b0 = ((const float4*)b)[threadIdx.x]; \
    float4 b1 = ((const float4*)b)[threadIdx.x + 256]; \
    float4 o0, o1; \
    o0.x=(v0.x-mean)*rstd*g0.x+b0.x; o0.y=(v0.y-mean)*rstd*g0.y+b0.y; \
    o0.z=(v0.z-mean)*rstd*g0.z+b0.z; o0.w=(v0.w-mean)*rstd*g0.w+b0.w; \
    o1.x=(v1.x-mean)*rstd*g1.x+b1.x; o1.y=(v1.y-mean)*rstd*g1.y+b1.y; \
    o1.z=(v1.z-mean)*rstd*g1.z+b1.z; o1.w=(v1.w-mean)*rstd*g1.w+b1.w;

__device__ __forceinline__ float4 silu4(float4 v) {
    v.x = v.x / (1.f + expf(-v.x)); v.y = v.y / (1.f + expf(-v.y));
    v.z = v.z / (1.f + expf(-v.z)); v.w = v.w / (1.f + expf(-v.w));
    return v;
}

// LN -> fp32 out (optionally SiLU)  [used for LN3 / s2]
template<int DO_SILU>
__global__ void ln_kernel(const float* __restrict__ in, float* __restrict__ out,
                          const float* __restrict__ g, const float* __restrict__ b)
{
    LN_PROLOG();
    if (DO_SILU) { o0 = silu4(o0); o1 = silu4(o1); }
    float4* op = (float4*)(out + (size_t)row * HH);
    op[threadIdx.x]       = o0;
    op[threadIdx.x + 256] = o1;
}

// LN -> split bf16 out (optionally SiLU)  [LN0, LN1]
template<int DO_SILU>
__global__ void ln_split(const float* __restrict__ in,
                         __nv_bfloat16* __restrict__ oh, __nv_bfloat16* __restrict__ ol,
                         const float* __restrict__ g, const float* __restrict__ b)
{
    LN_PROLOG();
    if (DO_SILU) { o0 = silu4(o0); o1 = silu4(o1); }
    uint2 h0, l0, h1, l1;
    split4(o0, h0, l0);
    split4(o1, h1, l1);
    uint2* hp = (uint2*)(oh + (size_t)row * HH);
    uint2* lp = (uint2*)(ol + (size_t)row * HH);
    hp[threadIdx.x] = h0; hp[threadIdx.x + 256] = h1;
    lp[threadIdx.x] = l0; lp[threadIdx.x + 256] = l1;
}

// LN(in) * mul -> split bf16 out  [LN2 fused with s1*s2]
__global__ void ln_mul_split(const float* __restrict__ in, const float* __restrict__ mul,
                             __nv_bfloat16* __restrict__ oh, __nv_bfloat16* __restrict__ ol,
                             const float* __restrict__ g, const float* __restrict__ b)
{
    LN_PROLOG();
    const float4* mp = (const float4*)(mul + (size_t)row * HH);
    float4 m0 = mp[threadIdx.x];
    float4 m1 = mp[threadIdx.x + 256];
    o0.x *= m0.x; o0.y *= m0.y; o0.z *= m0.z; o0.w *= m0.w;
    o1.x *= m1.x; o1.y *= m1.y; o1.z *= m1.z; o1.w *= m1.w;
    uint2 h0, l0, h1, l1;
    split4(o0, h0, l0);
    split4(o1, h1, l1);
    uint2* hp = (uint2*)(oh + (size_t)row * HH);
    uint2* lp = (uint2*)(ol + (size_t)row * HH);
    hp[threadIdx.x] = h0; hp[threadIdx.x + 256] = h1;
    lp[threadIdx.x] = l0; lp[threadIdx.x + 256] = l1;
}

// ------------------------------- minGRU scan ----------------------------------
__device__ __forceinline__ float softplusf(float x) {
    return fmaxf(x, 0.0f) + log1pf(expf(-fabsf(x)));
}
__device__ __forceinline__ float loggf(float x) {
    return (x >= 0.0f) ? logf(x + 0.5f) : -softplusf(-x);
}
__device__ __forceinline__ float laddexp(float a, float b) {
    float m = fmaxf(a, b);
    float d = fminf(a, b) - m;
    return m + log1pf(expf(d));
}

__global__ void scan_a(const float* __restrict__ Kx, const float* __restrict__ Px,
                       float* __restrict__ rend, float* __restrict__ asum)
{
    const int tid = blockIdx.x * 256 + threadIdx.x;
    const int h = tid & (HH - 1);
    const int rest = tid >> 11;
    const int j = rest & (CHUNKS - 1);
    const int b = rest >> CLOG;
    const size_t base = ((size_t)b * SS + (size_t)j * CLEN) * HH + h;
    float A = 0.f, r = -__int_as_float(0x7f800000);
    for (int tt = 0; tt < CLEN; tt++) {
        const float kv = Kx[base + (size_t)tt * HH];
        const float pv = Px[base + (size_t)tt * HH];
        const float lc = -softplusf(kv);
        const float lv = -softplusf(-kv) + loggf(pv);
        A += lc;
        r = laddexp(r + lc, lv);
    }
    rend[tid] = r;
    asum[tid] = A;
}

__global__ void scan_b(const float* __restrict__ rend, const float* __restrict__ asum,
                       float* __restrict__ lhin)
{
    const int tid = blockIdx.x * 256 + threadIdx.x;
    const int h = tid & (HH - 1);
    const int b = tid >> 11;
    float carry = -0.69314718056f;
#pragma unroll
    for (int j = 0; j < CHUNKS; j++) {
        const int idx = ((b * CHUNKS + j) << 11) + h;
        lhin[idx] = carry;
        carry = laddexp(asum[idx] + carry, rend[idx]);
    }
}

__global__ void scan_c(const float* __restrict__ Kx, const float* __restrict__ Px,
                       const float* __restrict__ lhin, float* __restrict__ out)
{
    const int tid = blockIdx.x * 256 + threadIdx.x;
    const int h = tid & (HH - 1);
    const int rest = tid >> 11;
    const int j = rest & (CHUNKS - 1);
    const int b = rest >> CLOG;
    const size_t base = ((size_t)b * SS + (size_t)j * CLEN) * HH + h;
    const float lhi = lhin[tid];
    float A = 0.f, r = -__int_as_float(0x7f800000);
    for (int tt = 0; tt < CLEN; tt++) {
        const float kv = Kx[base + (size_t)tt * HH];
        const float pv = Px[base + (size_t)tt * HH];
        const float lc = -softplusf(kv);
        const float lv = -softplusf(-kv) + loggf(pv);
        A += lc;
        r = laddexp(r + lc, lv);
        out[base + (size_t)tt * HH] = expf(laddexp(r, A + lhi));
    }
}

// --------------------------------- driver -------------------------------------
extern "C" void kernel_launch(void* const* d_in, const int* in_sizes, int n_in,
                              void* d_out, int out_size)
{
    const float* x    = (const float*)d_in[0];
    const float* Wp1  = (const float*)d_in[1];
    const float* bp1  = (const float*)d_in[2];
    const float* Wp2  = (const float*)d_in[3];
    const float* bp2  = (const float*)d_in[4];
    const float* convW= (const float*)d_in[5];
    const float* convb= (const float*)d_in[6];
    const float* Wz   = (const float*)d_in[7];
    const float* bz   = (const float*)d_in[8];
    const float* Wh   = (const float*)d_in[9];
    const float* bh   = (const float*)d_in[10];
    const float* Wd   = (const float*)d_in[11];
    const float* bd   = (const float*)d_in[12];
    const float* lng  = (const float*)d_in[13];
    const float* lnb  = (const float*)d_in[14];
    float* xb = (float*)d_out;

    float *b0,*b2,*b3,*b4,*rend,*asum,*lhin;
    __nv_bfloat16 *cvth,*cvtl,*cvtxh,*cvtxl;
    __nv_bfloat16 *wp1h,*wp1l,*wp2h,*wp2l,*wzh,*wzl,*whh,*whl,*wdh,*wdl,*wch,*wcl;
    cudaGetSymbolAddress((void**)&b0,  g_b0);
    cudaGetSymbolAddress((void**)&b2,  g_b2);
    cudaGetSymbolAddress((void**)&b3,  g_b3);
    cudaGetSymbolAddress((void**)&b4,  g_b4);
    cudaGetSymbolAddress((void**)&rend,g_rend);
    cudaGetSymbolAddress((void**)&asum,g_asum);
    cudaGetSymbolAddress((void**)&lhin,g_lhin);
    cudaGetSymbolAddress((void**)&cvth,g_cvth);
    cudaGetSymbolAddress((void**)&cvtl,g_cvtl);
    cudaGetSymbolAddress((void**)&cvtxh,g_cvtxh);
    cudaGetSymbolAddress((void**)&cvtxl,g_cvtxl);
    cudaGetSymbolAddress((void**)&wp1h,g_wp1h);
    cudaGetSymbolAddress((void**)&wp1l,g_wp1l);
    cudaGetSymbolAddress((void**)&wp2h,g_wp2h);
    cudaGetSymbolAddress((void**)&wp2l,g_wp2l);
    cudaGetSymbolAddress((void**)&wzh, g_wzh);
    cudaGetSymbolAddress((void**)&wzl, g_wzl);
    cudaGetSymbolAddress((void**)&whh, g_whh);
    cudaGetSymbolAddress((void**)&whl, g_whl);
    cudaGetSymbolAddress((void**)&wdh, g_wdh);
    cudaGetSymbolAddress((void**)&wdl, g_wdl);
    cudaGetSymbolAddress((void**)&wch, g_wch);
    cudaGetSymbolAddress((void**)&wcl, g_wcl);

    cudaFuncSetAttribute(gemm_ts, cudaFuncAttributeMaxDynamicSharedMemorySize, SMEM_DYN);

    cudaMemcpyAsync(xb, x, (size_t)MTOK * DD * sizeof(float),
                    cudaMemcpyDeviceToDevice, 0);

    // weight conversions (every launch; deterministic)
    {
        const int npd = LAYERS*HH*DD/4;
        const int nhh = LAYERS*HH*HH/4;
        cvt_split<<<(npd+255)/256, 256>>>(Wp1, wp1h, wp1l, npd);
        cvt_split<<<(npd+255)/256, 256>>>(Wp2, wp2h, wp2l, npd);
        cvt_split<<<(nhh+255)/256, 256>>>(Wz,  wzh,  wzl,  nhh);
        cvt_split<<<(nhh+255)/256, 256>>>(Wh,  whh,  whl,  nhh);
        cvt_split<<<(npd+255)/256, 256>>>(Wd,  wdh,  wdl,  npd);
        const size_t ct = (size_t)LAYERS*HH*HH;
        cvt_convw<<<(unsigned)((ct+255)/256), 256>>>(convW, wch, wcl);
    }

    // initial x split
    cvt_split<<<(MTOK*DD/4+255)/256, 256>>>(xb, cvtxh, cvtxl, MTOK*DD/4);

    const dim3 gH(HH/TN, MTOK/TM);   // (8, 32)
    const dim3 gD(DD/TN, MTOK/TM);   // (4, 32)

    for (int i = 0; i < LAYERS; i++) {
        // strand 2: proj2 + LN3(SiLU) -> b4 fp32
        gemm_ts<<<gH, 256, SMEM_DYN>>>(cvtxh, cvtxl,
                                       wp2h + (size_t)i*HH*DD, wp2l + (size_t)i*HH*DD,
                                       bp2 + i*HH, b4, HH, DD, 1, 0, 0, 0, 0);
        ln_kernel<1><<<MTOK, 256>>>(b4, b4, lng + (size_t)(i*4+3)*HH, lnb + (size_t)(i*4+3)*HH);

        // strand 1: proj1 -> b0; LN0 -> split
        gemm_ts<<<gH, 256, SMEM_DYN>>>(cvtxh, cvtxl,
                                       wp1h + (size_t)i*HH*DD, wp1l + (size_t)i*HH*DD,
                                       bp1 + i*HH, b0, HH, DD, 1, 0, 0, 0, 0);
        ln_split<0><<<MTOK, 256>>>(b0, cvth, cvtl,
                                   lng + (size_t)(i*4+0)*HH, lnb + (size_t)(i*4+0)*HH);

        // conv1d: 3 shifted taps accumulated in TMEM; LN1+SiLU -> split
        gemm_ts<<<gH, 256, SMEM_DYN>>>(cvth, cvtl,
                                       wch + (size_t)i*3*HH*HH, wcl + (size_t)i*3*HH*HH,
                                       convb + i*HH, b0, HH, HH, 3, (size_t)HH*HH, 0, 0, 0);
        ln_split<1><<<MTOK, 256>>>(b0, cvth, cvtl,
                                   lng + (size_t)(i*4+1)*HH, lnb + (size_t)(i*4+1)*HH);

        // minGRU projections + scan
        gemm_ts<<<gH, 256, SMEM_DYN>>>(cvth, cvtl,
                                       wzh + (size_t)i*HH*HH, wzl + (size_t)i*HH*HH,
                                       bz + i*HH, b2, HH, HH, 1, 0, 0, 0, 0);
        gemm_ts<<<gH, 256, SMEM_DYN>>>(cvth, cvtl,
                                       whh + (size_t)i*HH*HH, whl + (size_t)i*HH*HH,
                                       bh + i*HH, b3, HH, HH, 1, 0, 0, 0, 0);
        scan_a<<<(BB*CHUNKS*HH)/256, 256>>>(b2, b3, rend, asum);
        scan_b<<<(BB*HH)/256, 256>>>(rend, asum, lhin);
        scan_c<<<(BB*CHUNKS*HH)/256, 256>>>(b2, b3, lhin, b0);

        // LN2 fused with s1*s2 gating -> split
        ln_mul_split<<<MTOK, 256>>>(b0, b4, cvth, cvtl,
                                    lng + (size_t)(i*4+2)*HH, lnb + (size_t)(i*4+2)*HH);

        // down projection + bias + residual; epilogue also emits next layer's x split
        gemm_ts<<<gD, 256, SMEM_DYN>>>(cvth, cvtl,
                                       wdh + (size_t)i*DD*HH, wdl + (size_t)i*DD*HH,
                                       bd + i*DD, xb, DD, HH, 1, 0, 1, cvtxh, cvtxl);
    }
}

// round 10
// speedup vs baseline: 12.4253x; 1.0106x over previous
#include <cuda_runtime.h>
#include <cuda_bf16.h>
#include <math.h>
#include <stdint.h>

#define LAYERS 4
#define BB 4
#define SS 2048
#define DD 1024
#define HH 2048
#define MTOK (BB*SS)      /* 8192 tokens */
#define EPSLN 1e-5f

#define CHUNKS 16
#define CLOG 4
#define CLEN (SS/CHUNKS)  /* 128 */

// arch-feature gate: tcgen05 only exists on the sm_103a/sm_100a ("a") targets.
#if defined(__CUDA_ARCH_FEAT_SM103_ALL) || defined(__CUDA_ARCH_FEAT_SM100_ALL)
#define USE_TC5 1
#else
#define USE_TC5 0
#endif

// ---- GEMM tiling ----
// CTA tile: 256(M) x 256(N). Two M=128 MMA accumulators in TMEM (cols 0-255, 256-511).
// K pipelined in FOUR 16-element stages = 32B column-quarters of the 128B-row SW128
// tiles (slot = stage & 3). Loads run 3 stages ahead of the tensor pipe.
#define TM 256
#define TN 256
#define SM_A_HI 0          /* 256 rows x 128B */
#define SM_A_LO 32768
#define SM_B_HI 65536
#define SM_B_LO 98304
#define TILE_BYTES 131072
#define SMEM_DYN (1024 + 1024 + TILE_BYTES)

// ------------------------- scratch -------------------------------------------
__device__ __align__(256) float g_b0[(size_t)MTOK*HH];
__device__ __align__(256) float g_b2[(size_t)MTOK*HH];
__device__ __align__(256) float g_b3[(size_t)MTOK*HH];
__device__ __align__(256) float g_b4[(size_t)MTOK*HH];
__device__ __align__(256) __nv_bfloat16 g_cvth[(size_t)MTOK*HH];   // activation split
__device__ __align__(256) __nv_bfloat16 g_cvtl[(size_t)MTOK*HH];
__device__ __align__(256) __nv_bfloat16 g_cvtxh[(size_t)MTOK*DD];  // x split
__device__ __align__(256) __nv_bfloat16 g_cvtxl[(size_t)MTOK*DD];
__device__ __align__(256) __nv_bfloat16 g_wp1h[(size_t)LAYERS*HH*DD];
__device__ __align__(256) __nv_bfloat16 g_wp1l[(size_t)LAYERS*HH*DD];
__device__ __align__(256) __nv_bfloat16 g_wp2h[(size_t)LAYERS*HH*DD];
__device__ __align__(256) __nv_bfloat16 g_wp2l[(size_t)LAYERS*HH*DD];
__device__ __align__(256) __nv_bfloat16 g_wzh[(size_t)LAYERS*HH*HH];
__device__ __align__(256) __nv_bfloat16 g_wzl[(size_t)LAYERS*HH*HH];
__device__ __align__(256) __nv_bfloat16 g_whh[(size_t)LAYERS*HH*HH];
__device__ __align__(256) __nv_bfloat16 g_whl[(size_t)LAYERS*HH*HH];
__device__ __align__(256) __nv_bfloat16 g_wdh[(size_t)LAYERS*DD*HH];
__device__ __align__(256) __nv_bfloat16 g_wdl[(size_t)LAYERS*DD*HH];
__device__ __align__(256) __nv_bfloat16 g_wch[(size_t)LAYERS*3*HH*HH];
__device__ __align__(256) __nv_bfloat16 g_wcl[(size_t)LAYERS*3*HH*HH];
__device__ float g_rend[BB*CHUNKS*HH];
__device__ float g_asum[BB*CHUNKS*HH];
__device__ float g_lhin[BB*CHUNKS*HH];

// ------------------------- helpers --------------------------------------------
__device__ __forceinline__ uint32_t smem_u32(const void* p) {
    uint32_t a;
    asm("{ .reg .u64 t; cvta.to.shared.u64 t, %1; cvt.u32.u64 %0, t; }" : "=r"(a) : "l"(p));
    return a;
}
#define SW128(b) ((b) ^ (((b) >> 3) & 0x70))

__device__ __forceinline__ void cpasync16(uint32_t dst, const void* src, int srcsize) {
    asm volatile("cp.async.cg.shared.global [%0], [%1], 16, %2;\n"
                 :: "r"(dst), "l"(src), "r"(srcsize));
}

__device__ __forceinline__ void split_store(float v, __nv_bfloat16* hi, __nv_bfloat16* lo) {
    __nv_bfloat16 h = __float2bfloat16(v);
    *hi = h;
    *lo = __float2bfloat16(v - __bfloat162float(h));
}
__device__ __forceinline__ void split4(float4 v, uint2& h, uint2& l) {
    __nv_bfloat16 hx = __float2bfloat16(v.x), hy = __float2bfloat16(v.y);
    __nv_bfloat16 hz = __float2bfloat16(v.z), hw = __float2bfloat16(v.w);
    __nv_bfloat16 lx = __float2bfloat16(v.x - __bfloat162float(hx));
    __nv_bfloat16 ly = __float2bfloat16(v.y - __bfloat162float(hy));
    __nv_bfloat16 lz = __float2bfloat16(v.z - __bfloat162float(hz));
    __nv_bfloat16 lw = __float2bfloat16(v.w - __bfloat162float(hw));
    h.x = (uint32_t)__bfloat16_as_ushort(hx) | ((uint32_t)__bfloat16_as_ushort(hy) << 16);
    h.y = (uint32_t)__bfloat16_as_ushort(hz) | ((uint32_t)__bfloat16_as_ushort(hw) << 16);
    l.x = (uint32_t)__bfloat16_as_ushort(lx) | ((uint32_t)__bfloat16_as_ushort(ly) << 16);
    l.y = (uint32_t)__bfloat16_as_ushort(lz) | ((uint32_t)__bfloat16_as_ushort(lw) << 16);
}

#if USE_TC5
__device__ __forceinline__ uint32_t elect_one_pred() {
    uint32_t pred;
    asm volatile("{\n\t.reg .pred p;\n\telect.sync _|p, 0xFFFFFFFF;\n\t"
                 "selp.b32 %0, 1, 0, p;\n\t}" : "=r"(pred));
    return pred;
}

static constexpr uint64_t SMEM_DESC_BASE_SW128 =
    (uint64_t(2) << 61) | (uint64_t(1) << 46) | (uint64_t(64) << 32) | (uint64_t(1) << 16);
#define MAKE_SMEM_DESC(base_addr) \
    (SMEM_DESC_BASE_SW128 | ((uint64_t)((base_addr) >> 4) & 0x3FFF))

#define TCGEN05_ALLOC(smem_result_addr, nCols) \
    asm volatile("tcgen05.alloc.cta_group::1.sync.aligned.shared::cta.b32 [%0], %1;" \
        :: "r"((uint32_t)(smem_result_addr)), "r"((uint32_t)(nCols)) : "memory")
#define TCGEN05_DEALLOC(tmem_addr, nCols) \
    asm volatile("tcgen05.dealloc.cta_group::1.sync.aligned.b32 %0, %1;" \
        :: "r"(tmem_addr), "r"((uint32_t)(nCols)))
#define TCGEN05_RELINQUISH() \
    asm volatile("tcgen05.relinquish_alloc_permit.cta_group::1.sync.aligned;")
#define TCGEN05_COMMIT(mbar) \
    asm volatile("tcgen05.commit.cta_group::1.mbarrier::arrive::one.shared::cluster.b64 [%0];" \
        :: "r"((uint32_t)(mbar)) : "memory")
#define TCGEN05_FENCE_AFTER() \
    asm volatile("tcgen05.fence::after_thread_sync;" ::: "memory")
#define TCGEN05_FENCE_BEFORE() \
    asm volatile("tcgen05.fence::before_thread_sync;" ::: "memory")
#define TCGEN05_WAIT_LD() \
    asm volatile("tcgen05.wait::ld.sync.aligned;" ::: "memory")
#define MBARRIER_INIT(mbar, cnt) \
    asm volatile("mbarrier.init.shared.b64 [%0], %1;" \
        :: "r"((uint32_t)(mbar)), "r"((uint32_t)(cnt)) : "memory")
#define MBARRIER_INVAL(mbar) \
    asm volatile("mbarrier.inval.shared.b64 [%0];" :: "r"((uint32_t)(mbar)) : "memory")

#define MBARRIER_WAIT_PARITY(mbar_smem_addr, phase_parity) do { \
    uint32_t _mbar = (uint32_t)(mbar_smem_addr); \
    uint32_t _parity = (uint32_t)(phase_parity); \
    uint32_t _done; \
    asm volatile("{\n\t.reg .pred p;\n\t" \
        "mbarrier.try_wait.parity.acquire.cta.shared::cta.b64 p, [%1], %2;\n\t" \
        "selp.b32 %0, 1, 0, p;\n\t}" : "=r"(_done) : "r"(_mbar), "r"(_parity) : "memory"); \
    if (!_done) { \
        asm volatile("{\n\t.reg .pred P1;\n\t" \
            "WAIT_LOOP_%=:\n\t" \
            "mbarrier.try_wait.parity.acquire.cta.shared::cta.b64 P1, [%0], %1, 0x989680;\n\t" \
            "@P1 bra.uni WAIT_DONE_%=;\n\t" \
            "bra.uni WAIT_LOOP_%=;\n\t" \
            "WAIT_DONE_%=:\n\t}" :: "r"(_mbar), "r"(_parity) : "memory"); \
    } \
} while(0)

#define TCGEN05_LD_X32(r, tmem_addr) \
    asm volatile("tcgen05.ld.sync.aligned.32x32b.x32.b32 " \
        "{%0, %1, %2, %3, %4, %5, %6, %7, %8, %9, %10, %11, %12, %13, %14, %15, " \
        "%16, %17, %18, %19, %20, %21, %22, %23, %24, %25, %26, %27, %28, %29, %30, %31}, [%32];" \
        : "=r"((r)[0]),  "=r"((r)[1]),  "=r"((r)[2]),  "=r"((r)[3]), \
          "=r"((r)[4]),  "=r"((r)[5]),  "=r"((r)[6]),  "=r"((r)[7]), \
          "=r"((r)[8]),  "=r"((r)[9]),  "=r"((r)[10]), "=r"((r)[11]), \
          "=r"((r)[12]), "=r"((r)[13]), "=r"((r)[14]), "=r"((r)[15]), \
          "=r"((r)[16]), "=r"((r)[17]), "=r"((r)[18]), "=r"((r)[19]), \
          "=r"((r)[20]), "=r"((r)[21]), "=r"((r)[22]), "=r"((r)[23]), \
          "=r"((r)[24]), "=r"((r)[25]), "=r"((r)[26]), "=r"((r)[27]), \
          "=r"((r)[28]), "=r"((r)[29]), "=r"((r)[30]), "=r"((r)[31]) \
        : "r"(tmem_addr))

__device__ __forceinline__ void mma_f16_ss(uint32_t d, uint64_t ad, uint64_t bd,
                                           uint32_t idesc, uint32_t en) {
    asm volatile("{\n\t.reg .pred p;\n\tsetp.ne.u32 p, %4, 0;\n\t"
        "tcgen05.mma.cta_group::1.kind::f16 [%0], %1, %2, %3, {%5, %5, %5, %5}, p;\n\t}"
        :: "r"(d), "l"(ad), "l"(bd), "r"(idesc), "r"(en), "r"(0u) : "memory");
}
#endif

// ------------------------------- GEMM -----------------------------------------
// C[M=8192, N] (+)= sum_taps sum_k A'[m,k]*B_tap[n,k] + bias[n]
// A' rows shifted by (tap-1) within each batch (zero pad) when taps==3.
// hi/lo split bf16: acc += Ah*Bh + Ah*Bl + Al*Bh (fp32 accumulate in TMEM).
// Stage c = 16 K-elements in 32B column-quarter (slot c&3) of the 128B-row tiles.
__device__ __forceinline__ void load_stage(
    int c, int kpt, int taps, int K,
    const __nv_bfloat16* __restrict__ Ahi, const __nv_bfloat16* __restrict__ Alo,
    const __nv_bfloat16* __restrict__ Bhi, const __nv_bfloat16* __restrict__ Blo,
    size_t tapStrideB, int bm, int bn, uint32_t tb)
{
    int tap = 0, kc = c;
    if (taps == 3) { tap = c / kpt; kc = c - tap * kpt; }
    const int shift = (taps == 3) ? (tap - 1) : 0;
    const int kbase = kc << 4;                 // 16 K per stage
    const uint32_t colb = (uint32_t)(c & 3) * 32;
    const int tid = threadIdx.x;

    // A: 256 rows x 2 16B-units (this quarter)
#pragma unroll
    for (int it = 0; it < 2; ++it) {
        const int u = tid + it * 256;
        const int r = u >> 1, c2 = u & 1;
        const int m = bm + r;
        const int t = m & (SS - 1);
        const bool ok = ((unsigned)(t + shift)) < (unsigned)SS;
        const int srcsz = ok ? 16 : 0;
        const size_t goff = (size_t)(ok ? (m + shift) : m) * K + kbase + c2 * 8;
        const uint32_t so = SW128((uint32_t)(r * 128 + colb + c2 * 16));
        cpasync16(tb + SM_A_HI + so, Ahi + goff, srcsz);
        cpasync16(tb + SM_A_LO + so, Alo + goff, srcsz);
    }
    // B: 256 rows x 2 units
    const __nv_bfloat16* Bh = Bhi + (size_t)tap * tapStrideB;
    const __nv_bfloat16* Bl = Blo + (size_t)tap * tapStrideB;
#pragma unroll
    for (int it = 0; it < 2; ++it) {
        const int u = tid + it * 256;
        const int r = u >> 1, c2 = u & 1;
        const size_t goff = (size_t)(bn + r) * K + kbase + c2 * 8;
        const uint32_t so = SW128((uint32_t)(r * 128 + colb + c2 * 16));
        cpasync16(tb + SM_B_HI + so, Bh + goff, 16);
        cpasync16(tb + SM_B_LO + so, Bl + goff, 16);
    }
}

__global__ __launch_bounds__(256, 1)
void gemm_ts(const __nv_bfloat16* __restrict__ Ahi, const __nv_bfloat16* __restrict__ Alo,
             const __nv_bfloat16* __restrict__ Bhi, const __nv_bfloat16* __restrict__ Blo,
             const float* __restrict__ bias, float* __restrict__ C,
             int N, int K, int taps, size_t tapStrideB, int accum,
             __nv_bfloat16* __restrict__ XsHi, __nv_bfloat16* __restrict__ XsLo)
{
    extern __shared__ char dsm[];
    const uint32_t raw = smem_u32(dsm);
    const uint32_t sb0 = (raw + 1023) & ~1023u;     // header (tmem ptr, mbar)
    const uint32_t tb  = sb0 + 1024;                // tiles, 1KB aligned

    const int tid = threadIdx.x;
    const int wid = tid >> 5;
    const int lane = tid & 31;
    const int bm = blockIdx.y * TM;
    const int bn = blockIdx.x * TN;
    const int kpt = K >> 4;                          // 16-K stages per tap
    const int nch = taps * kpt;

#if USE_TC5
    const uint32_t mb0 = sb0 + 8;
    if (wid == 0) { TCGEN05_ALLOC(sb0, 512); TCGEN05_RELINQUISH(); }
    if (tid == 0) { MBARRIER_INIT(mb0, 1); }
    __syncthreads();
    uint32_t tmem;
    asm volatile("ld.shared.b32 %0, [%1];" : "=r"(tmem) : "r"(sb0));

    // per-MMA: M=128, N=256, K=16, bf16 in, fp32 out
    const uint32_t idesc = (1u << 4) | (1u << 7) | (1u << 10)
                         | ((TN / 8) << 17) | ((128 / 16) << 24);

    const uint64_t dAh0 = MAKE_SMEM_DESC(tb + SM_A_HI);
    const uint64_t dAh1 = MAKE_SMEM_DESC(tb + SM_A_HI + 16384);
    const uint64_t dAl0 = MAKE_SMEM_DESC(tb + SM_A_LO);
    const uint64_t dAl1 = MAKE_SMEM_DESC(tb + SM_A_LO + 16384);
    const uint64_t dBh  = MAKE_SMEM_DESC(tb + SM_B_HI);
    const uint64_t dBl  = MAKE_SMEM_DESC(tb + SM_B_LO);

    // prologue: fill 3 of the 4 slots
    load_stage(0, kpt, taps, K, Ahi, Alo, Bhi, Blo, tapStrideB, bm, bn, tb);
    asm volatile("cp.async.commit_group;" ::: "memory");
    load_stage(1, kpt, taps, K, Ahi, Alo, Bhi, Blo, tapStrideB, bm, bn, tb);
    asm volatile("cp.async.commit_group;" ::: "memory");
    load_stage(2, kpt, taps, K, Ahi, Alo, Bhi, Blo, tapStrideB, bm, bn, tb);
    asm volatile("cp.async.commit_group;" ::: "memory");

    int ph = 0;
    for (int c = 0; c < nch; ++c) {
        if (c + 1 >= nch)      asm volatile("cp.async.wait_group 0;" ::: "memory");
        else if (c + 2 >= nch) asm volatile("cp.async.wait_group 1;" ::: "memory");
        else                   asm volatile("cp.async.wait_group 2;" ::: "memory");
        __syncthreads();

        if (wid == 0) {
            if (elect_one_pred()) {
                asm volatile("fence.proxy.async.shared::cta;" ::: "memory");
                const uint32_t cofs = (uint32_t)(c & 3) * 2;   // 32B col offset, 16B units
                const uint32_t en0 = (c == 0) ? 0u : 1u;
                mma_f16_ss(tmem,       dAh0 + cofs, dBh + cofs, idesc, en0);
                mma_f16_ss(tmem,       dAh0 + cofs, dBl + cofs, idesc, 1u);
                mma_f16_ss(tmem,       dAl0 + cofs, dBh + cofs, idesc, 1u);
                mma_f16_ss(tmem + 256, dAh1 + cofs, dBh + cofs, idesc, en0);
                mma_f16_ss(tmem + 256, dAh1 + cofs, dBl + cofs, idesc, 1u);
                mma_f16_ss(tmem + 256, dAl1 + cofs, dBh + cofs, idesc, 1u);
                TCGEN05_COMMIT(mb0);
            }
        }
        // wait for MMA(c-1) completion -> slot (c+3)&3 is free for refill
        if (c >= 1) { MBARRIER_WAIT_PARITY(mb0, ph); ph ^= 1; }
        if (c + 3 < nch) {
            load_stage(c + 3, kpt, taps, K, Ahi, Alo, Bhi, Blo,
                       tapStrideB, bm, bn, tb);
            asm volatile("cp.async.commit_group;" ::: "memory");
        }
    }
    // final: wait for MMA(nch-1)
    MBARRIER_WAIT_PARITY(mb0, ph);
    TCGEN05_FENCE_AFTER();

    // epilogue: 8 warps; warps 0-3 -> M-half 0 (tmem cols 0-255), 4-7 -> half 1
    {
        const int h = wid >> 2;
        const int row = bm + h * 128 + (wid & 3) * 32 + lane;
        float* crow = C + (size_t)row * N + bn;
        const uint32_t tbase = tmem + (uint32_t)h * 256;
#pragma unroll 1
        for (int g = 0; g < 8; ++g) {
            uint32_t r[32];
            TCGEN05_LD_X32(r, tbase + g * 32);
            TCGEN05_WAIT_LD();
            const int cb = g * 32;
#pragma unroll
            for (int j = 0; j < 8; ++j) {
                float4 o;
                o.x = __uint_as_float(r[j * 4 + 0]);
                o.y = __uint_as_float(r[j * 4 + 1]);
                o.z = __uint_as_float(r[j * 4 + 2]);
                o.w = __uint_as_float(r[j * 4 + 3]);
                if (bias) {
                    float4 bi = *(const float4*)(bias + bn + cb + j * 4);
                    o.x += bi.x; o.y += bi.y; o.z += bi.z; o.w += bi.w;
                }
                if (accum) {
                    float4 p = *(const float4*)(crow + cb + j * 4);
                    o.x += p.x; o.y += p.y; o.z += p.z; o.w += p.w;
                }
                *(float4*)(crow + cb + j * 4) = o;
                if (XsHi) {
                    uint2 hh, ll;
                    split4(o, hh, ll);
                    const size_t xo = (size_t)row * N + bn + cb + j * 4;
                    *(uint2*)(XsHi + xo) = hh;
                    *(uint2*)(XsLo + xo) = ll;
                }
            }
        }
        TCGEN05_FENCE_BEFORE();
    }
    __syncthreads();
    if (tid == 0) { MBARRIER_INVAL(mb0); }
    if (wid == 0) { TCGEN05_DEALLOC(tmem, 512); }
#else
    // Correct SIMT fallback for non-'a' compile targets (never runs on GB300).
    (void)tb; (void)wid; (void)lane;
    for (int idx = tid; idx < TM * TN; idx += 256) {
        const int mi = idx >> 8;          // 0..255 (row within tile)
        const int ni = idx & 255;
        const int row = bm + mi;
        const int col = bn + ni;
        float acc = bias ? bias[col] : 0.f;
        for (int tap = 0; tap < taps; ++tap) {
            const int shift = (taps == 3) ? (tap - 1) : 0;
            const int t = row & (SS - 1);
            if (((unsigned)(t + shift)) >= (unsigned)SS) continue;
            const __nv_bfloat16* ar = Ahi + (size_t)(row + shift) * K;
            const __nv_bfloat16* al = Alo + (size_t)(row + shift) * K;
            const __nv_bfloat16* br = Bhi + (size_t)tap * tapStrideB + (size_t)col * K;
            const __nv_bfloat16* bl = Blo + (size_t)tap * tapStrideB + (size_t)col * K;
            for (int k = 0; k < K; ++k) {
                float a = __bfloat162float(ar[k]), a2 = __bfloat162float(al[k]);
                float b = __bfloat162float(br[k]), b2 = __bfloat162float(bl[k]);
                acc += a * b + a * b2 + a2 * b;
            }
        }
        float* p = C + (size_t)row * N + col;
        float v = acc + (accum ? *p : 0.f);
        *p = v;
        if (XsHi) split_store(v, XsHi + (size_t)row * N + col, XsLo + (size_t)row * N + col);
    }
#endif
}

// ------------------------- conversions ----------------------------------------
__global__ void cvt_split(const float* __restrict__ in, __nv_bfloat16* __restrict__ hi,
                          __nv_bfloat16* __restrict__ lo, int n4)
{
    const int i = blockIdx.x * 256 + threadIdx.x;
    if (i < n4) {
        float4 v = ((const float4*)in)[i];
        uint2 h, l;
        split4(v, h, l);
        ((uint2*)hi)[i] = h;
        ((uint2*)lo)[i] = l;
    }
}

// convW [L][O=H][I=H][3] -> [L][tap][O][I] split; one thread per (l,o,i) triple
__global__ void cvt_convw(const float* __restrict__ w, __nv_bfloat16* __restrict__ hi,
                          __nv_bfloat16* __restrict__ lo)
{
    const size_t idx = (size_t)blockIdx.x * 256 + threadIdx.x;  // over L*H*H
    const size_t total = (size_t)LAYERS * HH * HH;
    if (idx < total) {
        const int i = (int)(idx & (HH - 1));
        size_t r = idx >> 11;
        const int o = (int)(r & (HH - 1));
        const int l = (int)(r >> 11);
        const float* p = w + idx * 3;
#pragma unroll
        for (int tap = 0; tap < 3; ++tap) {
            const size_t dst = (((size_t)l * 3 + tap) * HH + o) * HH + i;
            split_store(p[tap], hi + dst, lo + dst);
        }
    }
}

// ------------------------------ LayerNorm family ------------------------------
#define LN_PROLOG() \
    __shared__ float red[8]; \
    __shared__ float s_mean, s_rstd; \
    const int row = blockIdx.x; \
    const float4* ip = (const float4*)(in + (size_t)row * HH); \
    float4 v0 = ip[threadIdx.x]; \
    float4 v1 = ip[threadIdx.x + 256]; \
    float s = v0.x+v0.y+v0.z+v0.w + v1.x+v1.y+v1.z+v1.w; \
    _Pragma("unroll") \
    for (int o = 16; o; o >>= 1) s += __shfl_xor_sync(0xffffffffu, s, o); \
    const int wid = threadIdx.x >> 5, lane = threadIdx.x & 31; \
    if (lane == 0) red[wid] = s; \
    __syncthreads(); \
    if (threadIdx.x == 0) { \
        float tt = 0.f; \
        _Pragma("unroll") \
        for (int i = 0; i < 8; i++) tt += red[i]; \
        s_mean = tt * (1.0f / HH); \
    } \
    __syncthreads(); \
    const float mean = s_mean; \
    float d, ss = 0.f; \
    d=v0.x-mean; ss+=d*d; d=v0.y-mean; ss+=d*d; d=v0.z-mean; ss+=d*d; d=v0.w-mean; ss+=d*d; \
    d=v1.x-mean; ss+=d*d; d=v1.y-mean; ss+=d*d; d=v1.z-mean; ss+=d*d; d=v1.w-mean; ss+=d*d; \
    _Pragma("unroll") \
    for (int o = 16; o; o >>= 1) ss += __shfl_xor_sync(0xffffffffu, ss, o); \
    if (lane == 0) red[wid] = ss; \
    __syncthreads(); \
    if (threadIdx.x == 0) { \
        float tt = 0.f; \
        _Pragma("unroll") \
        for (int i = 0; i < 8; i++) tt += red[i]; \
        s_rstd = rsqrtf(tt * (1.0f / HH) + EPSLN); \
    } \
    __syncthreads(); \
    const float rstd = s_rstd; \
    float4 g0 = ((const float4*)g)[threadIdx.x]; \
    float4 g1 = ((const float4*)g)[threadIdx.x + 256]; \
    float4 b0 = ((const float4*)b)[threadIdx.x]; \
    float4 b1 = ((const float4*)b)[threadIdx.x + 256]; \
    float4 o0, o1; \
    o0.x=(v0.x-mean)*rstd*g0.x+b0.x; o0.y=(v0.y-mean)*rstd*g0.y+b0.y; \
    o0.z=(v0.z-mean)*rstd*g0.z+b0.z; o0.w=(v0.w-mean)*rstd*g0.w+b0.w; \
    o1.x=(v1.x-mean)*rstd*g1.x+b1.x; o1.y=(v1.y-mean)*rstd*g1.y+b1.y; \
    o1.z=(v1.z-mean)*rstd*g1.z+b1.z; o1.w=(v1.w-mean)*rstd*g1.w+b1.w;

__device__ __forceinline__ float4 silu4(float4 v) {
    v.x = v.x / (1.f + expf(-v.x)); v.y = v.y / (1.f + expf(-v.y));
    v.z = v.z / (1.f + expf(-v.z)); v.w = v.w / (1.f + expf(-v.w));
    return v;
}

template<int DO_SILU>
__global__ void ln_kernel(const float* __restrict__ in, float* __restrict__ out,
                          const float* __restrict__ g, const float* __restrict__ b)
{
    LN_PROLOG();
    if (DO_SILU) { o0 = silu4(o0); o1 = silu4(o1); }
    float4* op = (float4*)(out + (size_t)row * HH);
    op[threadIdx.x]       = o0;
    op[threadIdx.x + 256] = o1;
}

template<int DO_SILU>
__global__ void ln_split(const float* __restrict__ in,
                         __nv_bfloat16* __restrict__ oh, __nv_bfloat16* __restrict__ ol,
                         const float* __restrict__ g, const float* __restrict__ b)
{
    LN_PROLOG();
    if (DO_SILU) { o0 = silu4(o0); o1 = silu4(o1); }
    uint2 h0, l0, h1, l1;
    split4(o0, h0, l0);
    split4(o1, h1, l1);
    uint2* hp = (uint2*)(oh + (size_t)row * HH);
    uint2* lp = (uint2*)(ol + (size_t)row * HH);
    hp[threadIdx.x] = h0; hp[threadIdx.x + 256] = h1;
    lp[threadIdx.x] = l0; lp[threadIdx.x + 256] = l1;
}

__global__ void ln_mul_split(const float* __restrict__ in, const float* __restrict__ mul,
                             __nv_bfloat16* __restrict__ oh, __nv_bfloat16* __restrict__ ol,
                             const float* __restrict__ g, const float* __restrict__ b)
{
    LN_PROLOG();
    const float4* mp = (const float4*)(mul + (size_t)row * HH);
    float4 m0 = mp[threadIdx.x];
    float4 m1 = mp[threadIdx.x + 256];
    o0.x *= m0.x; o0.y *= m0.y; o0.z *= m0.z; o0.w *= m0.w;
    o1.x *= m1.x; o1.y *= m1.y; o1.z *= m1.z; o1.w *= m1.w;
    uint2 h0, l0, h1, l1;
    split4(o0, h0, l0);
    split4(o1, h1, l1);
    uint2* hp = (uint2*)(oh + (size_t)row * HH);
    uint2* lp = (uint2*)(ol + (size_t)row * HH);
    hp[threadIdx.x] = h0; hp[threadIdx.x + 256] = h1;
    lp[threadIdx.x] = l0; lp[threadIdx.x + 256] = l1;
}

// ------------------------------- minGRU scan ----------------------------------
__device__ __forceinline__ float softplusf(float x) {
    return fmaxf(x, 0.0f) + log1pf(expf(-fabsf(x)));
}
__device__ __forceinline__ float loggf(float x) {
    return (x >= 0.0f) ? logf(x + 0.5f) : -softplusf(-x);
}
__device__ __forceinline__ float laddexp(float a, float b) {
    float m = fmaxf(a, b);
    float d = fminf(a, b) - m;
    return m + log1pf(expf(d));
}

// one softplus per element: -softplus(-k) == k - softplus(k) (bitwise-equal here)
__global__ void scan_a(const float* __restrict__ Kx, const float* __restrict__ Px,
                       float* __restrict__ rend, float* __restrict__ asum)
{
    const int tid = blockIdx.x * 256 + threadIdx.x;
    const int h = tid & (HH - 1);
    const int rest = tid >> 11;
    const int j = rest & (CHUNKS - 1);
    const int b = rest >> CLOG;
    const size_t base = ((size_t)b * SS + (size_t)j * CLEN) * HH + h;
    float A = 0.f, r = -__int_as_float(0x7f800000);
    for (int tt = 0; tt < CLEN; tt++) {
        const float kv = Kx[base + (size_t)tt * HH];
        const float pv = Px[base + (size_t)tt * HH];
        const float sp = softplusf(kv);
        const float lc = -sp;
        const float lv = (kv - sp) + loggf(pv);
        A += lc;
        r = laddexp(r + lc, lv);
    }
    rend[tid] = r;
    asum[tid] = A;
}

__global__ void scan_b(const float* __restrict__ rend, const float* __restrict__ asum,
                       float* __restrict__ lhin)
{
    const int tid = blockIdx.x * 256 + threadIdx.x;
    const int h = tid & (HH - 1);
    const int b = tid >> 11;
    float carry = -0.69314718056f;
#pragma unroll
    for (int j = 0; j < CHUNKS; j++) {
        const int idx = ((b * CHUNKS + j) << 11) + h;
        lhin[idx] = carry;
        carry = laddexp(asum[idx] + carry, rend[idx]);
    }
}

__global__ void scan_c(const float* __restrict__ Kx, const float* __restrict__ Px,
                       const float* __restrict__ lhin, float* __restrict__ out)
{
    const int tid = blockIdx.x * 256 + threadIdx.x;
    const int h = tid & (HH - 1);
    const int rest = tid >> 11;
    const int j = rest & (CHUNKS - 1);
    const int b = rest >> CLOG;
    const size_t base = ((size_t)b * SS + (size_t)j * CLEN) * HH + h;
    const float lhi = lhin[tid];
    float A = 0.f, r = -__int_as_float(0x7f800000);
    for (int tt = 0; tt < CLEN; tt++) {
        const float kv = Kx[base + (size_t)tt * HH];
        const float pv = Px[base + (size_t)tt * HH];
        const float sp = softplusf(kv);
        const float lc = -sp;
        const float lv = (kv - sp) + loggf(pv);
        A += lc;
        r = laddexp(r + lc, lv);
        out[base + (size_t)tt * HH] = expf(laddexp(r, A + lhi));
    }
}

// --------------------------------- driver -------------------------------------
extern "C" void kernel_launch(void* const* d_in, const int* in_sizes, int n_in,
                              void* d_out, int out_size)
{
    const float* x    = (const float*)d_in[0];
    const float* Wp1  = (const float*)d_in[1];
    const float* bp1  = (const float*)d_in[2];
    const float* Wp2  = (const float*)d_in[3];
    const float* bp2  = (const float*)d_in[4];
    const float* convW= (const float*)d_in[5];
    const float* convb= (const float*)d_in[6];
    const float* Wz   = (const float*)d_in[7];
    const float* bz   = (const float*)d_in[8];
    const float* Wh   = (const float*)d_in[9];
    const float* bh   = (const float*)d_in[10];
    const float* Wd   = (const float*)d_in[11];
    const float* bd   = (const float*)d_in[12];
    const float* lng  = (const float*)d_in[13];
    const float* lnb  = (const float*)d_in[14];
    float* xb = (float*)d_out;

    float *b0,*b2,*b3,*b4,*rend,*asum,*lhin;
    __nv_bfloat16 *cvth,*cvtl,*cvtxh,*cvtxl;
    __nv_bfloat16 *wp1h,*wp1l,*wp2h,*wp2l,*wzh,*wzl,*whh,*whl,*wdh,*wdl,*wch,*wcl;
    cudaGetSymbolAddress((void**)&b0,  g_b0);
    cudaGetSymbolAddress((void**)&b2,  g_b2);
    cudaGetSymbolAddress((void**)&b3,  g_b3);
    cudaGetSymbolAddress((void**)&b4,  g_b4);
    cudaGetSymbolAddress((void**)&rend,g_rend);
    cudaGetSymbolAddress((void**)&asum,g_asum);
    cudaGetSymbolAddress((void**)&lhin,g_lhin);
    cudaGetSymbolAddress((void**)&cvth,g_cvth);
    cudaGetSymbolAddress((void**)&cvtl,g_cvtl);
    cudaGetSymbolAddress((void**)&cvtxh,g_cvtxh);
    cudaGetSymbolAddress((void**)&cvtxl,g_cvtxl);
    cudaGetSymbolAddress((void**)&wp1h,g_wp1h);
    cudaGetSymbolAddress((void**)&wp1l,g_wp1l);
    cudaGetSymbolAddress((void**)&wp2h,g_wp2h);
    cudaGetSymbolAddress((void**)&wp2l,g_wp2l);
    cudaGetSymbolAddress((void**)&wzh, g_wzh);
    cudaGetSymbolAddress((void**)&wzl, g_wzl);
    cudaGetSymbolAddress((void**)&whh, g_whh);
    cudaGetSymbolAddress((void**)&whl, g_whl);
    cudaGetSymbolAddress((void**)&wdh, g_wdh);
    cudaGetSymbolAddress((void**)&wdl, g_wdl);
    cudaGetSymbolAddress((void**)&wch, g_wch);
    cudaGetSymbolAddress((void**)&wcl, g_wcl);

    cudaFuncSetAttribute(gemm_ts, cudaFuncAttributeMaxDynamicSharedMemorySize, SMEM_DYN);

    cudaMemcpyAsync(xb, x, (size_t)MTOK * DD * sizeof(float),
                    cudaMemcpyDeviceToDevice, 0);

    const int npd = LAYERS*HH*DD/4;
    const int nhh = LAYERS*HH*HH/4;
    const dim3 gH(HH/TN, MTOK/TM);   // (8, 32)
    const dim3 gD(DD/TN, MTOK/TM);   // (4, 32)

    // ordered so ncu -s 5 -c 1 captures a gemm_ts (kernel launches:
    // 4x cvt_split, gemm(#5), gemm(#6 <- captured), ...)
    cvt_split<<<(MTOK*DD/4+255)/256, 256>>>(xb, cvtxh, cvtxl, MTOK*DD/4);
    cvt_split<<<(npd+255)/256, 256>>>(Wp2, wp2h, wp2l, npd);
    cvt_split<<<(npd+255)/256, 256>>>(Wp1, wp1h, wp1l, npd);
    cvt_split<<<(nhh+255)/256, 256>>>(Wz,  wzh,  wzl,  nhh);
    // layer-0 projections hoisted here
    gemm_ts<<<gH, 256, SMEM_DYN>>>(cvtxh, cvtxl, wp2h, wp2l, bp2, b4, HH, DD, 1, 0, 0, 0, 0);
    gemm_ts<<<gH, 256, SMEM_DYN>>>(cvtxh, cvtxl, wp1h, wp1l, bp1, b0, HH, DD, 1, 0, 0, 0, 0);
    // remaining weight conversions
    cvt_split<<<(nhh+255)/256, 256>>>(Wh,  whh,  whl,  nhh);
    cvt_split<<<(npd+255)/256, 256>>>(Wd,  wdh,  wdl,  npd);
    cvt_convw<<<(unsigned)(((size_t)LAYERS*HH*HH+255)/256), 256>>>(convW, wch, wcl);

    for (int i = 0; i < LAYERS; i++) {
        if (i) {
            gemm_ts<<<gH, 256, SMEM_DYN>>>(cvtxh, cvtxl,
                                           wp2h + (size_t)i*HH*DD, wp2l + (size_t)i*HH*DD,
                                           bp2 + i*HH, b4, HH, DD, 1, 0, 0, 0, 0);
        }
        ln_kernel<1><<<MTOK, 256>>>(b4, b4, lng + (size_t)(i*4+3)*HH, lnb + (size_t)(i*4+3)*HH);
        if (i) {
            gemm_ts<<<gH, 256, SMEM_DYN>>>(cvtxh, cvtxl,
                                           wp1h + (size_t)i*HH*DD, wp1l + (size_t)i*HH*DD,
                                           bp1 + i*HH, b0, HH, DD, 1, 0, 0, 0, 0);
        }
        ln_split<0><<<MTOK, 256>>>(b0, cvth, cvtl,
                                   lng + (size_t)(i*4+0)*HH, lnb + (size_t)(i*4+0)*HH);

        // conv1d: 3 shifted taps accumulated in TMEM; LN1+SiLU -> split
        gemm_ts<<<gH, 256, SMEM_DYN>>>(cvth, cvtl,
                                       wch + (size_t)i*3*HH*HH, wcl + (size_t)i*3*HH*HH,
                                       convb + i*HH, b0, HH, HH, 3, (size_t)HH*HH, 0, 0, 0);
        ln_split<1><<<MTOK, 256>>>(b0, cvth, cvtl,
                                   lng + (size_t)(i*4+1)*HH, lnb + (size_t)(i*4+1)*HH);

        // minGRU projections + scan
        gemm_ts<<<gH, 256, SMEM_DYN>>>(cvth, cvtl,
                                       wzh + (size_t)i*HH*HH, wzl + (size_t)i*HH*HH,
                                       bz + i*HH, b2, HH, HH, 1, 0, 0, 0, 0);
        gemm_ts<<<gH, 256, SMEM_DYN>>>(cvth, cvtl,
                                       whh + (size_t)i*HH*HH, whl + (size_t)i*HH*HH,
                                       bh + i*HH, b3, HH, HH, 1, 0, 0, 0, 0);
        scan_a<<<(BB*CHUNKS*HH)/256, 256>>>(b2, b3, rend, asum);
        scan_b<<<(BB*HH)/256, 256>>>(rend, asum, lhin);
        scan_c<<<(BB*CHUNKS*HH)/256, 256>>>(b2, b3, lhin, b0);

        // LN2 fused with s1*s2 gating -> split
        ln_mul_split<<<MTOK, 256>>>(b0, b4, cvth, cvtl,
                                    lng + (size_t)(i*4+2)*HH, lnb + (size_t)(i*4+2)*HH);

        // down projection + bias + residual; epilogue also emits next layer's x split
        gemm_ts<<<gD, 256, SMEM_DYN>>>(cvth, cvtl,
                                       wdh + (size_t)i*DD*HH, wdl + (size_t)i*DD*HH,
                                       bd + i*DD, xb, DD, HH, 1, 0, 1, cvtxh, cvtxl);
    }
}

// round 14
// speedup vs baseline: 12.5783x; 1.0123x over previous
#include <cuda_runtime.h>
#include <cuda_bf16.h>
#include <math.h>
#include <stdint.h>

#define LAYERS 4
#define BB 4
#define SS 2048
#define DD 1024
#define HH 2048
#define MTOK (BB*SS)      /* 8192 tokens */
#define EPSLN 1e-5f

#define CHUNKS 16
#define CLOG 4
#define CLEN (SS/CHUNKS)  /* 128 */

// arch-feature gate: tcgen05 only exists on the sm_103a/sm_100a ("a") targets.
#if defined(__CUDA_ARCH_FEAT_SM103_ALL) || defined(__CUDA_ARCH_FEAT_SM100_ALL)
#define USE_TC5 1
#else
#define USE_TC5 0
#endif

// ---- GEMM tiling ----
// CTA tile: 256(M) x 256(N). Two M=128 MMA accumulators in TMEM (cols 0-255, 256-511).
// K pipelined in FOUR 16-element stages = 32B column-quarters of the 128B-row SW128
// tiles (slot = stage & 3). Loads run 3 stages ahead of the tensor pipe.
#define TM 256
#define TN 256
#define SM_A_HI 0          /* 256 rows x 128B */
#define SM_A_LO 32768
#define SM_B_HI 65536
#define SM_B_LO 98304
#define TILE_BYTES 131072
#define SMEM_DYN (1024 + 1024 + TILE_BYTES)

// ------------------------- scratch -------------------------------------------
__device__ __align__(256) float g_b0[(size_t)MTOK*HH];
__device__ __align__(256) float g_b2[(size_t)MTOK*HH];
__device__ __align__(256) float g_b3[(size_t)MTOK*HH];
__device__ __align__(256) float g_b4[(size_t)MTOK*HH];
__device__ __align__(256) __nv_bfloat16 g_cvth[(size_t)MTOK*HH];   // activation split
__device__ __align__(256) __nv_bfloat16 g_cvtl[(size_t)MTOK*HH];
__device__ __align__(256) __nv_bfloat16 g_cvtxh[(size_t)MTOK*DD];  // x split
__device__ __align__(256) __nv_bfloat16 g_cvtxl[(size_t)MTOK*DD];
__device__ __align__(256) __nv_bfloat16 g_wp1h[(size_t)LAYERS*HH*DD];
__device__ __align__(256) __nv_bfloat16 g_wp1l[(size_t)LAYERS*HH*DD];
__device__ __align__(256) __nv_bfloat16 g_wp2h[(size_t)LAYERS*HH*DD];
__device__ __align__(256) __nv_bfloat16 g_wp2l[(size_t)LAYERS*HH*DD];
__device__ __align__(256) __nv_bfloat16 g_wzh[(size_t)LAYERS*HH*HH];
__device__ __align__(256) __nv_bfloat16 g_wzl[(size_t)LAYERS*HH*HH];
__device__ __align__(256) __nv_bfloat16 g_whh[(size_t)LAYERS*HH*HH];
__device__ __align__(256) __nv_bfloat16 g_whl[(size_t)LAYERS*HH*HH];
__device__ __align__(256) __nv_bfloat16 g_wdh[(size_t)LAYERS*DD*HH];
__device__ __align__(256) __nv_bfloat16 g_wdl[(size_t)LAYERS*DD*HH];
__device__ __align__(256) __nv_bfloat16 g_wch[(size_t)LAYERS*3*HH*HH];
__device__ __align__(256) __nv_bfloat16 g_wcl[(size_t)LAYERS*3*HH*HH];
__device__ float g_rend[BB*CHUNKS*HH];
__device__ float g_asum[BB*CHUNKS*HH];
__device__ float g_lhin[BB*CHUNKS*HH];

// ------------------------- helpers --------------------------------------------
__device__ __forceinline__ uint32_t smem_u32(const void* p) {
    uint32_t a;
    asm("{ .reg .u64 t; cvta.to.shared.u64 t, %1; cvt.u32.u64 %0, t; }" : "=r"(a) : "l"(p));
    return a;
}
#define SW128(b) ((b) ^ (((b) >> 3) & 0x70))

__device__ __forceinline__ void cpasync16(uint32_t dst, const void* src, int srcsize) {
    asm volatile("cp.async.cg.shared.global [%0], [%1], 16, %2;\n"
                 :: "r"(dst), "l"(src), "r"(srcsize));
}

__device__ __forceinline__ void split_store(float v, __nv_bfloat16* hi, __nv_bfloat16* lo) {
    __nv_bfloat16 h = __float2bfloat16(v);
    *hi = h;
    *lo = __float2bfloat16(v - __bfloat162float(h));
}
__device__ __forceinline__ void split4(float4 v, uint2& h, uint2& l) {
    __nv_bfloat16 hx = __float2bfloat16(v.x), hy = __float2bfloat16(v.y);
    __nv_bfloat16 hz = __float2bfloat16(v.z), hw = __float2bfloat16(v.w);
    __nv_bfloat16 lx = __float2bfloat16(v.x - __bfloat162float(hx));
    __nv_bfloat16 ly = __float2bfloat16(v.y - __bfloat162float(hy));
    __nv_bfloat16 lz = __float2bfloat16(v.z - __bfloat162float(hz));
    __nv_bfloat16 lw = __float2bfloat16(v.w - __bfloat162float(hw));
    h.x = (uint32_t)__bfloat16_as_ushort(hx) | ((uint32_t)__bfloat16_as_ushort(hy) << 16);
    h.y = (uint32_t)__bfloat16_as_ushort(hz) | ((uint32_t)__bfloat16_as_ushort(hw) << 16);
    l.x = (uint32_t)__bfloat16_as_ushort(lx) | ((uint32_t)__bfloat16_as_ushort(ly) << 16);
    l.y = (uint32_t)__bfloat16_as_ushort(lz) | ((uint32_t)__bfloat16_as_ushort(lw) << 16);
}

#if USE_TC5
__device__ __forceinline__ uint32_t elect_one_pred() {
    uint32_t pred;
    asm volatile("{\n\t.reg .pred p;\n\telect.sync _|p, 0xFFFFFFFF;\n\t"
                 "selp.b32 %0, 1, 0, p;\n\t}" : "=r"(pred));
    return pred;
}

static constexpr uint64_t SMEM_DESC_BASE_SW128 =
    (uint64_t(2) << 61) | (uint64_t(1) << 46) | (uint64_t(64) << 32) | (uint64_t(1) << 16);
#define MAKE_SMEM_DESC(base_addr) \
    (SMEM_DESC_BASE_SW128 | ((uint64_t)((base_addr) >> 4) & 0x3FFF))

#define TCGEN05_ALLOC(smem_result_addr, nCols) \
    asm volatile("tcgen05.alloc.cta_group::1.sync.aligned.shared::cta.b32 [%0], %1;" \
        :: "r"((uint32_t)(smem_result_addr)), "r"((uint32_t)(nCols)) : "memory")
#define TCGEN05_DEALLOC(tmem_addr, nCols) \
    asm volatile("tcgen05.dealloc.cta_group::1.sync.aligned.b32 %0, %1;" \
        :: "r"(tmem_addr), "r"((uint32_t)(nCols)))
#define TCGEN05_RELINQUISH() \
    asm volatile("tcgen05.relinquish_alloc_permit.cta_group::1.sync.aligned;")
#define TCGEN05_COMMIT(mbar) \
    asm volatile("tcgen05.commit.cta_group::1.mbarrier::arrive::one.shared::cluster.b64 [%0];" \
        :: "r"((uint32_t)(mbar)) : "memory")
#define TCGEN05_FENCE_AFTER() \
    asm volatile("tcgen05.fence::after_thread_sync;" ::: "memory")
#define TCGEN05_FENCE_BEFORE() \
    asm volatile("tcgen05.fence::before_thread_sync;" ::: "memory")
#define TCGEN05_WAIT_LD() \
    asm volatile("tcgen05.wait::ld.sync.aligned;" ::: "memory")
#define MBARRIER_INIT(mbar, cnt) \
    asm volatile("mbarrier.init.shared.b64 [%0], %1;" \
        :: "r"((uint32_t)(mbar)), "r"((uint32_t)(cnt)) : "memory")
#define MBARRIER_INVAL(mbar) \
    asm volatile("mbarrier.inval.shared.b64 [%0];" :: "r"((uint32_t)(mbar)) : "memory")

#define MBARRIER_WAIT_PARITY(mbar_smem_addr, phase_parity) do { \
    uint32_t _mbar = (uint32_t)(mbar_smem_addr); \
    uint32_t _parity = (uint32_t)(phase_parity); \
    uint32_t _done; \
    asm volatile("{\n\t.reg .pred p;\n\t" \
        "mbarrier.try_wait.parity.acquire.cta.shared::cta.b64 p, [%1], %2;\n\t" \
        "selp.b32 %0, 1, 0, p;\n\t}" : "=r"(_done) : "r"(_mbar), "r"(_parity) : "memory"); \
    if (!_done) { \
        asm volatile("{\n\t.reg .pred P1;\n\t" \
            "WAIT_LOOP_%=:\n\t" \
            "mbarrier.try_wait.parity.acquire.cta.shared::cta.b64 P1, [%0], %1, 0x989680;\n\t" \
            "@P1 bra.uni WAIT_DONE_%=;\n\t" \
            "bra.uni WAIT_LOOP_%=;\n\t" \
            "WAIT_DONE_%=:\n\t}" :: "r"(_mbar), "r"(_parity) : "memory"); \
    } \
} while(0)

#define TCGEN05_LD_X32(r, tmem_addr) \
    asm volatile("tcgen05.ld.sync.aligned.32x32b.x32.b32 " \
        "{%0, %1, %2, %3, %4, %5, %6, %7, %8, %9, %10, %11, %12, %13, %14, %15, " \
        "%16, %17, %18, %19, %20, %21, %22, %23, %24, %25, %26, %27, %28, %29, %30, %31}, [%32];" \
        : "=r"((r)[0]),  "=r"((r)[1]),  "=r"((r)[2]),  "=r"((r)[3]), \
          "=r"((r)[4]),  "=r"((r)[5]),  "=r"((r)[6]),  "=r"((r)[7]), \
          "=r"((r)[8]),  "=r"((r)[9]),  "=r"((r)[10]), "=r"((r)[11]), \
          "=r"((r)[12]), "=r"((r)[13]), "=r"((r)[14]), "=r"((r)[15]), \
          "=r"((r)[16]), "=r"((r)[17]), "=r"((r)[18]), "=r"((r)[19]), \
          "=r"((r)[20]), "=r"((r)[21]), "=r"((r)[22]), "=r"((r)[23]), \
          "=r"((r)[24]), "=r"((r)[25]), "=r"((r)[26]), "=r"((r)[27]), \
          "=r"((r)[28]), "=r"((r)[29]), "=r"((r)[30]), "=r"((r)[31]) \
        : "r"(tmem_addr))

__device__ __forceinline__ void mma_f16_ss(uint32_t d, uint64_t ad, uint64_t bd,
                                           uint32_t idesc, uint32_t en) {
    asm volatile("{\n\t.reg .pred p;\n\tsetp.ne.u32 p, %4, 0;\n\t"
        "tcgen05.mma.cta_group::1.kind::f16 [%0], %1, %2, %3, {%5, %5, %5, %5}, p;\n\t}"
        :: "r"(d), "l"(ad), "l"(bd), "r"(idesc), "r"(en), "r"(0u) : "memory");
}
#endif

// ------------------------------- GEMM -----------------------------------------
// C[M=8192, N] (+)= sum_taps sum_k A'[m,k]*B_tap[n,k] + bias[n]
// A' rows shifted by (tap-1) within each batch (zero pad) when taps==3.
// hi/lo split bf16: acc += Ah*Bh + Ah*Bl + Al*Bh (fp32 accumulate in TMEM).
// Stage c = 16 K-elements in 32B column-quarter (slot c&3) of the 128B-row tiles.
__device__ __forceinline__ void load_stage(
    int c, int kpt, int taps, int K,
    const __nv_bfloat16* __restrict__ Ahi, const __nv_bfloat16* __restrict__ Alo,
    const __nv_bfloat16* __restrict__ Bhi, const __nv_bfloat16* __restrict__ Blo,
    size_t tapStrideB, int bm, int bn, uint32_t tb)
{
    int tap = 0, kc = c;
    if (taps == 3) { tap = c / kpt; kc = c - tap * kpt; }
    const int shift = (taps == 3) ? (tap - 1) : 0;
    const int kbase = kc << 4;                 // 16 K per stage
    const uint32_t colb = (uint32_t)(c & 3) * 32;
    const int tid = threadIdx.x;

    // A: 256 rows x 2 16B-units (this quarter)
#pragma unroll
    for (int it = 0; it < 2; ++it) {
        const int u = tid + it * 256;
        const int r = u >> 1, c2 = u & 1;
        const int m = bm + r;
        const int t = m & (SS - 1);
        const bool ok = ((unsigned)(t + shift)) < (unsigned)SS;
        const int srcsz = ok ? 16 : 0;
        const size_t goff = (size_t)(ok ? (m + shift) : m) * K + kbase + c2 * 8;
        const uint32_t so = SW128((uint32_t)(r * 128 + colb + c2 * 16));
        cpasync16(tb + SM_A_HI + so, Ahi + goff, srcsz);
        cpasync16(tb + SM_A_LO + so, Alo + goff, srcsz);
    }
    // B: 256 rows x 2 units
    const __nv_bfloat16* Bh = Bhi + (size_t)tap * tapStrideB;
    const __nv_bfloat16* Bl = Blo + (size_t)tap * tapStrideB;
#pragma unroll
    for (int it = 0; it < 2; ++it) {
        const int u = tid + it * 256;
        const int r = u >> 1, c2 = u & 1;
        const size_t goff = (size_t)(bn + r) * K + kbase + c2 * 8;
        const uint32_t so = SW128((uint32_t)(r * 128 + colb + c2 * 16));
        cpasync16(tb + SM_B_HI + so, Bh + goff, 16);
        cpasync16(tb + SM_B_LO + so, Bl + goff, 16);
    }
}

__global__ __launch_bounds__(256, 1)
void gemm_ts(const __nv_bfloat16* __restrict__ Ahi, const __nv_bfloat16* __restrict__ Alo,
             const __nv_bfloat16* __restrict__ Bhi, const __nv_bfloat16* __restrict__ Blo,
             const float* __restrict__ bias, float* __restrict__ C,
             int N, int K, int taps, size_t tapStrideB, int accum,
             __nv_bfloat16* __restrict__ XsHi, __nv_bfloat16* __restrict__ XsLo)
{
    extern __shared__ char dsm[];
    const uint32_t raw = smem_u32(dsm);
    const uint32_t sb0 = (raw + 1023) & ~1023u;     // header (tmem ptr, mbar)
    const uint32_t tb  = sb0 + 1024;                // tiles, 1KB aligned

    const int tid = threadIdx.x;
    const int wid = tid >> 5;
    const int lane = tid & 31;
    const int bm = blockIdx.y * TM;
    const int bn = blockIdx.x * TN;
    const int kpt = K >> 4;                          // 16-K stages per tap
    const int nch = taps * kpt;

#if USE_TC5
    const uint32_t mb0 = sb0 + 8;
    if (wid == 0) { TCGEN05_ALLOC(sb0, 512); TCGEN05_RELINQUISH(); }
    if (tid == 0) { MBARRIER_INIT(mb0, 1); }
    __syncthreads();
    uint32_t tmem;
    asm volatile("ld.shared.b32 %0, [%1];" : "=r"(tmem) : "r"(sb0));

    // per-MMA: M=128, N=256, K=16, bf16 in, fp32 out
    const uint32_t idesc = (1u << 4) | (1u << 7) | (1u << 10)
                         | ((TN / 8) << 17) | ((128 / 16) << 24);

    const uint64_t dAh0 = MAKE_SMEM_DESC(tb + SM_A_HI);
    const uint64_t dAh1 = MAKE_SMEM_DESC(tb + SM_A_HI + 16384);
    const uint64_t dAl0 = MAKE_SMEM_DESC(tb + SM_A_LO);
    const uint64_t dAl1 = MAKE_SMEM_DESC(tb + SM_A_LO + 16384);
    const uint64_t dBh  = MAKE_SMEM_DESC(tb + SM_B_HI);
    const uint64_t dBl  = MAKE_SMEM_DESC(tb + SM_B_LO);

    // prologue: fill 3 of the 4 slots
    load_stage(0, kpt, taps, K, Ahi, Alo, Bhi, Blo, tapStrideB, bm, bn, tb);
    asm volatile("cp.async.commit_group;" ::: "memory");
    load_stage(1, kpt, taps, K, Ahi, Alo, Bhi, Blo, tapStrideB, bm, bn, tb);
    asm volatile("cp.async.commit_group;" ::: "memory");
    load_stage(2, kpt, taps, K, Ahi, Alo, Bhi, Blo, tapStrideB, bm, bn, tb);
    asm volatile("cp.async.commit_group;" ::: "memory");

    int ph = 0;
    for (int c = 0; c < nch; ++c) {
        if (c + 1 >= nch)      asm volatile("cp.async.wait_group 0;" ::: "memory");
        else if (c + 2 >= nch) asm volatile("cp.async.wait_group 1;" ::: "memory");
        else                   asm volatile("cp.async.wait_group 2;" ::: "memory");
        __syncthreads();

        if (wid == 0) {
            if (elect_one_pred()) {
                asm volatile("fence.proxy.async.shared::cta;" ::: "memory");
                const uint32_t cofs = (uint32_t)(c & 3) * 2;   // 32B col offset, 16B units
                const uint32_t en0 = (c == 0) ? 0u : 1u;
                mma_f16_ss(tmem,       dAh0 + cofs, dBh + cofs, idesc, en0);
                mma_f16_ss(tmem,       dAh0 + cofs, dBl + cofs, idesc, 1u);
                mma_f16_ss(tmem,       dAl0 + cofs, dBh + cofs, idesc, 1u);
                mma_f16_ss(tmem + 256, dAh1 + cofs, dBh + cofs, idesc, en0);
                mma_f16_ss(tmem + 256, dAh1 + cofs, dBl + cofs, idesc, 1u);
                mma_f16_ss(tmem + 256, dAl1 + cofs, dBh + cofs, idesc, 1u);
                TCGEN05_COMMIT(mb0);
            }
        }
        // wait for MMA(c-1) completion -> slot (c+3)&3 is free for refill
        if (c >= 1) { MBARRIER_WAIT_PARITY(mb0, ph); ph ^= 1; }
        if (c + 3 < nch) {
            load_stage(c + 3, kpt, taps, K, Ahi, Alo, Bhi, Blo,
                       tapStrideB, bm, bn, tb);
            asm volatile("cp.async.commit_group;" ::: "memory");
        }
    }
    // final: wait for MMA(nch-1)
    MBARRIER_WAIT_PARITY(mb0, ph);
    TCGEN05_FENCE_AFTER();

    // epilogue: 8 warps; warps 0-3 -> M-half 0 (tmem cols 0-255), 4-7 -> half 1
    {
        const int h = wid >> 2;
        const int row = bm + h * 128 + (wid & 3) * 32 + lane;
        float* crow = C + (size_t)row * N + bn;
        const uint32_t tbase = tmem + (uint32_t)h * 256;
#pragma unroll 1
        for (int g = 0; g < 8; ++g) {
            uint32_t r[32];
            TCGEN05_LD_X32(r, tbase + g * 32);
            TCGEN05_WAIT_LD();
            const int cb = g * 32;
#pragma unroll
            for (int j = 0; j < 8; ++j) {
                float4 o;
                o.x = __uint_as_float(r[j * 4 + 0]);
                o.y = __uint_as_float(r[j * 4 + 1]);
                o.z = __uint_as_float(r[j * 4 + 2]);
                o.w = __uint_as_float(r[j * 4 + 3]);
                if (bias) {
                    float4 bi = *(const float4*)(bias + bn + cb + j * 4);
                    o.x += bi.x; o.y += bi.y; o.z += bi.z; o.w += bi.w;
                }
                if (accum) {
                    float4 p = *(const float4*)(crow + cb + j * 4);
                    o.x += p.x; o.y += p.y; o.z += p.z; o.w += p.w;
                }
                *(float4*)(crow + cb + j * 4) = o;
                if (XsHi) {
                    uint2 hh, ll;
                    split4(o, hh, ll);
                    const size_t xo = (size_t)row * N + bn + cb + j * 4;
                    *(uint2*)(XsHi + xo) = hh;
                    *(uint2*)(XsLo + xo) = ll;
                }
            }
        }
        TCGEN05_FENCE_BEFORE();
    }
    __syncthreads();
    if (tid == 0) { MBARRIER_INVAL(mb0); }
    if (wid == 0) { TCGEN05_DEALLOC(tmem, 512); }
#else
    // Correct SIMT fallback for non-'a' compile targets (never runs on GB300).
    (void)tb; (void)wid; (void)lane;
    for (int idx = tid; idx < TM * TN; idx += 256) {
        const int mi = idx >> 8;          // 0..255 (row within tile)
        const int ni = idx & 255;
        const int row = bm + mi;
        const int col = bn + ni;
        float acc = bias ? bias[col] : 0.f;
        for (int tap = 0; tap < taps; ++tap) {
            const int shift = (taps == 3) ? (tap - 1) : 0;
            const int t = row & (SS - 1);
            if (((unsigned)(t + shift)) >= (unsigned)SS) continue;
            const __nv_bfloat16* ar = Ahi + (size_t)(row + shift) * K;
            const __nv_bfloat16* al = Alo + (size_t)(row + shift) * K;
            const __nv_bfloat16* br = Bhi + (size_t)tap * tapStrideB + (size_t)col * K;
            const __nv_bfloat16* bl = Blo + (size_t)tap * tapStrideB + (size_t)col * K;
            for (int k = 0; k < K; ++k) {
                float a = __bfloat162float(ar[k]), a2 = __bfloat162float(al[k]);
                float b = __bfloat162float(br[k]), b2 = __bfloat162float(bl[k]);
                acc += a * b + a * b2 + a2 * b;
            }
        }
        float* p = C + (size_t)row * N + col;
        float v = acc + (accum ? *p : 0.f);
        *p = v;
        if (XsHi) split_store(v, XsHi + (size_t)row * N + col, XsLo + (size_t)row * N + col);
    }
#endif
}

// ------------------------- conversions ----------------------------------------
__global__ void cvt_split(const float* __restrict__ in, __nv_bfloat16* __restrict__ hi,
                          __nv_bfloat16* __restrict__ lo, int n4)
{
    const int i = blockIdx.x * 256 + threadIdx.x;
    if (i < n4) {
        float4 v = ((const float4*)in)[i];
        uint2 h, l;
        split4(v, h, l);
        ((uint2*)hi)[i] = h;
        ((uint2*)lo)[i] = l;
    }
}

// convW [L][O=H][I=H][3] -> [L][tap][O][I] split; one thread per (l,o,i) triple
__global__ void cvt_convw(const float* __restrict__ w, __nv_bfloat16* __restrict__ hi,
                          __nv_bfloat16* __restrict__ lo)
{
    const size_t idx = (size_t)blockIdx.x * 256 + threadIdx.x;  // over L*H*H
    const size_t total = (size_t)LAYERS * HH * HH;
    if (idx < total) {
        const int i = (int)(idx & (HH - 1));
        size_t r = idx >> 11;
        const int o = (int)(r & (HH - 1));
        const int l = (int)(r >> 11);
        const float* p = w + idx * 3;
#pragma unroll
        for (int tap = 0; tap < 3; ++tap) {
            const size_t dst = (((size_t)l * 3 + tap) * HH + o) * HH + i;
            split_store(p[tap], hi + dst, lo + dst);
        }
    }
}

// ------------------------------ LayerNorm family ------------------------------
#define LN_PROLOG() \
    __shared__ float red[8]; \
    __shared__ float s_mean, s_rstd; \
    const int row = blockIdx.x; \
    const float4* ip = (const float4*)(in + (size_t)row * HH); \
    float4 v0 = ip[threadIdx.x]; \
    float4 v1 = ip[threadIdx.x + 256]; \
    float s = v0.x+v0.y+v0.z+v0.w + v1.x+v1.y+v1.z+v1.w; \
    _Pragma("unroll") \
    for (int o = 16; o; o >>= 1) s += __shfl_xor_sync(0xffffffffu, s, o); \
    const int wid = threadIdx.x >> 5, lane = threadIdx.x & 31; \
    if (lane == 0) red[wid] = s; \
    __syncthreads(); \
    if (threadIdx.x == 0) { \
        float tt = 0.f; \
        _Pragma("unroll") \
        for (int i = 0; i < 8; i++) tt += red[i]; \
        s_mean = tt * (1.0f / HH); \
    } \
    __syncthreads(); \
    const float mean = s_mean; \
    float d, ss = 0.f; \
    d=v0.x-mean; ss+=d*d; d=v0.y-mean; ss+=d*d; d=v0.z-mean; ss+=d*d; d=v0.w-mean; ss+=d*d; \
    d=v1.x-mean; ss+=d*d; d=v1.y-mean; ss+=d*d; d=v1.z-mean; ss+=d*d; d=v1.w-mean; ss+=d*d; \
    _Pragma("unroll") \
    for (int o = 16; o; o >>= 1) ss += __shfl_xor_sync(0xffffffffu, ss, o); \
    if (lane == 0) red[wid] = ss; \
    __syncthreads(); \
    if (threadIdx.x == 0) { \
        float tt = 0.f; \
        _Pragma("unroll") \
        for (int i = 0; i < 8; i++) tt += red[i]; \
        s_rstd = rsqrtf(tt * (1.0f / HH) + EPSLN); \
    } \
    __syncthreads(); \
    const float rstd = s_rstd; \
    float4 g0 = ((const float4*)g)[threadIdx.x]; \
    float4 g1 = ((const float4*)g)[threadIdx.x + 256]; \
    float4 b0 = ((const float4*)b)[threadIdx.x]; \
    float4 b1 = ((const float4*)b)[threadIdx.x + 256]; \
    float4 o0, o1; \
    o0.x=(v0.x-mean)*rstd*g0.x+b0.x; o0.y=(v0.y-mean)*rstd*g0.y+b0.y; \
    o0.z=(v0.z-mean)*rstd*g0.z+b0.z; o0.w=(v0.w-mean)*rstd*g0.w+b0.w; \
    o1.x=(v1.x-mean)*rstd*g1.x+b1.x; o1.y=(v1.y-mean)*rstd*g1.y+b1.y; \
    o1.z=(v1.z-mean)*rstd*g1.z+b1.z; o1.w=(v1.w-mean)*rstd*g1.w+b1.w;

__device__ __forceinline__ float4 silu4(float4 v) {
    v.x = v.x / (1.f + expf(-v.x)); v.y = v.y / (1.f + expf(-v.y));
    v.z = v.z / (1.f + expf(-v.z)); v.w = v.w / (1.f + expf(-v.w));
    return v;
}

// LN -> split bf16 out (optionally SiLU)  [LN0, LN1]
template<int DO_SILU>
__global__ void ln_split(const float* __restrict__ in,
                         __nv_bfloat16* __restrict__ oh, __nv_bfloat16* __restrict__ ol,
                         const float* __restrict__ g, const float* __restrict__ b)
{
    LN_PROLOG();
    if (DO_SILU) { o0 = silu4(o0); o1 = silu4(o1); }
    uint2 h0, l0, h1, l1;
    split4(o0, h0, l0);
    split4(o1, h1, l1);
    uint2* hp = (uint2*)(oh + (size_t)row * HH);
    uint2* lp = (uint2*)(ol + (size_t)row * HH);
    hp[threadIdx.x] = h0; hp[threadIdx.x + 256] = h1;
    lp[threadIdx.x] = l0; lp[threadIdx.x + 256] = l1;
}

// Double-LN gating: split( LN(in;g,b) * SiLU(LN(p2;g2,b2)) ).
// Fuses the old ln_kernel<1>(b4) pass into the gating kernel (saves a full
// fp32 read+write of b4 per layer; math order identical, fp32 stores exact).
__global__ void ln2_mul_split(const float* __restrict__ in, const float* __restrict__ p2,
                              __nv_bfloat16* __restrict__ oh, __nv_bfloat16* __restrict__ ol,
                              const float* __restrict__ g, const float* __restrict__ b,
                              const float* __restrict__ g2, const float* __restrict__ b2)
{
    __shared__ float redA[8], redB[8];
    __shared__ float s_m1, s_r1, s_m2, s_r2;
    const int row = blockIdx.x;
    const float4* ip = (const float4*)(in + (size_t)row * HH);
    const float4* pp = (const float4*)(p2 + (size_t)row * HH);
    float4 v0 = ip[threadIdx.x], v1 = ip[threadIdx.x + 256];
    float4 w0 = pp[threadIdx.x], w1 = pp[threadIdx.x + 256];

    float sa = v0.x+v0.y+v0.z+v0.w + v1.x+v1.y+v1.z+v1.w;
    float sb = w0.x+w0.y+w0.z+w0.w + w1.x+w1.y+w1.z+w1.w;
#pragma unroll
    for (int o = 16; o; o >>= 1) {
        sa += __shfl_xor_sync(0xffffffffu, sa, o);
        sb += __shfl_xor_sync(0xffffffffu, sb, o);
    }
    const int wid = threadIdx.x >> 5, lane = threadIdx.x & 31;
    if (lane == 0) { redA[wid] = sa; redB[wid] = sb; }
    __syncthreads();
    if (threadIdx.x == 0) {
        float ta = 0.f, tb2 = 0.f;
#pragma unroll
        for (int i = 0; i < 8; i++) { ta += redA[i]; tb2 += redB[i]; }
        s_m1 = ta * (1.0f / HH);
        s_m2 = tb2 * (1.0f / HH);
    }
    __syncthreads();
    const float m1 = s_m1, m2 = s_m2;
    float d, ssa = 0.f, ssb = 0.f;
    d=v0.x-m1; ssa+=d*d; d=v0.y-m1; ssa+=d*d; d=v0.z-m1; ssa+=d*d; d=v0.w-m1; ssa+=d*d;
    d=v1.x-m1; ssa+=d*d; d=v1.y-m1; ssa+=d*d; d=v1.z-m1; ssa+=d*d; d=v1.w-m1; ssa+=d*d;
    d=w0.x-m2; ssb+=d*d; d=w0.y-m2; ssb+=d*d; d=w0.z-m2; ssb+=d*d; d=w0.w-m2; ssb+=d*d;
    d=w1.x-m2; ssb+=d*d; d=w1.y-m2; ssb+=d*d; d=w1.z-m2; ssb+=d*d; d=w1.w-m2; ssb+=d*d;
#pragma unroll
    for (int o = 16; o; o >>= 1) {
        ssa += __shfl_xor_sync(0xffffffffu, ssa, o);
        ssb += __shfl_xor_sync(0xffffffffu, ssb, o);
    }
    if (lane == 0) { redA[wid] = ssa; redB[wid] = ssb; }
    __syncthreads();
    if (threadIdx.x == 0) {
        float ta = 0.f, tb2 = 0.f;
#pragma unroll
        for (int i = 0; i < 8; i++) { ta += redA[i]; tb2 += redB[i]; }
        s_r1 = rsqrtf(ta * (1.0f / HH) + EPSLN);
        s_r2 = rsqrtf(tb2 * (1.0f / HH) + EPSLN);
    }
    __syncthreads();
    const float r1 = s_r1, r2 = s_r2;

    float4 ga0 = ((const float4*)g)[threadIdx.x],  ga1 = ((const float4*)g)[threadIdx.x + 256];
    float4 ba0 = ((const float4*)b)[threadIdx.x],  ba1 = ((const float4*)b)[threadIdx.x + 256];
    float4 gb0 = ((const float4*)g2)[threadIdx.x], gb1 = ((const float4*)g2)[threadIdx.x + 256];
    float4 bb0 = ((const float4*)b2)[threadIdx.x], bb1 = ((const float4*)b2)[threadIdx.x + 256];

    float4 o0, o1, u0, u1;
    o0.x=(v0.x-m1)*r1*ga0.x+ba0.x; o0.y=(v0.y-m1)*r1*ga0.y+ba0.y;
    o0.z=(v0.z-m1)*r1*ga0.z+ba0.z; o0.w=(v0.w-m1)*r1*ga0.w+ba0.w;
    o1.x=(v1.x-m1)*r1*ga1.x+ba1.x; o1.y=(v1.y-m1)*r1*ga1.y+ba1.y;
    o1.z=(v1.z-m1)*r1*ga1.z+ba1.z; o1.w=(v1.w-m1)*r1*ga1.w+ba1.w;
    u0.x=(w0.x-m2)*r2*gb0.x+bb0.x; u0.y=(w0.y-m2)*r2*gb0.y+bb0.y;
    u0.z=(w0.z-m2)*r2*gb0.z+bb0.z; u0.w=(w0.w-m2)*r2*gb0.w+bb0.w;
    u1.x=(w1.x-m2)*r2*gb1.x+bb1.x; u1.y=(w1.y-m2)*r2*gb1.y+bb1.y;
    u1.z=(w1.z-m2)*r2*gb1.z+bb1.z; u1.w=(w1.w-m2)*r2*gb1.w+bb1.w;
    u0 = silu4(u0); u1 = silu4(u1);
    o0.x*=u0.x; o0.y*=u0.y; o0.z*=u0.z; o0.w*=u0.w;
    o1.x*=u1.x; o1.y*=u1.y; o1.z*=u1.z; o1.w*=u1.w;

    uint2 h0, l0, h1, l1;
    split4(o0, h0, l0);
    split4(o1, h1, l1);
    uint2* hp = (uint2*)(oh + (size_t)row * HH);
    uint2* lp = (uint2*)(ol + (size_t)row * HH);
    hp[threadIdx.x] = h0; hp[threadIdx.x + 256] = h1;
    lp[threadIdx.x] = l0; lp[threadIdx.x + 256] = l1;
}

// ------------------------------- minGRU scan ----------------------------------
__device__ __forceinline__ float softplusf(float x) {
    return fmaxf(x, 0.0f) + log1pf(expf(-fabsf(x)));
}
__device__ __forceinline__ float loggf(float x) {
    return (x >= 0.0f) ? logf(x + 0.5f) : -softplusf(-x);
}
__device__ __forceinline__ float laddexp(float a, float b) {
    float m = fmaxf(a, b);
    float d = fminf(a, b) - m;
    return m + log1pf(expf(d));
}

// one softplus per element: -softplus(-k) == k - softplus(k) (bitwise-equal here)
__global__ void scan_a(const float* __restrict__ Kx, const float* __restrict__ Px,
                       float* __restrict__ rend, float* __restrict__ asum)
{
    const int tid = blockIdx.x * 256 + threadIdx.x;
    const int h = tid & (HH - 1);
    const int rest = tid >> 11;
    const int j = rest & (CHUNKS - 1);
    const int b = rest >> CLOG;
    const size_t base = ((size_t)b * SS + (size_t)j * CLEN) * HH + h;
    float A = 0.f, r = -__int_as_float(0x7f800000);
    for (int tt = 0; tt < CLEN; tt++) {
        const float kv = Kx[base + (size_t)tt * HH];
        const float pv = Px[base + (size_t)tt * HH];
        const float sp = softplusf(kv);
        const float lc = -sp;
        const float lv = (kv - sp) + loggf(pv);
        A += lc;
        r = laddexp(r + lc, lv);
    }
    rend[tid] = r;
    asum[tid] = A;
}

__global__ void scan_b(const float* __restrict__ rend, const float* __restrict__ asum,
                       float* __restrict__ lhin)
{
    const int tid = blockIdx.x * 256 + threadIdx.x;
    const int h = tid & (HH - 1);
    const int b = tid >> 11;
    float carry = -0.69314718056f;
#pragma unroll
    for (int j = 0; j < CHUNKS; j++) {
        const int idx = ((b * CHUNKS + j) << 11) + h;
        lhin[idx] = carry;
        carry = laddexp(asum[idx] + carry, rend[idx]);
    }
}

__global__ void scan_c(const float* __restrict__ Kx, const float* __restrict__ Px,
                       const float* __restrict__ lhin, float* __restrict__ out)
{
    const int tid = blockIdx.x * 256 + threadIdx.x;
    const int h = tid & (HH - 1);
    const int rest = tid >> 11;
    const int j = rest & (CHUNKS - 1);
    const int b = rest >> CLOG;
    const size_t base = ((size_t)b * SS + (size_t)j * CLEN) * HH + h;
    const float lhi = lhin[tid];
    float A = 0.f, r = -__int_as_float(0x7f800000);
    for (int tt = 0; tt < CLEN; tt++) {
        const float kv = Kx[base + (size_t)tt * HH];
        const float pv = Px[base + (size_t)tt * HH];
        const float sp = softplusf(kv);
        const float lc = -sp;
        const float lv = (kv - sp) + loggf(pv);
        A += lc;
        r = laddexp(r + lc, lv);
        out[base + (size_t)tt * HH] = expf(laddexp(r, A + lhi));
    }
}

// --------------------------------- driver -------------------------------------
extern "C" void kernel_launch(void* const* d_in, const int* in_sizes, int n_in,
                              void* d_out, int out_size)
{
    const float* x    = (const float*)d_in[0];
    const float* Wp1  = (const float*)d_in[1];
    const float* bp1  = (const float*)d_in[2];
    const float* Wp2  = (const float*)d_in[3];
    const float* bp2  = (const float*)d_in[4];
    const float* convW= (const float*)d_in[5];
    const float* convb= (const float*)d_in[6];
    const float* Wz   = (const float*)d_in[7];
    const float* bz   = (const float*)d_in[8];
    const float* Wh   = (const float*)d_in[9];
    const float* bh   = (const float*)d_in[10];
    const float* Wd   = (const float*)d_in[11];
    const float* bd   = (const float*)d_in[12];
    const float* lng  = (const float*)d_in[13];
    const float* lnb  = (const float*)d_in[14];
    float* xb = (float*)d_out;

    float *b0,*b2,*b3,*b4,*rend,*asum,*lhin;
    __nv_bfloat16 *cvth,*cvtl,*cvtxh,*cvtxl;
    __nv_bfloat16 *wp1h,*wp1l,*wp2h,*wp2l,*wzh,*wzl,*whh,*whl,*wdh,*wdl,*wch,*wcl;
    cudaGetSymbolAddress((void**)&b0,  g_b0);
    cudaGetSymbolAddress((void**)&b2,  g_b2);
    cudaGetSymbolAddress((void**)&b3,  g_b3);
    cudaGetSymbolAddress((void**)&b4,  g_b4);
    cudaGetSymbolAddress((void**)&rend,g_rend);
    cudaGetSymbolAddress((void**)&asum,g_asum);
    cudaGetSymbolAddress((void**)&lhin,g_lhin);
    cudaGetSymbolAddress((void**)&cvth,g_cvth);
    cudaGetSymbolAddress((void**)&cvtl,g_cvtl);
    cudaGetSymbolAddress((void**)&cvtxh,g_cvtxh);
    cudaGetSymbolAddress((void**)&cvtxl,g_cvtxl);
    cudaGetSymbolAddress((void**)&wp1h,g_wp1h);
    cudaGetSymbolAddress((void**)&wp1l,g_wp1l);
    cudaGetSymbolAddress((void**)&wp2h,g_wp2h);
    cudaGetSymbolAddress((void**)&wp2l,g_wp2l);
    cudaGetSymbolAddress((void**)&wzh, g_wzh);
    cudaGetSymbolAddress((void**)&wzl, g_wzl);
    cudaGetSymbolAddress((void**)&whh, g_whh);
    cudaGetSymbolAddress((void**)&whl, g_whl);
    cudaGetSymbolAddress((void**)&wdh, g_wdh);
    cudaGetSymbolAddress((void**)&wdl, g_wdl);
    cudaGetSymbolAddress((void**)&wch, g_wch);
    cudaGetSymbolAddress((void**)&wcl, g_wcl);

    cudaFuncSetAttribute(gemm_ts, cudaFuncAttributeMaxDynamicSharedMemorySize, SMEM_DYN);

    cudaMemcpyAsync(xb, x, (size_t)MTOK * DD * sizeof(float),
                    cudaMemcpyDeviceToDevice, 0);

    const int npd = LAYERS*HH*DD/4;
    const int nhh = LAYERS*HH*HH/4;
    const dim3 gH(HH/TN, MTOK/TM);   // (8, 32)
    const dim3 gD(DD/TN, MTOK/TM);   // (4, 32)

    // R10-proven launch ordering (benches + profiles cleanly).
    cvt_split<<<(MTOK*DD/4+255)/256, 256>>>(xb, cvtxh, cvtxl, MTOK*DD/4);
    cvt_split<<<(npd+255)/256, 256>>>(Wp2, wp2h, wp2l, npd);
    cvt_split<<<(npd+255)/256, 256>>>(Wp1, wp1h, wp1l, npd);
    cvt_split<<<(nhh+255)/256, 256>>>(Wz,  wzh,  wzl,  nhh);
    // layer-0 projections hoisted here
    gemm_ts<<<gH, 256, SMEM_DYN>>>(cvtxh, cvtxl, wp2h, wp2l, bp2, b4, HH, DD, 1, 0, 0, 0, 0);
    gemm_ts<<<gH, 256, SMEM_DYN>>>(cvtxh, cvtxl, wp1h, wp1l, bp1, b0, HH, DD, 1, 0, 0, 0, 0);
    // remaining weight conversions
    cvt_split<<<(nhh+255)/256, 256>>>(Wh,  whh,  whl,  nhh);
    cvt_split<<<(npd+255)/256, 256>>>(Wd,  wdh,  wdl,  npd);
    cvt_convw<<<(unsigned)(((size_t)LAYERS*HH*HH+255)/256), 256>>>(convW, wch, wcl);

    for (int i = 0; i < LAYERS; i++) {
        if (i) {
            gemm_ts<<<gH, 256, SMEM_DYN>>>(cvtxh, cvtxl,
                                           wp2h + (size_t)i*HH*DD, wp2l + (size_t)i*HH*DD,
                                           bp2 + i*HH, b4, HH, DD, 1, 0, 0, 0, 0);
            gemm_ts<<<gH, 256, SMEM_DYN>>>(cvtxh, cvtxl,
                                           wp1h + (size_t)i*HH*DD, wp1l + (size_t)i*HH*DD,
                                           bp1 + i*HH, b0, HH, DD, 1, 0, 0, 0, 0);
        }
        ln_split<0><<<MTOK, 256>>>(b0, cvth, cvtl,
                                   lng + (size_t)(i*4+0)*HH, lnb + (size_t)(i*4+0)*HH);

        // conv1d: 3 shifted taps accumulated in TMEM; LN1+SiLU -> split
        gemm_ts<<<gH, 256, SMEM_DYN>>>(cvth, cvtl,
                                       wch + (size_t)i*3*HH*HH, wcl + (size_t)i*3*HH*HH,
                                       convb + i*HH, b0, HH, HH, 3, (size_t)HH*HH, 0, 0, 0);
        ln_split<1><<<MTOK, 256>>>(b0, cvth, cvtl,
                                   lng + (size_t)(i*4+1)*HH, lnb + (size_t)(i*4+1)*HH);

        // minGRU projections + scan
        gemm_ts<<<gH, 256, SMEM_DYN>>>(cvth, cvtl,
                                       wzh + (size_t)i*HH*HH, wzl + (size_t)i*HH*HH,
                                       bz + i*HH, b2, HH, HH, 1, 0, 0, 0, 0);
        gemm_ts<<<gH, 256, SMEM_DYN>>>(cvth, cvtl,
                                       whh + (size_t)i*HH*HH, whl + (size_t)i*HH*HH,
                                       bh + i*HH, b3, HH, HH, 1, 0, 0, 0, 0);
        scan_a<<<(BB*CHUNKS*HH)/256, 256>>>(b2, b3, rend, asum);
        scan_b<<<(BB*HH)/256, 256>>>(rend, asum, lhin);
        scan_c<<<(BB*CHUNKS*HH)/256, 256>>>(b2, b3, lhin, b0);

        // gating: split( LN2(scan_out) * SiLU(LN3(proj2_raw)) )  — fused double-LN
        ln2_mul_split<<<MTOK, 256>>>(b0, b4, cvth, cvtl,
                                     lng + (size_t)(i*4+2)*HH, lnb + (size_t)(i*4+2)*HH,
                                     lng + (size_t)(i*4+3)*HH, lnb + (size_t)(i*4+3)*HH);

        // down projection + bias + residual; epilogue also emits next layer's x split
        gemm_ts<<<gD, 256, SMEM_DYN>>>(cvth, cvtl,
                                       wdh + (size_t)i*DD*HH, wdl + (size_t)i*DD*HH,
                                       bd + i*DD, xb, DD, HH, 1, 0, 1, cvtxh, cvtxl);
    }
}